// round 4
// baseline (speedup 1.0000x reference)
#include <cuda_runtime.h>
#include <cuda_bf16.h>
#include <cstdint>
#include <math.h>

// ---------------------------------------------------------------------------
// SelfAttentionV3 (B=4, S=2048, E=1024) via bf16x3 split-precision HMMA GEMMs.
// Non-'a' PTX only: mma.sync + ldmatrix + cp.async (tcgen05 is arch-gated off).
// R4: single-barrier multistage schedule + whole-chunk fragment preload.
// ---------------------------------------------------------------------------

#define EMBED 1024
#define BATCH 4
#define SEQ   2048
#define ROWS  (BATCH * SEQ)   // 8192

typedef __nv_bfloat16 bf16;

// ---------------- static scratch (no allocs allowed) -----------------------
__device__ bf16 g_Xhi[(size_t)ROWS * EMBED];
__device__ bf16 g_Xlo[(size_t)ROWS * EMBED];
__device__ bf16 g_Wqkvhi[(size_t)3 * EMBED * EMBED];
__device__ bf16 g_Wqkvlo[(size_t)3 * EMBED * EMBED];
__device__ bf16 g_Wouthi[(size_t)EMBED * EMBED];
__device__ bf16 g_Woutlo[(size_t)EMBED * EMBED];
__device__ bf16 g_qkvhi[(size_t)ROWS * 3 * EMBED];
__device__ bf16 g_qkvlo[(size_t)ROWS * 3 * EMBED];
__device__ float g_att[(size_t)BATCH * SEQ * SEQ];
__device__ bf16 g_atthi[(size_t)BATCH * SEQ * SEQ];
__device__ bf16 g_attlo[(size_t)BATCH * SEQ * SEQ];
__device__ bf16 g_vthi[(size_t)BATCH * EMBED * SEQ];
__device__ bf16 g_vtlo[(size_t)BATCH * EMBED * SEQ];
__device__ bf16 g_ctxhi[(size_t)ROWS * EMBED];
__device__ bf16 g_ctxlo[(size_t)ROWS * EMBED];

// ---------------- PTX helpers ----------------------------------------------
__device__ __forceinline__ uint32_t smem_u32(const void* p) {
    uint32_t a;
    asm("{ .reg .u64 t; cvta.to.shared.u64 t, %1; cvt.u32.u64 %0, t; }"
        : "=r"(a) : "l"(p));
    return a;
}
__device__ __forceinline__ void cp16(uint32_t dst, const void* src) {
    asm volatile("cp.async.cg.shared.global [%0], [%1], 16;"
                 :: "r"(dst), "l"(src) : "memory");
}
__device__ __forceinline__ void cp_commit() {
    asm volatile("cp.async.commit_group;" ::: "memory");
}
template <int N>
__device__ __forceinline__ void cp_wait() {
    asm volatile("cp.async.wait_group %0;" :: "n"(N) : "memory");
}
__device__ __forceinline__ void ldm4(uint32_t* r, uint32_t addr) {
    asm volatile("ldmatrix.sync.aligned.m8n8.x4.shared.b16 {%0,%1,%2,%3}, [%4];"
                 : "=r"(r[0]), "=r"(r[1]), "=r"(r[2]), "=r"(r[3]) : "r"(addr));
}
__device__ __forceinline__ void mma16816(float* c, const uint32_t* a, const uint32_t* b) {
    asm volatile("mma.sync.aligned.m16n8k16.row.col.f32.bf16.bf16.f32 "
                 "{%0,%1,%2,%3}, {%4,%5,%6,%7}, {%8,%9}, {%0,%1,%2,%3};"
                 : "+f"(c[0]), "+f"(c[1]), "+f"(c[2]), "+f"(c[3])
                 : "r"(a[0]), "r"(a[1]), "r"(a[2]), "r"(a[3]), "r"(b[0]), "r"(b[1]));
}
__device__ __forceinline__ void split1(float x, bf16& h, bf16& l) {
    h = __float2bfloat16(x);
    l = __float2bfloat16(x - __bfloat162float(h));
}
__device__ __forceinline__ uint32_t pack2(bf16 a, bf16 b) {
    uint16_t ua = *reinterpret_cast<uint16_t*>(&a);
    uint16_t ub = *reinterpret_cast<uint16_t*>(&b);
    return (uint32_t)ua | ((uint32_t)ub << 16);
}

// ---------------------------------------------------------------------------
// bf16x3 GEMM: C = scale*(A[M,K] x B[N,K]^T) (+bias). Tile 128x128, Kc=32.
// smem row: [hi 32 bf16 | lo 32 bf16] = 128B, SW128 swizzle.
// ---------------------------------------------------------------------------
#define BM 128
#define BN 128
#define NSTAGE 3
#define STAGE_BYTES 32768
#define SMEM_TOTAL (NSTAGE * STAGE_BYTES)

struct Frag {
    uint32_t ah[4][4];   // A hi, 4 m-tiles
    uint32_t al[4][4];   // A lo
    uint32_t bh[8];      // B hi, 4 n8-tiles
    uint32_t bl[8];      // B lo
};

template <bool HAS_BIAS, bool SPLIT>
__global__ __launch_bounds__(256, 1) void gemm_bf16x3(
    const bf16* __restrict__ Ahi, const bf16* __restrict__ Alo,
    const bf16* __restrict__ Bhi, const bf16* __restrict__ Blo,
    const float* __restrict__ bias,
    float* __restrict__ C, bf16* __restrict__ Chi, bf16* __restrict__ Clo,
    int K, int lda, int ldb, int ldc,
    long aBS, long bBS, long cBS, float scale)
{
    extern __shared__ char smem[];
    const uint32_t sb = smem_u32(smem);
    const int tid = threadIdx.x;
    const int lane = tid & 31;
    const int wid = tid >> 5;
    const int wm = wid & 1;       // m 64-half
    const int wn = wid >> 1;      // n 32-quarter

    const long bm = (long)blockIdx.y * BM;
    const long bn = (long)blockIdx.x * BN;
    Ahi += (long)blockIdx.z * aBS;  Alo += (long)blockIdx.z * aBS;
    Bhi += (long)blockIdx.z * bBS;  Blo += (long)blockIdx.z * bBS;
    if (SPLIT) { Chi += (long)blockIdx.z * cBS; Clo += (long)blockIdx.z * cBS; }
    else       { C   += (long)blockIdx.z * cBS; }

    const int nchunk = K >> 5;

    // ---- cp.async per-thread assignments (4 A chunks + 4 B chunks) ----
    const bf16* pA[4]; const bf16* pB[4];
    uint32_t dA[4];
#pragma unroll
    for (int i = 0; i < 4; i++) {
        int ch = tid + i * 256;         // 0..1023
        int row = ch >> 3;
        int q = ch & 7;
        int half = q >> 2;              // 0=hi 1=lo
        int qq = q & 3;                 // 16B quarter within half
        uint32_t col = half * 64 + qq * 16;
        uint32_t sw = col ^ ((row & 7) * 16);
        dA[i] = (uint32_t)(row * 128) + sw;
        pA[i] = (half ? Alo : Ahi) + (size_t)(bm + row) * lda + qq * 8;
        pB[i] = (half ? Blo : Bhi) + (size_t)(bn + row) * ldb + qq * 8;
    }

    // ---- ldmatrix lane address components ----
    const int rA = (lane & 7) + ((lane >> 3) & 1) * 8;
    const uint32_t cA16 = ((lane >> 4) & 1) * 16;
    const int rB = (lane & 7) + ((lane >> 4) & 1) * 8;
    const uint32_t cB16 = ((lane >> 3) & 1) * 16;

    uint32_t aoff[4], axor[4];
#pragma unroll
    for (int mt = 0; mt < 4; mt++) {
        int arow = wm * 64 + mt * 16 + rA;
        aoff[mt] = arow * 128;
        axor[mt] = (arow & 7) * 16;
    }
    uint32_t boff[2], bxor[2];
#pragma unroll
    for (int t = 0; t < 2; t++) {
        int brow = wn * 32 + t * 16 + rB;
        boff[t] = brow * 128;
        bxor[t] = (brow & 7) * 16;
    }

    float acc[4][4][4];
#pragma unroll
    for (int mt = 0; mt < 4; mt++)
#pragma unroll
        for (int nt = 0; nt < 4; nt++)
#pragma unroll
            for (int r = 0; r < 4; r++) acc[mt][nt][r] = 0.f;

    // fragment loader for one k16 step (s = 0/1) from a given stage base
    auto ldfrag = [&](Frag& f, uint32_t baseA, int s) {
        const uint32_t baseB = baseA + 16384;
#pragma unroll
        for (int t = 0; t < 2; t++) {
            uint32_t c = s * 32 + cB16;
            ldm4(&f.bh[t * 4], baseB + boff[t] + (c ^ bxor[t]));
            ldm4(&f.bl[t * 4], baseB + boff[t] + ((c + 64) ^ bxor[t]));
        }
#pragma unroll
        for (int mt = 0; mt < 4; mt++) {
            uint32_t cc = s * 32 + cA16;
            ldm4(f.ah[mt], baseA + aoff[mt] + (cc ^ axor[mt]));
            ldm4(f.al[mt], baseA + aoff[mt] + ((cc + 64) ^ axor[mt]));
        }
    };
    auto mmastep = [&](const Frag& f) {
#pragma unroll
        for (int mt = 0; mt < 4; mt++)
#pragma unroll
            for (int nt = 0; nt < 4; nt++)
                mma16816(acc[mt][nt], f.ah[mt], &f.bh[nt * 2]);
#pragma unroll
        for (int mt = 0; mt < 4; mt++)
#pragma unroll
            for (int nt = 0; nt < 4; nt++)
                mma16816(acc[mt][nt], f.ah[mt], &f.bl[nt * 2]);
#pragma unroll
        for (int mt = 0; mt < 4; mt++)
#pragma unroll
            for (int nt = 0; nt < 4; nt++)
                mma16816(acc[mt][nt], f.al[mt], &f.bh[nt * 2]);
    };

    // ---- prologue: stages 0..1 in flight ----
#pragma unroll
    for (int st = 0; st < NSTAGE - 1; st++) {
        int k0 = st * 32;
        uint32_t baseA = sb + st * STAGE_BYTES;
#pragma unroll
        for (int i = 0; i < 4; i++) cp16(baseA + dA[i], pA[i] + k0);
#pragma unroll
        for (int i = 0; i < 4; i++) cp16(baseA + 16384 + dA[i], pB[i] + k0);
        cp_commit();
    }
    cp_wait<NSTAGE - 2>();
    __syncthreads();

    // ---- main loop: ONE barrier per chunk ----
    for (int kc = 0; kc < nchunk; kc++) {
        const uint32_t baseA = sb + (kc % NSTAGE) * STAGE_BYTES;

        // issue cp.async for chunk kc+2 into the stage consumed at kc-1
        // (all warps passed the previous barrier, so that stage is free)
        int next = kc + NSTAGE - 1;
        if (next < nchunk) {
            int k0 = next * 32;
            uint32_t nb = sb + (next % NSTAGE) * STAGE_BYTES;
#pragma unroll
            for (int i = 0; i < 4; i++) cp16(nb + dA[i], pA[i] + k0);
#pragma unroll
            for (int i = 0; i < 4; i++) cp16(nb + 16384 + dA[i], pB[i] + k0);
        }
        cp_commit();

        // preload both k16-steps, then stream 96 MMAs from registers
        Frag f0, f1;
        ldfrag(f0, baseA, 0);
        ldfrag(f1, baseA, 1);
        mmastep(f0);
        mmastep(f1);

        cp_wait<NSTAGE - 2>();   // chunk kc+1 resident
        __syncthreads();
    }

    // ---- epilogue ----
#pragma unroll
    for (int mt = 0; mt < 4; mt++) {
        long r0 = bm + wm * 64 + mt * 16 + (lane >> 2);
        long r1 = r0 + 8;
#pragma unroll
        for (int nt = 0; nt < 4; nt++) {
            long col = bn + wn * 32 + nt * 8 + (lane & 3) * 2;
            float b0v = 0.f, b1v = 0.f;
            if (HAS_BIAS) { b0v = bias[col]; b1v = bias[col + 1]; }
            float v00 = acc[mt][nt][0] * scale + b0v;
            float v01 = acc[mt][nt][1] * scale + b1v;
            float v10 = acc[mt][nt][2] * scale + b0v;
            float v11 = acc[mt][nt][3] * scale + b1v;
            if (SPLIT) {
                bf16 h0, h1, l0, l1;
                split1(v00, h0, l0); split1(v01, h1, l1);
                *reinterpret_cast<uint32_t*>(&Chi[r0 * ldc + col]) = pack2(h0, h1);
                *reinterpret_cast<uint32_t*>(&Clo[r0 * ldc + col]) = pack2(l0, l1);
                split1(v10, h0, l0); split1(v11, h1, l1);
                *reinterpret_cast<uint32_t*>(&Chi[r1 * ldc + col]) = pack2(h0, h1);
                *reinterpret_cast<uint32_t*>(&Clo[r1 * ldc + col]) = pack2(l0, l1);
            } else {
                float2 u0 = make_float2(v00, v01);
                float2 u1 = make_float2(v10, v11);
                *reinterpret_cast<float2*>(&C[r0 * ldc + col]) = u0;
                *reinterpret_cast<float2*>(&C[r1 * ldc + col]) = u1;
            }
        }
    }
}

// ---------------------------------------------------------------------------
// fp32 -> (hi,lo) bf16 split conversion (vectorized)
// ---------------------------------------------------------------------------
__global__ __launch_bounds__(256) void split_kernel(
    const float* __restrict__ src, bf16* __restrict__ hi, bf16* __restrict__ lo, int n4)
{
    int i = blockIdx.x * blockDim.x + threadIdx.x;
    if (i >= n4) return;
    float4 v = reinterpret_cast<const float4*>(src)[i];
    bf16 h0, h1, h2, h3, l0, l1, l2, l3;
    split1(v.x, h0, l0); split1(v.y, h1, l1);
    split1(v.z, h2, l2); split1(v.w, h3, l3);
    uint2 hw = make_uint2(pack2(h0, h1), pack2(h2, h3));
    uint2 lw = make_uint2(pack2(l0, l1), pack2(l2, l3));
    reinterpret_cast<uint2*>(hi)[i] = hw;
    reinterpret_cast<uint2*>(lo)[i] = lw;
}

// ---------------------------------------------------------------------------
// V transpose (hi & lo): vt[b][e][s] = qkv[b*S+s][2E+e]
// ---------------------------------------------------------------------------
__global__ __launch_bounds__(256) void transpose_v_kernel(
    const bf16* __restrict__ qh, const bf16* __restrict__ ql,
    bf16* __restrict__ vth, bf16* __restrict__ vtl)
{
    __shared__ bf16 th[32][33];
    __shared__ bf16 tl[32][33];
    const int b = blockIdx.z;
    const int e0 = blockIdx.x * 32;
    const int s0 = blockIdx.y * 32;
    const int tx = threadIdx.x & 31;
    const int ty = threadIdx.x >> 5;  // 0..7
#pragma unroll
    for (int i = 0; i < 4; i++) {
        int s = s0 + ty + i * 8;
        size_t idx = (size_t)(b * SEQ + s) * (3 * EMBED) + 2 * EMBED + e0 + tx;
        th[ty + i * 8][tx] = qh[idx];
        tl[ty + i * 8][tx] = ql[idx];
    }
    __syncthreads();
#pragma unroll
    for (int i = 0; i < 4; i++) {
        int e = e0 + ty + i * 8;
        size_t o = (size_t)(b * EMBED + e) * SEQ + s0 + tx;
        vth[o] = th[tx][ty + i * 8];
        vtl[o] = tl[tx][ty + i * 8];
    }
}

// ---------------------------------------------------------------------------
// Row softmax with mask; writes (hi,lo) bf16 probabilities.
// ---------------------------------------------------------------------------
__global__ __launch_bounds__(256) void softmax_kernel(
    const float* __restrict__ att, const int* __restrict__ mask,
    bf16* __restrict__ phi, bf16* __restrict__ plo)
{
    const size_t row = blockIdx.x;
    const float* a = att + row * SEQ;
    const int* m = mask + row * SEQ;
    const int tid = threadIdx.x;

    __shared__ float red_max[8];
    __shared__ float red_sum[8];

    float v[8];
    float mx = -INFINITY;
#pragma unroll
    for (int i = 0; i < 8; i++) {
        int idx = tid + i * 256;
        float x = a[idx];
        x = (m[idx] != 0) ? x : -INFINITY;
        v[i] = x;
        mx = fmaxf(mx, x);
    }
#pragma unroll
    for (int o = 16; o > 0; o >>= 1)
        mx = fmaxf(mx, __shfl_xor_sync(0xffffffffu, mx, o));
    if ((tid & 31) == 0) red_max[tid >> 5] = mx;
    __syncthreads();
    float bmax = red_max[0];
#pragma unroll
    for (int w = 1; w < 8; w++) bmax = fmaxf(bmax, red_max[w]);

    float s = 0.f;
#pragma unroll
    for (int i = 0; i < 8; i++) {
        v[i] = __expf(v[i] - bmax);
        s += v[i];
    }
#pragma unroll
    for (int o = 16; o > 0; o >>= 1)
        s += __shfl_xor_sync(0xffffffffu, s, o);
    if ((tid & 31) == 0) red_sum[tid >> 5] = s;
    __syncthreads();
    float total = 0.f;
#pragma unroll
    for (int w = 0; w < 8; w++) total += red_sum[w];

    float inv = 1.f / total;
#pragma unroll
    for (int i = 0; i < 8; i++) {
        int idx = tid + i * 256;
        float p = v[i] * inv;
        bf16 h, l;
        split1(p, h, l);
        phi[row * SEQ + idx] = h;
        plo[row * SEQ + idx] = l;
    }
}

// ---------------------------------------------------------------------------
extern "C" void kernel_launch(void* const* d_in, const int* in_sizes, int n_in,
                              void* d_out, int out_size)
{
    const float* X    = (const float*)d_in[0];
    const int*   mask = (const int*)  d_in[1];
    const float* Wqkv = (const float*)d_in[2];
    const float* bqkv = (const float*)d_in[3];
    const float* Wout = (const float*)d_in[4];
    const float* bout = (const float*)d_in[5];
    float* out = (float*)d_out;

    bf16 *Xhi, *Xlo, *Wqkvhi, *Wqkvlo, *Wouthi, *Woutlo;
    bf16 *qkvhi, *qkvlo, *atthi, *attlo, *vthi, *vtlo, *ctxhi, *ctxlo;
    float* att;
    cudaGetSymbolAddress((void**)&Xhi, g_Xhi);
    cudaGetSymbolAddress((void**)&Xlo, g_Xlo);
    cudaGetSymbolAddress((void**)&Wqkvhi, g_Wqkvhi);
    cudaGetSymbolAddress((void**)&Wqkvlo, g_Wqkvlo);
    cudaGetSymbolAddress((void**)&Wouthi, g_Wouthi);
    cudaGetSymbolAddress((void**)&Woutlo, g_Woutlo);
    cudaGetSymbolAddress((void**)&qkvhi, g_qkvhi);
    cudaGetSymbolAddress((void**)&qkvlo, g_qkvlo);
    cudaGetSymbolAddress((void**)&att, g_att);
    cudaGetSymbolAddress((void**)&atthi, g_atthi);
    cudaGetSymbolAddress((void**)&attlo, g_attlo);
    cudaGetSymbolAddress((void**)&vthi, g_vthi);
    cudaGetSymbolAddress((void**)&vtlo, g_vtlo);
    cudaGetSymbolAddress((void**)&ctxhi, g_ctxhi);
    cudaGetSymbolAddress((void**)&ctxlo, g_ctxlo);

    cudaFuncSetAttribute(gemm_bf16x3<true, true>,
                         cudaFuncAttributeMaxDynamicSharedMemorySize, SMEM_TOTAL);
    cudaFuncSetAttribute(gemm_bf16x3<false, false>,
                         cudaFuncAttributeMaxDynamicSharedMemorySize, SMEM_TOTAL);
    cudaFuncSetAttribute(gemm_bf16x3<false, true>,
                         cudaFuncAttributeMaxDynamicSharedMemorySize, SMEM_TOTAL);
    cudaFuncSetAttribute(gemm_bf16x3<true, false>,
                         cudaFuncAttributeMaxDynamicSharedMemorySize, SMEM_TOTAL);

    // 0) split inputs to (hi,lo) bf16
    split_kernel<<<(ROWS * EMBED / 4 + 255) / 256, 256>>>(X, Xhi, Xlo, ROWS * EMBED / 4);
    split_kernel<<<(3 * EMBED * EMBED / 4 + 255) / 256, 256>>>(Wqkv, Wqkvhi, Wqkvlo,
                                                               3 * EMBED * EMBED / 4);
    split_kernel<<<(EMBED * EMBED / 4 + 255) / 256, 256>>>(Wout, Wouthi, Woutlo,
                                                           EMBED * EMBED / 4);

    // 1) qkv = X Wqkv^T + bqkv  (split output)
    {
        dim3 grid(3 * EMBED / BN, ROWS / BM, 1);
        gemm_bf16x3<true, true><<<grid, 256, SMEM_TOTAL>>>(
            Xhi, Xlo, Wqkvhi, Wqkvlo, bqkv,
            nullptr, qkvhi, qkvlo,
            EMBED, EMBED, EMBED, 3 * EMBED,
            0, 0, 0, 1.0f);
    }
    // 2) vt = V^T (hi,lo)
    {
        dim3 grid(EMBED / 32, SEQ / 32, BATCH);
        transpose_v_kernel<<<grid, 256>>>(qkvhi, qkvlo, vthi, vtlo);
    }
    // 3) att = Q K^T / 32  (fp32 output)
    {
        dim3 grid(SEQ / BN, SEQ / BM, BATCH);
        gemm_bf16x3<false, false><<<grid, 256, SMEM_TOTAL>>>(
            qkvhi, qkvlo, qkvhi + EMBED, qkvlo + EMBED, nullptr,
            att, nullptr, nullptr,
            EMBED, 3 * EMBED, 3 * EMBED, SEQ,
            (long)SEQ * 3 * EMBED, (long)SEQ * 3 * EMBED, (long)SEQ * SEQ,
            1.0f / 32.0f);
    }
    // 4) softmax -> (hi,lo)
    softmax_kernel<<<BATCH * SEQ, 256>>>(att, mask, atthi, attlo);

    // 5) ctx = att vt^T  (split output)
    {
        dim3 grid(EMBED / BN, SEQ / BM, BATCH);
        gemm_bf16x3<false, true><<<grid, 256, SMEM_TOTAL>>>(
            atthi, attlo, vthi, vtlo, nullptr,
            nullptr, ctxhi, ctxlo,
            SEQ, SEQ, SEQ, EMBED,
            (long)SEQ * SEQ, (long)EMBED * SEQ, (long)SEQ * EMBED,
            1.0f);
    }
    // 6) out = ctx Wout^T + bout  (fp32)
    {
        dim3 grid(EMBED / BN, ROWS / BM, 1);
        gemm_bf16x3<true, false><<<grid, 256, SMEM_TOTAL>>>(
            ctxhi, ctxlo, Wouthi, Woutlo, bout,
            out, nullptr, nullptr,
            EMBED, EMBED, EMBED, EMBED,
            0, 0, 0, 1.0f);
    }
}

// round 5
// speedup vs baseline: 1.0882x; 1.0882x over previous
#include <cuda_runtime.h>
#include <cuda_bf16.h>
#include <cstdint>
#include <math.h>

// ---------------------------------------------------------------------------
// SelfAttentionV3 (B=4, S=2048, E=1024) via bf16x3 split-precision HMMA GEMMs.
// Non-'a' PTX only: mma.sync + ldmatrix + cp.async (tcgen05 is arch-gated off).
// R5: R3 inner schedule (proven) + K-chunk 64 (half the barriers/drains),
//     3-stage 192KB smem pipeline, prefetch issued before compute.
// ---------------------------------------------------------------------------

#define EMBED 1024
#define BATCH 4
#define SEQ   2048
#define ROWS  (BATCH * SEQ)   // 8192

typedef __nv_bfloat16 bf16;

// ---------------- static scratch (no allocs allowed) -----------------------
__device__ bf16 g_Xhi[(size_t)ROWS * EMBED];
__device__ bf16 g_Xlo[(size_t)ROWS * EMBED];
__device__ bf16 g_Wqkvhi[(size_t)3 * EMBED * EMBED];
__device__ bf16 g_Wqkvlo[(size_t)3 * EMBED * EMBED];
__device__ bf16 g_Wouthi[(size_t)EMBED * EMBED];
__device__ bf16 g_Woutlo[(size_t)EMBED * EMBED];
__device__ bf16 g_qkvhi[(size_t)ROWS * 3 * EMBED];
__device__ bf16 g_qkvlo[(size_t)ROWS * 3 * EMBED];
__device__ float g_att[(size_t)BATCH * SEQ * SEQ];
__device__ bf16 g_atthi[(size_t)BATCH * SEQ * SEQ];
__device__ bf16 g_attlo[(size_t)BATCH * SEQ * SEQ];
__device__ bf16 g_vthi[(size_t)BATCH * EMBED * SEQ];
__device__ bf16 g_vtlo[(size_t)BATCH * EMBED * SEQ];
__device__ bf16 g_ctxhi[(size_t)ROWS * EMBED];
__device__ bf16 g_ctxlo[(size_t)ROWS * EMBED];

// ---------------- PTX helpers ----------------------------------------------
__device__ __forceinline__ uint32_t smem_u32(const void* p) {
    uint32_t a;
    asm("{ .reg .u64 t; cvta.to.shared.u64 t, %1; cvt.u32.u64 %0, t; }"
        : "=r"(a) : "l"(p));
    return a;
}
__device__ __forceinline__ void cp16(uint32_t dst, const void* src) {
    asm volatile("cp.async.cg.shared.global [%0], [%1], 16;"
                 :: "r"(dst), "l"(src) : "memory");
}
__device__ __forceinline__ void cp_commit() {
    asm volatile("cp.async.commit_group;" ::: "memory");
}
template <int N>
__device__ __forceinline__ void cp_wait() {
    asm volatile("cp.async.wait_group %0;" :: "n"(N) : "memory");
}
__device__ __forceinline__ void ldm4(uint32_t* r, uint32_t addr) {
    asm volatile("ldmatrix.sync.aligned.m8n8.x4.shared.b16 {%0,%1,%2,%3}, [%4];"
                 : "=r"(r[0]), "=r"(r[1]), "=r"(r[2]), "=r"(r[3]) : "r"(addr));
}
__device__ __forceinline__ void mma16816(float* c, const uint32_t* a, const uint32_t* b) {
    asm volatile("mma.sync.aligned.m16n8k16.row.col.f32.bf16.bf16.f32 "
                 "{%0,%1,%2,%3}, {%4,%5,%6,%7}, {%8,%9}, {%0,%1,%2,%3};"
                 : "+f"(c[0]), "+f"(c[1]), "+f"(c[2]), "+f"(c[3])
                 : "r"(a[0]), "r"(a[1]), "r"(a[2]), "r"(a[3]), "r"(b[0]), "r"(b[1]));
}
__device__ __forceinline__ void split1(float x, bf16& h, bf16& l) {
    h = __float2bfloat16(x);
    l = __float2bfloat16(x - __bfloat162float(h));
}
__device__ __forceinline__ uint32_t pack2(bf16 a, bf16 b) {
    uint16_t ua = *reinterpret_cast<uint16_t*>(&a);
    uint16_t ub = *reinterpret_cast<uint16_t*>(&b);
    return (uint32_t)ua | ((uint32_t)ub << 16);
}

// ---------------------------------------------------------------------------
// bf16x3 GEMM: C = scale*(A[M,K] x B[N,K]^T) (+bias). Tile 128x128, Kc=64.
// smem row (256B): [hi 64 bf16 (128B) | lo 64 bf16 (128B)], swizzle per half.
// ---------------------------------------------------------------------------
#define BM 128
#define BN 128
#define NSTAGE 3
#define TILE_BYTES 32768                 // one operand tile (A or B)
#define STAGE_BYTES (2 * TILE_BYTES)     // A + B
#define SMEM_TOTAL (NSTAGE * STAGE_BYTES)

template <bool HAS_BIAS, bool SPLIT>
__global__ __launch_bounds__(256, 1) void gemm_bf16x3(
    const bf16* __restrict__ Ahi, const bf16* __restrict__ Alo,
    const bf16* __restrict__ Bhi, const bf16* __restrict__ Blo,
    const float* __restrict__ bias,
    float* __restrict__ C, bf16* __restrict__ Chi, bf16* __restrict__ Clo,
    int K, int lda, int ldb, int ldc,
    long aBS, long bBS, long cBS, float scale)
{
    extern __shared__ char smem[];
    const uint32_t sb = smem_u32(smem);
    const int tid = threadIdx.x;
    const int lane = tid & 31;
    const int wid = tid >> 5;
    const int wm = wid & 1;       // m 64-half
    const int wn = wid >> 1;      // n 32-quarter

    const long bm = (long)blockIdx.y * BM;
    const long bn = (long)blockIdx.x * BN;
    Ahi += (long)blockIdx.z * aBS;  Alo += (long)blockIdx.z * aBS;
    Bhi += (long)blockIdx.z * bBS;  Blo += (long)blockIdx.z * bBS;
    if (SPLIT) { Chi += (long)blockIdx.z * cBS; Clo += (long)blockIdx.z * cBS; }
    else       { C   += (long)blockIdx.z * cBS; }

    const int nchunk = K >> 6;      // 64-K chunks

    // ---- cp.async per-thread assignments: 8 A chunks + 8 B chunks of 16B ----
    // tile = 128 rows x 256B; row: [hi qq=0..7 | lo qq=0..7] 16B units
    const bf16* pA[8]; const bf16* pB[8];
    uint32_t dst16[8];
#pragma unroll
    for (int i = 0; i < 8; i++) {
        int ch = tid + i * 256;          // 0..2047
        int row = ch >> 4;               // 0..127
        int q = ch & 15;
        int half = q >> 3;               // 0=hi 1=lo
        int qq = q & 7;                  // 16B unit within 128B half
        uint32_t sw = (uint32_t)(qq * 16) ^ ((row & 7) * 16);
        dst16[i] = (uint32_t)(row * 256) + half * 128 + sw;
        pA[i] = (half ? Alo : Ahi) + (size_t)(bm + row) * lda + qq * 8;
        pB[i] = (half ? Blo : Bhi) + (size_t)(bn + row) * ldb + qq * 8;
    }

    // ---- ldmatrix lane address components ----
    const int rA = (lane & 7) + ((lane >> 3) & 1) * 8;
    const uint32_t cA16 = ((lane >> 4) & 1) * 16;
    const int rB = (lane & 7) + ((lane >> 4) & 1) * 8;
    const uint32_t cB16 = ((lane >> 3) & 1) * 16;

    uint32_t aoff[4], axor[4];
#pragma unroll
    for (int mt = 0; mt < 4; mt++) {
        int arow = wm * 64 + mt * 16 + rA;
        aoff[mt] = arow * 256;
        axor[mt] = (arow & 7) * 16;
    }
    uint32_t boff[2], bxor[2];
#pragma unroll
    for (int t = 0; t < 2; t++) {
        int brow = wn * 32 + t * 16 + rB;
        boff[t] = brow * 256;
        bxor[t] = (brow & 7) * 16;
    }

    float acc[4][4][4];
#pragma unroll
    for (int mt = 0; mt < 4; mt++)
#pragma unroll
        for (int nt = 0; nt < 4; nt++)
#pragma unroll
            for (int r = 0; r < 4; r++) acc[mt][nt][r] = 0.f;

    // ---- prologue: stages 0..1 in flight ----
#pragma unroll
    for (int st = 0; st < NSTAGE - 1; st++) {
        int k0 = st * 64;
        uint32_t baseA = sb + st * STAGE_BYTES;
#pragma unroll
        for (int i = 0; i < 8; i++) cp16(baseA + dst16[i], pA[i] + k0);
#pragma unroll
        for (int i = 0; i < 8; i++) cp16(baseA + TILE_BYTES + dst16[i], pB[i] + k0);
        cp_commit();
    }
    cp_wait<NSTAGE - 2>();
    __syncthreads();

    // ---- main loop ----
    for (int kc = 0; kc < nchunk; kc++) {
        const uint32_t baseA = sb + (kc % NSTAGE) * STAGE_BYTES;
        const uint32_t baseB = baseA + TILE_BYTES;

        // prefetch chunk kc+2 into the stage consumed at kc-1 (safe: all
        // threads passed the barrier ending iteration kc-1)
        int next = kc + NSTAGE - 1;
        if (next < nchunk) {
            int k0 = next * 64;
            uint32_t nb = sb + (next % NSTAGE) * STAGE_BYTES;
#pragma unroll
            for (int i = 0; i < 8; i++) cp16(nb + dst16[i], pA[i] + k0);
#pragma unroll
            for (int i = 0; i < 8; i++) cp16(nb + TILE_BYTES + dst16[i], pB[i] + k0);
        }
        cp_commit();

        // 4 k16 steps; per-step fragment loads (R3-proven register footprint)
#pragma unroll
        for (int s = 0; s < 4; s++) {
            uint32_t bh[8], bl[8];
#pragma unroll
            for (int t = 0; t < 2; t++) {
                uint32_t c = s * 32 + cB16;
                ldm4(&bh[t * 4], baseB + boff[t] + (c ^ bxor[t]));
                ldm4(&bl[t * 4], baseB + boff[t] + 128 + (c ^ bxor[t]));
            }
#pragma unroll
            for (int mt = 0; mt < 4; mt++) {
                uint32_t a[4];
                uint32_t cc = s * 32 + cA16;
                ldm4(a, baseA + aoff[mt] + (cc ^ axor[mt]));
#pragma unroll
                for (int nt = 0; nt < 4; nt++) mma16816(acc[mt][nt], a, &bh[nt * 2]);
#pragma unroll
                for (int nt = 0; nt < 4; nt++) mma16816(acc[mt][nt], a, &bl[nt * 2]);
                ldm4(a, baseA + aoff[mt] + 128 + (cc ^ axor[mt]));
#pragma unroll
                for (int nt = 0; nt < 4; nt++) mma16816(acc[mt][nt], a, &bh[nt * 2]);
            }
        }

        cp_wait<NSTAGE - 2>();   // chunk kc+1 resident
        __syncthreads();
    }

    // ---- epilogue ----
#pragma unroll
    for (int mt = 0; mt < 4; mt++) {
        long r0 = bm + wm * 64 + mt * 16 + (lane >> 2);
        long r1 = r0 + 8;
#pragma unroll
        for (int nt = 0; nt < 4; nt++) {
            long col = bn + wn * 32 + nt * 8 + (lane & 3) * 2;
            float b0v = 0.f, b1v = 0.f;
            if (HAS_BIAS) { b0v = bias[col]; b1v = bias[col + 1]; }
            float v00 = acc[mt][nt][0] * scale + b0v;
            float v01 = acc[mt][nt][1] * scale + b1v;
            float v10 = acc[mt][nt][2] * scale + b0v;
            float v11 = acc[mt][nt][3] * scale + b1v;
            if (SPLIT) {
                bf16 h0, h1, l0, l1;
                split1(v00, h0, l0); split1(v01, h1, l1);
                *reinterpret_cast<uint32_t*>(&Chi[r0 * ldc + col]) = pack2(h0, h1);
                *reinterpret_cast<uint32_t*>(&Clo[r0 * ldc + col]) = pack2(l0, l1);
                split1(v10, h0, l0); split1(v11, h1, l1);
                *reinterpret_cast<uint32_t*>(&Chi[r1 * ldc + col]) = pack2(h0, h1);
                *reinterpret_cast<uint32_t*>(&Clo[r1 * ldc + col]) = pack2(l0, l1);
            } else {
                float2 u0 = make_float2(v00, v01);
                float2 u1 = make_float2(v10, v11);
                *reinterpret_cast<float2*>(&C[r0 * ldc + col]) = u0;
                *reinterpret_cast<float2*>(&C[r1 * ldc + col]) = u1;
            }
        }
    }
}

// ---------------------------------------------------------------------------
// fp32 -> (hi,lo) bf16 split conversion (vectorized)
// ---------------------------------------------------------------------------
__global__ __launch_bounds__(256) void split_kernel(
    const float* __restrict__ src, bf16* __restrict__ hi, bf16* __restrict__ lo, int n4)
{
    int i = blockIdx.x * blockDim.x + threadIdx.x;
    if (i >= n4) return;
    float4 v = reinterpret_cast<const float4*>(src)[i];
    bf16 h0, h1, h2, h3, l0, l1, l2, l3;
    split1(v.x, h0, l0); split1(v.y, h1, l1);
    split1(v.z, h2, l2); split1(v.w, h3, l3);
    uint2 hw = make_uint2(pack2(h0, h1), pack2(h2, h3));
    uint2 lw = make_uint2(pack2(l0, l1), pack2(l2, l3));
    reinterpret_cast<uint2*>(hi)[i] = hw;
    reinterpret_cast<uint2*>(lo)[i] = lw;
}

// ---------------------------------------------------------------------------
// V transpose (hi & lo): vt[b][e][s] = qkv[b*S+s][2E+e]
// ---------------------------------------------------------------------------
__global__ __launch_bounds__(256) void transpose_v_kernel(
    const bf16* __restrict__ qh, const bf16* __restrict__ ql,
    bf16* __restrict__ vth, bf16* __restrict__ vtl)
{
    __shared__ bf16 th[32][33];
    __shared__ bf16 tl[32][33];
    const int b = blockIdx.z;
    const int e0 = blockIdx.x * 32;
    const int s0 = blockIdx.y * 32;
    const int tx = threadIdx.x & 31;
    const int ty = threadIdx.x >> 5;  // 0..7
#pragma unroll
    for (int i = 0; i < 4; i++) {
        int s = s0 + ty + i * 8;
        size_t idx = (size_t)(b * SEQ + s) * (3 * EMBED) + 2 * EMBED + e0 + tx;
        th[ty + i * 8][tx] = qh[idx];
        tl[ty + i * 8][tx] = ql[idx];
    }
    __syncthreads();
#pragma unroll
    for (int i = 0; i < 4; i++) {
        int e = e0 + ty + i * 8;
        size_t o = (size_t)(b * EMBED + e) * SEQ + s0 + tx;
        vth[o] = th[tx][ty + i * 8];
        vtl[o] = tl[tx][ty + i * 8];
    }
}

// ---------------------------------------------------------------------------
// Row softmax with mask; writes (hi,lo) bf16 probabilities.
// ---------------------------------------------------------------------------
__global__ __launch_bounds__(256) void softmax_kernel(
    const float* __restrict__ att, const int* __restrict__ mask,
    bf16* __restrict__ phi, bf16* __restrict__ plo)
{
    const size_t row = blockIdx.x;
    const float* a = att + row * SEQ;
    const int* m = mask + row * SEQ;
    const int tid = threadIdx.x;

    __shared__ float red_max[8];
    __shared__ float red_sum[8];

    float v[8];
    float mx = -INFINITY;
#pragma unroll
    for (int i = 0; i < 8; i++) {
        int idx = tid + i * 256;
        float x = a[idx];
        x = (m[idx] != 0) ? x : -INFINITY;
        v[i] = x;
        mx = fmaxf(mx, x);
    }
#pragma unroll
    for (int o = 16; o > 0; o >>= 1)
        mx = fmaxf(mx, __shfl_xor_sync(0xffffffffu, mx, o));
    if ((tid & 31) == 0) red_max[tid >> 5] = mx;
    __syncthreads();
    float bmax = red_max[0];
#pragma unroll
    for (int w = 1; w < 8; w++) bmax = fmaxf(bmax, red_max[w]);

    float s = 0.f;
#pragma unroll
    for (int i = 0; i < 8; i++) {
        v[i] = __expf(v[i] - bmax);
        s += v[i];
    }
#pragma unroll
    for (int o = 16; o > 0; o >>= 1)
        s += __shfl_xor_sync(0xffffffffu, s, o);
    if ((tid & 31) == 0) red_sum[tid >> 5] = s;
    __syncthreads();
    float total = 0.f;
#pragma unroll
    for (int w = 0; w < 8; w++) total += red_sum[w];

    float inv = 1.f / total;
#pragma unroll
    for (int i = 0; i < 8; i++) {
        int idx = tid + i * 256;
        float p = v[i] * inv;
        bf16 h, l;
        split1(p, h, l);
        phi[row * SEQ + idx] = h;
        plo[row * SEQ + idx] = l;
    }
}

// ---------------------------------------------------------------------------
extern "C" void kernel_launch(void* const* d_in, const int* in_sizes, int n_in,
                              void* d_out, int out_size)
{
    const float* X    = (const float*)d_in[0];
    const int*   mask = (const int*)  d_in[1];
    const float* Wqkv = (const float*)d_in[2];
    const float* bqkv = (const float*)d_in[3];
    const float* Wout = (const float*)d_in[4];
    const float* bout = (const float*)d_in[5];
    float* out = (float*)d_out;

    bf16 *Xhi, *Xlo, *Wqkvhi, *Wqkvlo, *Wouthi, *Woutlo;
    bf16 *qkvhi, *qkvlo, *atthi, *attlo, *vthi, *vtlo, *ctxhi, *ctxlo;
    float* att;
    cudaGetSymbolAddress((void**)&Xhi, g_Xhi);
    cudaGetSymbolAddress((void**)&Xlo, g_Xlo);
    cudaGetSymbolAddress((void**)&Wqkvhi, g_Wqkvhi);
    cudaGetSymbolAddress((void**)&Wqkvlo, g_Wqkvlo);
    cudaGetSymbolAddress((void**)&Wouthi, g_Wouthi);
    cudaGetSymbolAddress((void**)&Woutlo, g_Woutlo);
    cudaGetSymbolAddress((void**)&qkvhi, g_qkvhi);
    cudaGetSymbolAddress((void**)&qkvlo, g_qkvlo);
    cudaGetSymbolAddress((void**)&att, g_att);
    cudaGetSymbolAddress((void**)&atthi, g_atthi);
    cudaGetSymbolAddress((void**)&attlo, g_attlo);
    cudaGetSymbolAddress((void**)&vthi, g_vthi);
    cudaGetSymbolAddress((void**)&vtlo, g_vtlo);
    cudaGetSymbolAddress((void**)&ctxhi, g_ctxhi);
    cudaGetSymbolAddress((void**)&ctxlo, g_ctxlo);

    cudaFuncSetAttribute(gemm_bf16x3<true, true>,
                         cudaFuncAttributeMaxDynamicSharedMemorySize, SMEM_TOTAL);
    cudaFuncSetAttribute(gemm_bf16x3<false, false>,
                         cudaFuncAttributeMaxDynamicSharedMemorySize, SMEM_TOTAL);
    cudaFuncSetAttribute(gemm_bf16x3<false, true>,
                         cudaFuncAttributeMaxDynamicSharedMemorySize, SMEM_TOTAL);
    cudaFuncSetAttribute(gemm_bf16x3<true, false>,
                         cudaFuncAttributeMaxDynamicSharedMemorySize, SMEM_TOTAL);

    // 0) split inputs to (hi,lo) bf16
    split_kernel<<<(ROWS * EMBED / 4 + 255) / 256, 256>>>(X, Xhi, Xlo, ROWS * EMBED / 4);
    split_kernel<<<(3 * EMBED * EMBED / 4 + 255) / 256, 256>>>(Wqkv, Wqkvhi, Wqkvlo,
                                                               3 * EMBED * EMBED / 4);
    split_kernel<<<(EMBED * EMBED / 4 + 255) / 256, 256>>>(Wout, Wouthi, Woutlo,
                                                           EMBED * EMBED / 4);

    // 1) qkv = X Wqkv^T + bqkv  (split output)
    {
        dim3 grid(3 * EMBED / BN, ROWS / BM, 1);
        gemm_bf16x3<true, true><<<grid, 256, SMEM_TOTAL>>>(
            Xhi, Xlo, Wqkvhi, Wqkvlo, bqkv,
            nullptr, qkvhi, qkvlo,
            EMBED, EMBED, EMBED, 3 * EMBED,
            0, 0, 0, 1.0f);
    }
    // 2) vt = V^T (hi,lo)
    {
        dim3 grid(EMBED / 32, SEQ / 32, BATCH);
        transpose_v_kernel<<<grid, 256>>>(qkvhi, qkvlo, vthi, vtlo);
    }
    // 3) att = Q K^T / 32  (fp32 output)
    {
        dim3 grid(SEQ / BN, SEQ / BM, BATCH);
        gemm_bf16x3<false, false><<<grid, 256, SMEM_TOTAL>>>(
            qkvhi, qkvlo, qkvhi + EMBED, qkvlo + EMBED, nullptr,
            att, nullptr, nullptr,
            EMBED, 3 * EMBED, 3 * EMBED, SEQ,
            (long)SEQ * 3 * EMBED, (long)SEQ * 3 * EMBED, (long)SEQ * SEQ,
            1.0f / 32.0f);
    }
    // 4) softmax -> (hi,lo)
    softmax_kernel<<<BATCH * SEQ, 256>>>(att, mask, atthi, attlo);

    // 5) ctx = att vt^T  (split output)
    {
        dim3 grid(EMBED / BN, SEQ / BM, BATCH);
        gemm_bf16x3<false, true><<<grid, 256, SMEM_TOTAL>>>(
            atthi, attlo, vthi, vtlo, nullptr,
            nullptr, ctxhi, ctxlo,
            SEQ, SEQ, SEQ, EMBED,
            (long)SEQ * SEQ, (long)EMBED * SEQ, (long)SEQ * EMBED,
            1.0f);
    }
    // 6) out = ctx Wout^T + bout  (fp32)
    {
        dim3 grid(EMBED / BN, ROWS / BM, 1);
        gemm_bf16x3<true, false><<<grid, 256, SMEM_TOTAL>>>(
            ctxhi, ctxlo, Wouthi, Woutlo, bout,
            out, nullptr, nullptr,
            EMBED, EMBED, EMBED, EMBED,
            0, 0, 0, 1.0f);
    }
}

// round 6
// speedup vs baseline: 1.7377x; 1.5968x over previous
#include <cuda_runtime.h>
#include <cuda_bf16.h>
#include <cstdint>
#include <math.h>

// ---------------------------------------------------------------------------
// SelfAttentionV3 (B=4, S=2048, E=1024) via bf16x3 split-precision HMMA GEMMs.
// Non-'a' PTX only: mma.sync + ldmatrix + cp.async (tcgen05 is arch-gated off).
// R6: R3-proven inner schedule, CTA tile 128x64, warp tile 32x32,
//     2 CTAs/SM (launch_bounds(256,2), <=128 regs), Kc=32, 3-stage 72KB smem.
// ---------------------------------------------------------------------------

#define EMBED 1024
#define BATCH 4
#define SEQ   2048
#define ROWS  (BATCH * SEQ)   // 8192

typedef __nv_bfloat16 bf16;

// ---------------- static scratch (no allocs allowed) -----------------------
__device__ bf16 g_Xhi[(size_t)ROWS * EMBED];
__device__ bf16 g_Xlo[(size_t)ROWS * EMBED];
__device__ bf16 g_Wqkvhi[(size_t)3 * EMBED * EMBED];
__device__ bf16 g_Wqkvlo[(size_t)3 * EMBED * EMBED];
__device__ bf16 g_Wouthi[(size_t)EMBED * EMBED];
__device__ bf16 g_Woutlo[(size_t)EMBED * EMBED];
__device__ bf16 g_qkvhi[(size_t)ROWS * 3 * EMBED];
__device__ bf16 g_qkvlo[(size_t)ROWS * 3 * EMBED];
__device__ float g_att[(size_t)BATCH * SEQ * SEQ];
__device__ bf16 g_atthi[(size_t)BATCH * SEQ * SEQ];
__device__ bf16 g_attlo[(size_t)BATCH * SEQ * SEQ];
__device__ bf16 g_vthi[(size_t)BATCH * EMBED * SEQ];
__device__ bf16 g_vtlo[(size_t)BATCH * EMBED * SEQ];
__device__ bf16 g_ctxhi[(size_t)ROWS * EMBED];
__device__ bf16 g_ctxlo[(size_t)ROWS * EMBED];

// ---------------- PTX helpers ----------------------------------------------
__device__ __forceinline__ uint32_t smem_u32(const void* p) {
    uint32_t a;
    asm("{ .reg .u64 t; cvta.to.shared.u64 t, %1; cvt.u32.u64 %0, t; }"
        : "=r"(a) : "l"(p));
    return a;
}
__device__ __forceinline__ void cp16(uint32_t dst, const void* src) {
    asm volatile("cp.async.cg.shared.global [%0], [%1], 16;"
                 :: "r"(dst), "l"(src) : "memory");
}
__device__ __forceinline__ void cp_commit() {
    asm volatile("cp.async.commit_group;" ::: "memory");
}
template <int N>
__device__ __forceinline__ void cp_wait() {
    asm volatile("cp.async.wait_group %0;" :: "n"(N) : "memory");
}
__device__ __forceinline__ void ldm4(uint32_t* r, uint32_t addr) {
    asm volatile("ldmatrix.sync.aligned.m8n8.x4.shared.b16 {%0,%1,%2,%3}, [%4];"
                 : "=r"(r[0]), "=r"(r[1]), "=r"(r[2]), "=r"(r[3]) : "r"(addr));
}
__device__ __forceinline__ void mma16816(float* c, const uint32_t* a, const uint32_t* b) {
    asm volatile("mma.sync.aligned.m16n8k16.row.col.f32.bf16.bf16.f32 "
                 "{%0,%1,%2,%3}, {%4,%5,%6,%7}, {%8,%9}, {%0,%1,%2,%3};"
                 : "+f"(c[0]), "+f"(c[1]), "+f"(c[2]), "+f"(c[3])
                 : "r"(a[0]), "r"(a[1]), "r"(a[2]), "r"(a[3]), "r"(b[0]), "r"(b[1]));
}
__device__ __forceinline__ void split1(float x, bf16& h, bf16& l) {
    h = __float2bfloat16(x);
    l = __float2bfloat16(x - __bfloat162float(h));
}
__device__ __forceinline__ uint32_t pack2(bf16 a, bf16 b) {
    uint16_t ua = *reinterpret_cast<uint16_t*>(&a);
    uint16_t ub = *reinterpret_cast<uint16_t*>(&b);
    return (uint32_t)ua | ((uint32_t)ub << 16);
}

// ---------------------------------------------------------------------------
// bf16x3 GEMM: C = scale*(A[M,K] x B[N,K]^T) (+bias). CTA tile 128x64, Kc=32.
// smem row (128B): [hi 32 bf16 | lo 32 bf16], XOR-16B swizzle per 8-row group.
// 8 warps in 4(m) x 2(n) grid, warp tile 32x32.
// ---------------------------------------------------------------------------
#define BM 128
#define BN 64
#define NSTAGE 3
#define A_BYTES 16384                    // 128 rows x 128B
#define B_BYTES 8192                     // 64 rows x 128B
#define STAGE_BYTES (A_BYTES + B_BYTES)  // 24576
#define SMEM_TOTAL (NSTAGE * STAGE_BYTES)

template <bool HAS_BIAS, bool SPLIT>
__global__ __launch_bounds__(256, 2) void gemm_bf16x3(
    const bf16* __restrict__ Ahi, const bf16* __restrict__ Alo,
    const bf16* __restrict__ Bhi, const bf16* __restrict__ Blo,
    const float* __restrict__ bias,
    float* __restrict__ C, bf16* __restrict__ Chi, bf16* __restrict__ Clo,
    int K, int lda, int ldb, int ldc,
    long aBS, long bBS, long cBS, float scale)
{
    extern __shared__ char smem[];
    const uint32_t sb = smem_u32(smem);
    const int tid = threadIdx.x;
    const int lane = tid & 31;
    const int wid = tid >> 5;
    const int wm = wid & 3;       // m 32-quarter (0..3)
    const int wn = wid >> 2;      // n 32-half    (0..1)

    const long bm = (long)blockIdx.y * BM;
    const long bn = (long)blockIdx.x * BN;
    Ahi += (long)blockIdx.z * aBS;  Alo += (long)blockIdx.z * aBS;
    Bhi += (long)blockIdx.z * bBS;  Blo += (long)blockIdx.z * bBS;
    if (SPLIT) { Chi += (long)blockIdx.z * cBS; Clo += (long)blockIdx.z * cBS; }
    else       { C   += (long)blockIdx.z * cBS; }

    const int nchunk = K >> 5;

    // ---- cp.async assignments: A 4x16B/thread, B 2x16B/thread ----
    const bf16* pA[4]; const bf16* pB[2];
    uint32_t dA[4], dB[2];
#pragma unroll
    for (int i = 0; i < 4; i++) {
        int ch = tid + i * 256;          // 0..1023
        int row = ch >> 3;               // 0..127
        int q = ch & 7;
        int half = q >> 2;               // 0=hi 1=lo
        int qq = q & 3;                  // 16B quarter within half
        uint32_t col = half * 64 + qq * 16;
        uint32_t sw = col ^ ((row & 7) * 16);
        dA[i] = (uint32_t)(row * 128) + sw;
        pA[i] = (half ? Alo : Ahi) + (size_t)(bm + row) * lda + qq * 8;
    }
#pragma unroll
    for (int i = 0; i < 2; i++) {
        int ch = tid + i * 256;          // 0..511
        int row = ch >> 3;               // 0..63
        int q = ch & 7;
        int half = q >> 2;
        int qq = q & 3;
        uint32_t col = half * 64 + qq * 16;
        uint32_t sw = col ^ ((row & 7) * 16);
        dB[i] = (uint32_t)(row * 128) + sw;
        pB[i] = (half ? Blo : Bhi) + (size_t)(bn + row) * ldb + qq * 8;
    }

    // ---- ldmatrix lane address components ----
    const int rA = (lane & 7) + ((lane >> 3) & 1) * 8;
    const uint32_t cA16 = ((lane >> 4) & 1) * 16;
    const int rB = (lane & 7) + ((lane >> 4) & 1) * 8;
    const uint32_t cB16 = ((lane >> 3) & 1) * 16;

    uint32_t aoff[2], axor[2];
#pragma unroll
    for (int mt = 0; mt < 2; mt++) {
        int arow = wm * 32 + mt * 16 + rA;
        aoff[mt] = arow * 128;
        axor[mt] = (arow & 7) * 16;
    }
    uint32_t boff[2], bxor[2];
#pragma unroll
    for (int t = 0; t < 2; t++) {
        int brow = wn * 32 + t * 16 + rB;
        boff[t] = brow * 128;
        bxor[t] = (brow & 7) * 16;
    }

    float acc[2][4][4];
#pragma unroll
    for (int mt = 0; mt < 2; mt++)
#pragma unroll
        for (int nt = 0; nt < 4; nt++)
#pragma unroll
            for (int r = 0; r < 4; r++) acc[mt][nt][r] = 0.f;

    // ---- prologue: stages 0..1 in flight ----
#pragma unroll
    for (int st = 0; st < NSTAGE - 1; st++) {
        int k0 = st * 32;
        uint32_t base = sb + st * STAGE_BYTES;
#pragma unroll
        for (int i = 0; i < 4; i++) cp16(base + dA[i], pA[i] + k0);
#pragma unroll
        for (int i = 0; i < 2; i++) cp16(base + A_BYTES + dB[i], pB[i] + k0);
        cp_commit();
    }
    cp_wait<NSTAGE - 2>();
    __syncthreads();

    // ---- main loop (R3-proven structure) ----
    for (int kc = 0; kc < nchunk; kc++) {
        const uint32_t baseA = sb + (kc % NSTAGE) * STAGE_BYTES;
        const uint32_t baseB = baseA + A_BYTES;

#pragma unroll
        for (int s = 0; s < 2; s++) {
            uint32_t bh[8], bl[8];
#pragma unroll
            for (int t = 0; t < 2; t++) {
                uint32_t c = s * 32 + cB16;
                ldm4(&bh[t * 4], baseB + boff[t] + (c ^ bxor[t]));
                ldm4(&bl[t * 4], baseB + boff[t] + ((c + 64) ^ bxor[t]));
            }
#pragma unroll
            for (int mt = 0; mt < 2; mt++) {
                uint32_t a[4];
                uint32_t cc = s * 32 + cA16;
                ldm4(a, baseA + aoff[mt] + (cc ^ axor[mt]));
#pragma unroll
                for (int nt = 0; nt < 4; nt++) mma16816(acc[mt][nt], a, &bh[nt * 2]);
#pragma unroll
                for (int nt = 0; nt < 4; nt++) mma16816(acc[mt][nt], a, &bl[nt * 2]);
                ldm4(a, baseA + aoff[mt] + ((cc + 64) ^ axor[mt]));
#pragma unroll
                for (int nt = 0; nt < 4; nt++) mma16816(acc[mt][nt], a, &bh[nt * 2]);
            }
        }
        __syncthreads();

        int next = kc + NSTAGE - 1;
        if (next < nchunk) {
            int k0 = next * 32;
            uint32_t nb = sb + (next % NSTAGE) * STAGE_BYTES;
#pragma unroll
            for (int i = 0; i < 4; i++) cp16(nb + dA[i], pA[i] + k0);
#pragma unroll
            for (int i = 0; i < 2; i++) cp16(nb + A_BYTES + dB[i], pB[i] + k0);
        }
        cp_commit();
        cp_wait<NSTAGE - 2>();
        __syncthreads();
    }

    // ---- epilogue ----
#pragma unroll
    for (int mt = 0; mt < 2; mt++) {
        long r0 = bm + wm * 32 + mt * 16 + (lane >> 2);
        long r1 = r0 + 8;
#pragma unroll
        for (int nt = 0; nt < 4; nt++) {
            long col = bn + wn * 32 + nt * 8 + (lane & 3) * 2;
            float b0v = 0.f, b1v = 0.f;
            if (HAS_BIAS) { b0v = bias[col]; b1v = bias[col + 1]; }
            float v00 = acc[mt][nt][0] * scale + b0v;
            float v01 = acc[mt][nt][1] * scale + b1v;
            float v10 = acc[mt][nt][2] * scale + b0v;
            float v11 = acc[mt][nt][3] * scale + b1v;
            if (SPLIT) {
                bf16 h0, h1, l0, l1;
                split1(v00, h0, l0); split1(v01, h1, l1);
                *reinterpret_cast<uint32_t*>(&Chi[r0 * ldc + col]) = pack2(h0, h1);
                *reinterpret_cast<uint32_t*>(&Clo[r0 * ldc + col]) = pack2(l0, l1);
                split1(v10, h0, l0); split1(v11, h1, l1);
                *reinterpret_cast<uint32_t*>(&Chi[r1 * ldc + col]) = pack2(h0, h1);
                *reinterpret_cast<uint32_t*>(&Clo[r1 * ldc + col]) = pack2(l0, l1);
            } else {
                float2 u0 = make_float2(v00, v01);
                float2 u1 = make_float2(v10, v11);
                *reinterpret_cast<float2*>(&C[r0 * ldc + col]) = u0;
                *reinterpret_cast<float2*>(&C[r1 * ldc + col]) = u1;
            }
        }
    }
}

// ---------------------------------------------------------------------------
// fp32 -> (hi,lo) bf16 split conversion (vectorized)
// ---------------------------------------------------------------------------
__global__ __launch_bounds__(256) void split_kernel(
    const float* __restrict__ src, bf16* __restrict__ hi, bf16* __restrict__ lo, int n4)
{
    int i = blockIdx.x * blockDim.x + threadIdx.x;
    if (i >= n4) return;
    float4 v = reinterpret_cast<const float4*>(src)[i];
    bf16 h0, h1, h2, h3, l0, l1, l2, l3;
    split1(v.x, h0, l0); split1(v.y, h1, l1);
    split1(v.z, h2, l2); split1(v.w, h3, l3);
    uint2 hw = make_uint2(pack2(h0, h1), pack2(h2, h3));
    uint2 lw = make_uint2(pack2(l0, l1), pack2(l2, l3));
    reinterpret_cast<uint2*>(hi)[i] = hw;
    reinterpret_cast<uint2*>(lo)[i] = lw;
}

// ---------------------------------------------------------------------------
// V transpose (hi & lo): vt[b][e][s] = qkv[b*S+s][2E+e]
// ---------------------------------------------------------------------------
__global__ __launch_bounds__(256) void transpose_v_kernel(
    const bf16* __restrict__ qh, const bf16* __restrict__ ql,
    bf16* __restrict__ vth, bf16* __restrict__ vtl)
{
    __shared__ bf16 th[32][33];
    __shared__ bf16 tl[32][33];
    const int b = blockIdx.z;
    const int e0 = blockIdx.x * 32;
    const int s0 = blockIdx.y * 32;
    const int tx = threadIdx.x & 31;
    const int ty = threadIdx.x >> 5;  // 0..7
#pragma unroll
    for (int i = 0; i < 4; i++) {
        int s = s0 + ty + i * 8;
        size_t idx = (size_t)(b * SEQ + s) * (3 * EMBED) + 2 * EMBED + e0 + tx;
        th[ty + i * 8][tx] = qh[idx];
        tl[ty + i * 8][tx] = ql[idx];
    }
    __syncthreads();
#pragma unroll
    for (int i = 0; i < 4; i++) {
        int e = e0 + ty + i * 8;
        size_t o = (size_t)(b * EMBED + e) * SEQ + s0 + tx;
        vth[o] = th[tx][ty + i * 8];
        vtl[o] = tl[tx][ty + i * 8];
    }
}

// ---------------------------------------------------------------------------
// Row softmax with mask; writes (hi,lo) bf16 probabilities.
// ---------------------------------------------------------------------------
__global__ __launch_bounds__(256) void softmax_kernel(
    const float* __restrict__ att, const int* __restrict__ mask,
    bf16* __restrict__ phi, bf16* __restrict__ plo)
{
    const size_t row = blockIdx.x;
    const float* a = att + row * SEQ;
    const int* m = mask + row * SEQ;
    const int tid = threadIdx.x;

    __shared__ float red_max[8];
    __shared__ float red_sum[8];

    float v[8];
    float mx = -INFINITY;
#pragma unroll
    for (int i = 0; i < 8; i++) {
        int idx = tid + i * 256;
        float x = a[idx];
        x = (m[idx] != 0) ? x : -INFINITY;
        v[i] = x;
        mx = fmaxf(mx, x);
    }
#pragma unroll
    for (int o = 16; o > 0; o >>= 1)
        mx = fmaxf(mx, __shfl_xor_sync(0xffffffffu, mx, o));
    if ((tid & 31) == 0) red_max[tid >> 5] = mx;
    __syncthreads();
    float bmax = red_max[0];
#pragma unroll
    for (int w = 1; w < 8; w++) bmax = fmaxf(bmax, red_max[w]);

    float s = 0.f;
#pragma unroll
    for (int i = 0; i < 8; i++) {
        v[i] = __expf(v[i] - bmax);
        s += v[i];
    }
#pragma unroll
    for (int o = 16; o > 0; o >>= 1)
        s += __shfl_xor_sync(0xffffffffu, s, o);
    if ((tid & 31) == 0) red_sum[tid >> 5] = s;
    __syncthreads();
    float total = 0.f;
#pragma unroll
    for (int w = 0; w < 8; w++) total += red_sum[w];

    float inv = 1.f / total;
#pragma unroll
    for (int i = 0; i < 8; i++) {
        int idx = tid + i * 256;
        float p = v[i] * inv;
        bf16 h, l;
        split1(p, h, l);
        phi[row * SEQ + idx] = h;
        plo[row * SEQ + idx] = l;
    }
}

// ---------------------------------------------------------------------------
extern "C" void kernel_launch(void* const* d_in, const int* in_sizes, int n_in,
                              void* d_out, int out_size)
{
    const float* X    = (const float*)d_in[0];
    const int*   mask = (const int*)  d_in[1];
    const float* Wqkv = (const float*)d_in[2];
    const float* bqkv = (const float*)d_in[3];
    const float* Wout = (const float*)d_in[4];
    const float* bout = (const float*)d_in[5];
    float* out = (float*)d_out;

    bf16 *Xhi, *Xlo, *Wqkvhi, *Wqkvlo, *Wouthi, *Woutlo;
    bf16 *qkvhi, *qkvlo, *atthi, *attlo, *vthi, *vtlo, *ctxhi, *ctxlo;
    float* att;
    cudaGetSymbolAddress((void**)&Xhi, g_Xhi);
    cudaGetSymbolAddress((void**)&Xlo, g_Xlo);
    cudaGetSymbolAddress((void**)&Wqkvhi, g_Wqkvhi);
    cudaGetSymbolAddress((void**)&Wqkvlo, g_Wqkvlo);
    cudaGetSymbolAddress((void**)&Wouthi, g_Wouthi);
    cudaGetSymbolAddress((void**)&Woutlo, g_Woutlo);
    cudaGetSymbolAddress((void**)&qkvhi, g_qkvhi);
    cudaGetSymbolAddress((void**)&qkvlo, g_qkvlo);
    cudaGetSymbolAddress((void**)&att, g_att);
    cudaGetSymbolAddress((void**)&atthi, g_atthi);
    cudaGetSymbolAddress((void**)&attlo, g_attlo);
    cudaGetSymbolAddress((void**)&vthi, g_vthi);
    cudaGetSymbolAddress((void**)&vtlo, g_vtlo);
    cudaGetSymbolAddress((void**)&ctxhi, g_ctxhi);
    cudaGetSymbolAddress((void**)&ctxlo, g_ctxlo);

    cudaFuncSetAttribute(gemm_bf16x3<true, true>,
                         cudaFuncAttributeMaxDynamicSharedMemorySize, SMEM_TOTAL);
    cudaFuncSetAttribute(gemm_bf16x3<false, false>,
                         cudaFuncAttributeMaxDynamicSharedMemorySize, SMEM_TOTAL);
    cudaFuncSetAttribute(gemm_bf16x3<false, true>,
                         cudaFuncAttributeMaxDynamicSharedMemorySize, SMEM_TOTAL);
    cudaFuncSetAttribute(gemm_bf16x3<true, false>,
                         cudaFuncAttributeMaxDynamicSharedMemorySize, SMEM_TOTAL);

    // 0) split inputs to (hi,lo) bf16
    split_kernel<<<(ROWS * EMBED / 4 + 255) / 256, 256>>>(X, Xhi, Xlo, ROWS * EMBED / 4);
    split_kernel<<<(3 * EMBED * EMBED / 4 + 255) / 256, 256>>>(Wqkv, Wqkvhi, Wqkvlo,
                                                               3 * EMBED * EMBED / 4);
    split_kernel<<<(EMBED * EMBED / 4 + 255) / 256, 256>>>(Wout, Wouthi, Woutlo,
                                                           EMBED * EMBED / 4);

    // 1) qkv = X Wqkv^T + bqkv  (split output)
    {
        dim3 grid(3 * EMBED / BN, ROWS / BM, 1);
        gemm_bf16x3<true, true><<<grid, 256, SMEM_TOTAL>>>(
            Xhi, Xlo, Wqkvhi, Wqkvlo, bqkv,
            nullptr, qkvhi, qkvlo,
            EMBED, EMBED, EMBED, 3 * EMBED,
            0, 0, 0, 1.0f);
    }
    // 2) vt = V^T (hi,lo)
    {
        dim3 grid(EMBED / 32, SEQ / 32, BATCH);
        transpose_v_kernel<<<grid, 256>>>(qkvhi, qkvlo, vthi, vtlo);
    }
    // 3) att = Q K^T / 32  (fp32 output)
    {
        dim3 grid(SEQ / BN, SEQ / BM, BATCH);
        gemm_bf16x3<false, false><<<grid, 256, SMEM_TOTAL>>>(
            qkvhi, qkvlo, qkvhi + EMBED, qkvlo + EMBED, nullptr,
            att, nullptr, nullptr,
            EMBED, 3 * EMBED, 3 * EMBED, SEQ,
            (long)SEQ * 3 * EMBED, (long)SEQ * 3 * EMBED, (long)SEQ * SEQ,
            1.0f / 32.0f);
    }
    // 4) softmax -> (hi,lo)
    softmax_kernel<<<BATCH * SEQ, 256>>>(att, mask, atthi, attlo);

    // 5) ctx = att vt^T  (split output)
    {
        dim3 grid(EMBED / BN, SEQ / BM, BATCH);
        gemm_bf16x3<false, true><<<grid, 256, SMEM_TOTAL>>>(
            atthi, attlo, vthi, vtlo, nullptr,
            nullptr, ctxhi, ctxlo,
            SEQ, SEQ, SEQ, EMBED,
            (long)SEQ * SEQ, (long)EMBED * SEQ, (long)SEQ * EMBED,
            1.0f);
    }
    // 6) out = ctx Wout^T + bout  (fp32)
    {
        dim3 grid(EMBED / BN, ROWS / BM, 1);
        gemm_bf16x3<true, false><<<grid, 256, SMEM_TOTAL>>>(
            ctxhi, ctxlo, Wouthi, Woutlo, bout,
            out, nullptr, nullptr,
            EMBED, EMBED, EMBED, EMBED,
            0, 0, 0, 1.0f);
    }
}

// round 7
// speedup vs baseline: 1.7692x; 1.0181x over previous
#include <cuda_runtime.h>
#include <cuda_bf16.h>
#include <cstdint>
#include <math.h>

// ---------------------------------------------------------------------------
// SelfAttentionV3 (B=4, S=2048, E=1024) via bf16x3 split-precision HMMA GEMMs.
// Non-'a' PTX only: mma.sync + ldmatrix + cp.async (tcgen05 is arch-gated off).
// R7: R6 config (128x64 CTA, 32x32 warp tile, 2 CTAs/SM, <=128 regs) +
//     single barrier per K-chunk (prefetch-first) + 4-stage pipeline.
// ---------------------------------------------------------------------------

#define EMBED 1024
#define BATCH 4
#define SEQ   2048
#define ROWS  (BATCH * SEQ)   // 8192

typedef __nv_bfloat16 bf16;

// ---------------- static scratch (no allocs allowed) -----------------------
__device__ bf16 g_Xhi[(size_t)ROWS * EMBED];
__device__ bf16 g_Xlo[(size_t)ROWS * EMBED];
__device__ bf16 g_Wqkvhi[(size_t)3 * EMBED * EMBED];
__device__ bf16 g_Wqkvlo[(size_t)3 * EMBED * EMBED];
__device__ bf16 g_Wouthi[(size_t)EMBED * EMBED];
__device__ bf16 g_Woutlo[(size_t)EMBED * EMBED];
__device__ bf16 g_qkvhi[(size_t)ROWS * 3 * EMBED];
__device__ bf16 g_qkvlo[(size_t)ROWS * 3 * EMBED];
__device__ float g_att[(size_t)BATCH * SEQ * SEQ];
__device__ bf16 g_atthi[(size_t)BATCH * SEQ * SEQ];
__device__ bf16 g_attlo[(size_t)BATCH * SEQ * SEQ];
__device__ bf16 g_vthi[(size_t)BATCH * EMBED * SEQ];
__device__ bf16 g_vtlo[(size_t)BATCH * EMBED * SEQ];
__device__ bf16 g_ctxhi[(size_t)ROWS * EMBED];
__device__ bf16 g_ctxlo[(size_t)ROWS * EMBED];

// ---------------- PTX helpers ----------------------------------------------
__device__ __forceinline__ uint32_t smem_u32(const void* p) {
    uint32_t a;
    asm("{ .reg .u64 t; cvta.to.shared.u64 t, %1; cvt.u32.u64 %0, t; }"
        : "=r"(a) : "l"(p));
    return a;
}
__device__ __forceinline__ void cp16(uint32_t dst, const void* src) {
    asm volatile("cp.async.cg.shared.global [%0], [%1], 16;"
                 :: "r"(dst), "l"(src) : "memory");
}
__device__ __forceinline__ void cp_commit() {
    asm volatile("cp.async.commit_group;" ::: "memory");
}
template <int N>
__device__ __forceinline__ void cp_wait() {
    asm volatile("cp.async.wait_group %0;" :: "n"(N) : "memory");
}
__device__ __forceinline__ void ldm4(uint32_t* r, uint32_t addr) {
    asm volatile("ldmatrix.sync.aligned.m8n8.x4.shared.b16 {%0,%1,%2,%3}, [%4];"
                 : "=r"(r[0]), "=r"(r[1]), "=r"(r[2]), "=r"(r[3]) : "r"(addr));
}
__device__ __forceinline__ void mma16816(float* c, const uint32_t* a, const uint32_t* b) {
    asm volatile("mma.sync.aligned.m16n8k16.row.col.f32.bf16.bf16.f32 "
                 "{%0,%1,%2,%3}, {%4,%5,%6,%7}, {%8,%9}, {%0,%1,%2,%3};"
                 : "+f"(c[0]), "+f"(c[1]), "+f"(c[2]), "+f"(c[3])
                 : "r"(a[0]), "r"(a[1]), "r"(a[2]), "r"(a[3]), "r"(b[0]), "r"(b[1]));
}
__device__ __forceinline__ void split1(float x, bf16& h, bf16& l) {
    h = __float2bfloat16(x);
    l = __float2bfloat16(x - __bfloat162float(h));
}
__device__ __forceinline__ uint32_t pack2(bf16 a, bf16 b) {
    uint16_t ua = *reinterpret_cast<uint16_t*>(&a);
    uint16_t ub = *reinterpret_cast<uint16_t*>(&b);
    return (uint32_t)ua | ((uint32_t)ub << 16);
}

// ---------------------------------------------------------------------------
// bf16x3 GEMM: C = scale*(A[M,K] x B[N,K]^T) (+bias). CTA tile 128x64, Kc=32.
// smem row (128B): [hi 32 bf16 | lo 32 bf16], XOR-16B swizzle per 8-row group.
// 8 warps in 4(m) x 2(n) grid, warp tile 32x32.
// ---------------------------------------------------------------------------
#define BM 128
#define BN 64
#define NSTAGE 4
#define A_BYTES 16384                    // 128 rows x 128B
#define B_BYTES 8192                     // 64 rows x 128B
#define STAGE_BYTES (A_BYTES + B_BYTES)  // 24576
#define SMEM_TOTAL (NSTAGE * STAGE_BYTES)  // 98304

template <bool HAS_BIAS, bool SPLIT>
__global__ __launch_bounds__(256, 2) void gemm_bf16x3(
    const bf16* __restrict__ Ahi, const bf16* __restrict__ Alo,
    const bf16* __restrict__ Bhi, const bf16* __restrict__ Blo,
    const float* __restrict__ bias,
    float* __restrict__ C, bf16* __restrict__ Chi, bf16* __restrict__ Clo,
    int K, int lda, int ldb, int ldc,
    long aBS, long bBS, long cBS, float scale)
{
    extern __shared__ char smem[];
    const uint32_t sb = smem_u32(smem);
    const int tid = threadIdx.x;
    const int lane = tid & 31;
    const int wid = tid >> 5;
    const int wm = wid & 3;       // m 32-quarter (0..3)
    const int wn = wid >> 2;      // n 32-half    (0..1)

    const long bm = (long)blockIdx.y * BM;
    const long bn = (long)blockIdx.x * BN;
    Ahi += (long)blockIdx.z * aBS;  Alo += (long)blockIdx.z * aBS;
    Bhi += (long)blockIdx.z * bBS;  Blo += (long)blockIdx.z * bBS;
    if (SPLIT) { Chi += (long)blockIdx.z * cBS; Clo += (long)blockIdx.z * cBS; }
    else       { C   += (long)blockIdx.z * cBS; }

    const int nchunk = K >> 5;

    // ---- cp.async assignments: A 4x16B/thread, B 2x16B/thread ----
    const bf16* pA[4]; const bf16* pB[2];
    uint32_t dA[4], dB[2];
#pragma unroll
    for (int i = 0; i < 4; i++) {
        int ch = tid + i * 256;          // 0..1023
        int row = ch >> 3;               // 0..127
        int q = ch & 7;
        int half = q >> 2;               // 0=hi 1=lo
        int qq = q & 3;                  // 16B quarter within half
        uint32_t col = half * 64 + qq * 16;
        uint32_t sw = col ^ ((row & 7) * 16);
        dA[i] = (uint32_t)(row * 128) + sw;
        pA[i] = (half ? Alo : Ahi) + (size_t)(bm + row) * lda + qq * 8;
    }
#pragma unroll
    for (int i = 0; i < 2; i++) {
        int ch = tid + i * 256;          // 0..511
        int row = ch >> 3;               // 0..63
        int q = ch & 7;
        int half = q >> 2;
        int qq = q & 3;
        uint32_t col = half * 64 + qq * 16;
        uint32_t sw = col ^ ((row & 7) * 16);
        dB[i] = (uint32_t)(row * 128) + sw;
        pB[i] = (half ? Blo : Bhi) + (size_t)(bn + row) * ldb + qq * 8;
    }

    // ---- ldmatrix lane address components ----
    const int rA = (lane & 7) + ((lane >> 3) & 1) * 8;
    const uint32_t cA16 = ((lane >> 4) & 1) * 16;
    const int rB = (lane & 7) + ((lane >> 4) & 1) * 8;
    const uint32_t cB16 = ((lane >> 3) & 1) * 16;

    uint32_t aoff[2], axor[2];
#pragma unroll
    for (int mt = 0; mt < 2; mt++) {
        int arow = wm * 32 + mt * 16 + rA;
        aoff[mt] = arow * 128;
        axor[mt] = (arow & 7) * 16;
    }
    uint32_t boff[2], bxor[2];
#pragma unroll
    for (int t = 0; t < 2; t++) {
        int brow = wn * 32 + t * 16 + rB;
        boff[t] = brow * 128;
        bxor[t] = (brow & 7) * 16;
    }

    float acc[2][4][4];
#pragma unroll
    for (int mt = 0; mt < 2; mt++)
#pragma unroll
        for (int nt = 0; nt < 4; nt++)
#pragma unroll
            for (int r = 0; r < 4; r++) acc[mt][nt][r] = 0.f;

    // ---- prologue: stages 0..NSTAGE-2 in flight ----
#pragma unroll
    for (int st = 0; st < NSTAGE - 1; st++) {
        int k0 = st * 32;
        uint32_t base = sb + st * STAGE_BYTES;
#pragma unroll
        for (int i = 0; i < 4; i++) cp16(base + dA[i], pA[i] + k0);
#pragma unroll
        for (int i = 0; i < 2; i++) cp16(base + A_BYTES + dB[i], pB[i] + k0);
        cp_commit();
    }
    cp_wait<NSTAGE - 2>();
    __syncthreads();

    // ---- main loop: ONE barrier per chunk ----
    for (int kc = 0; kc < nchunk; kc++) {
        const uint32_t baseA = sb + (kc % NSTAGE) * STAGE_BYTES;
        const uint32_t baseB = baseA + A_BYTES;

        // prefetch chunk kc+NSTAGE-1 into the stage consumed at kc-1
        // (the barrier that ended iteration kc-1 guarantees it is free)
        int next = kc + NSTAGE - 1;
        if (next < nchunk) {
            int k0 = next * 32;
            uint32_t nb = sb + (next % NSTAGE) * STAGE_BYTES;
#pragma unroll
            for (int i = 0; i < 4; i++) cp16(nb + dA[i], pA[i] + k0);
#pragma unroll
            for (int i = 0; i < 2; i++) cp16(nb + A_BYTES + dB[i], pB[i] + k0);
        }
        cp_commit();

        // compute current chunk (R3/R6-proven per-step fragment schedule)
#pragma unroll
        for (int s = 0; s < 2; s++) {
            uint32_t bh[8], bl[8];
#pragma unroll
            for (int t = 0; t < 2; t++) {
                uint32_t c = s * 32 + cB16;
                ldm4(&bh[t * 4], baseB + boff[t] + (c ^ bxor[t]));
                ldm4(&bl[t * 4], baseB + boff[t] + ((c + 64) ^ bxor[t]));
            }
#pragma unroll
            for (int mt = 0; mt < 2; mt++) {
                uint32_t a[4];
                uint32_t cc = s * 32 + cA16;
                ldm4(a, baseA + aoff[mt] + (cc ^ axor[mt]));
#pragma unroll
                for (int nt = 0; nt < 4; nt++) mma16816(acc[mt][nt], a, &bh[nt * 2]);
#pragma unroll
                for (int nt = 0; nt < 4; nt++) mma16816(acc[mt][nt], a, &bl[nt * 2]);
                ldm4(a, baseA + aoff[mt] + ((cc + 64) ^ axor[mt]));
#pragma unroll
                for (int nt = 0; nt < 4; nt++) mma16816(acc[mt][nt], a, &bh[nt * 2]);
            }
        }

        cp_wait<NSTAGE - 2>();   // chunk kc+1 resident
        __syncthreads();
    }

    // ---- epilogue ----
#pragma unroll
    for (int mt = 0; mt < 2; mt++) {
        long r0 = bm + wm * 32 + mt * 16 + (lane >> 2);
        long r1 = r0 + 8;
#pragma unroll
        for (int nt = 0; nt < 4; nt++) {
            long col = bn + wn * 32 + nt * 8 + (lane & 3) * 2;
            float b0v = 0.f, b1v = 0.f;
            if (HAS_BIAS) { b0v = bias[col]; b1v = bias[col + 1]; }
            float v00 = acc[mt][nt][0] * scale + b0v;
            float v01 = acc[mt][nt][1] * scale + b1v;
            float v10 = acc[mt][nt][2] * scale + b0v;
            float v11 = acc[mt][nt][3] * scale + b1v;
            if (SPLIT) {
                bf16 h0, h1, l0, l1;
                split1(v00, h0, l0); split1(v01, h1, l1);
                *reinterpret_cast<uint32_t*>(&Chi[r0 * ldc + col]) = pack2(h0, h1);
                *reinterpret_cast<uint32_t*>(&Clo[r0 * ldc + col]) = pack2(l0, l1);
                split1(v10, h0, l0); split1(v11, h1, l1);
                *reinterpret_cast<uint32_t*>(&Chi[r1 * ldc + col]) = pack2(h0, h1);
                *reinterpret_cast<uint32_t*>(&Clo[r1 * ldc + col]) = pack2(l0, l1);
            } else {
                float2 u0 = make_float2(v00, v01);
                float2 u1 = make_float2(v10, v11);
                *reinterpret_cast<float2*>(&C[r0 * ldc + col]) = u0;
                *reinterpret_cast<float2*>(&C[r1 * ldc + col]) = u1;
            }
        }
    }
}

// ---------------------------------------------------------------------------
// fp32 -> (hi,lo) bf16 split conversion (vectorized)
// ---------------------------------------------------------------------------
__global__ __launch_bounds__(256) void split_kernel(
    const float* __restrict__ src, bf16* __restrict__ hi, bf16* __restrict__ lo, int n4)
{
    int i = blockIdx.x * blockDim.x + threadIdx.x;
    if (i >= n4) return;
    float4 v = reinterpret_cast<const float4*>(src)[i];
    bf16 h0, h1, h2, h3, l0, l1, l2, l3;
    split1(v.x, h0, l0); split1(v.y, h1, l1);
    split1(v.z, h2, l2); split1(v.w, h3, l3);
    uint2 hw = make_uint2(pack2(h0, h1), pack2(h2, h3));
    uint2 lw = make_uint2(pack2(l0, l1), pack2(l2, l3));
    reinterpret_cast<uint2*>(hi)[i] = hw;
    reinterpret_cast<uint2*>(lo)[i] = lw;
}

// ---------------------------------------------------------------------------
// V transpose (hi & lo): vt[b][e][s] = qkv[b*S+s][2E+e]
// ---------------------------------------------------------------------------
__global__ __launch_bounds__(256) void transpose_v_kernel(
    const bf16* __restrict__ qh, const bf16* __restrict__ ql,
    bf16* __restrict__ vth, bf16* __restrict__ vtl)
{
    __shared__ bf16 th[32][33];
    __shared__ bf16 tl[32][33];
    const int b = blockIdx.z;
    const int e0 = blockIdx.x * 32;
    const int s0 = blockIdx.y * 32;
    const int tx = threadIdx.x & 31;
    const int ty = threadIdx.x >> 5;  // 0..7
#pragma unroll
    for (int i = 0; i < 4; i++) {
        int s = s0 + ty + i * 8;
        size_t idx = (size_t)(b * SEQ + s) * (3 * EMBED) + 2 * EMBED + e0 + tx;
        th[ty + i * 8][tx] = qh[idx];
        tl[ty + i * 8][tx] = ql[idx];
    }
    __syncthreads();
#pragma unroll
    for (int i = 0; i < 4; i++) {
        int e = e0 + ty + i * 8;
        size_t o = (size_t)(b * EMBED + e) * SEQ + s0 + tx;
        vth[o] = th[tx][ty + i * 8];
        vtl[o] = tl[tx][ty + i * 8];
    }
}

// ---------------------------------------------------------------------------
// Row softmax with mask; writes (hi,lo) bf16 probabilities.
// ---------------------------------------------------------------------------
__global__ __launch_bounds__(256) void softmax_kernel(
    const float* __restrict__ att, const int* __restrict__ mask,
    bf16* __restrict__ phi, bf16* __restrict__ plo)
{
    const size_t row = blockIdx.x;
    const float* a = att + row * SEQ;
    const int* m = mask + row * SEQ;
    const int tid = threadIdx.x;

    __shared__ float red_max[8];
    __shared__ float red_sum[8];

    float v[8];
    float mx = -INFINITY;
#pragma unroll
    for (int i = 0; i < 8; i++) {
        int idx = tid + i * 256;
        float x = a[idx];
        x = (m[idx] != 0) ? x : -INFINITY;
        v[i] = x;
        mx = fmaxf(mx, x);
    }
#pragma unroll
    for (int o = 16; o > 0; o >>= 1)
        mx = fmaxf(mx, __shfl_xor_sync(0xffffffffu, mx, o));
    if ((tid & 31) == 0) red_max[tid >> 5] = mx;
    __syncthreads();
    float bmax = red_max[0];
#pragma unroll
    for (int w = 1; w < 8; w++) bmax = fmaxf(bmax, red_max[w]);

    float s = 0.f;
#pragma unroll
    for (int i = 0; i < 8; i++) {
        v[i] = __expf(v[i] - bmax);
        s += v[i];
    }
#pragma unroll
    for (int o = 16; o > 0; o >>= 1)
        s += __shfl_xor_sync(0xffffffffu, s, o);
    if ((tid & 31) == 0) red_sum[tid >> 5] = s;
    __syncthreads();
    float total = 0.f;
#pragma unroll
    for (int w = 0; w < 8; w++) total += red_sum[w];

    float inv = 1.f / total;
#pragma unroll
    for (int i = 0; i < 8; i++) {
        int idx = tid + i * 256;
        float p = v[i] * inv;
        bf16 h, l;
        split1(p, h, l);
        phi[row * SEQ + idx] = h;
        plo[row * SEQ + idx] = l;
    }
}

// ---------------------------------------------------------------------------
extern "C" void kernel_launch(void* const* d_in, const int* in_sizes, int n_in,
                              void* d_out, int out_size)
{
    const float* X    = (const float*)d_in[0];
    const int*   mask = (const int*)  d_in[1];
    const float* Wqkv = (const float*)d_in[2];
    const float* bqkv = (const float*)d_in[3];
    const float* Wout = (const float*)d_in[4];
    const float* bout = (const float*)d_in[5];
    float* out = (float*)d_out;

    bf16 *Xhi, *Xlo, *Wqkvhi, *Wqkvlo, *Wouthi, *Woutlo;
    bf16 *qkvhi, *qkvlo, *atthi, *attlo, *vthi, *vtlo, *ctxhi, *ctxlo;
    float* att;
    cudaGetSymbolAddress((void**)&Xhi, g_Xhi);
    cudaGetSymbolAddress((void**)&Xlo, g_Xlo);
    cudaGetSymbolAddress((void**)&Wqkvhi, g_Wqkvhi);
    cudaGetSymbolAddress((void**)&Wqkvlo, g_Wqkvlo);
    cudaGetSymbolAddress((void**)&Wouthi, g_Wouthi);
    cudaGetSymbolAddress((void**)&Woutlo, g_Woutlo);
    cudaGetSymbolAddress((void**)&qkvhi, g_qkvhi);
    cudaGetSymbolAddress((void**)&qkvlo, g_qkvlo);
    cudaGetSymbolAddress((void**)&att, g_att);
    cudaGetSymbolAddress((void**)&atthi, g_atthi);
    cudaGetSymbolAddress((void**)&attlo, g_attlo);
    cudaGetSymbolAddress((void**)&vthi, g_vthi);
    cudaGetSymbolAddress((void**)&vtlo, g_vtlo);
    cudaGetSymbolAddress((void**)&ctxhi, g_ctxhi);
    cudaGetSymbolAddress((void**)&ctxlo, g_ctxlo);

    cudaFuncSetAttribute(gemm_bf16x3<true, true>,
                         cudaFuncAttributeMaxDynamicSharedMemorySize, SMEM_TOTAL);
    cudaFuncSetAttribute(gemm_bf16x3<false, false>,
                         cudaFuncAttributeMaxDynamicSharedMemorySize, SMEM_TOTAL);
    cudaFuncSetAttribute(gemm_bf16x3<false, true>,
                         cudaFuncAttributeMaxDynamicSharedMemorySize, SMEM_TOTAL);
    cudaFuncSetAttribute(gemm_bf16x3<true, false>,
                         cudaFuncAttributeMaxDynamicSharedMemorySize, SMEM_TOTAL);

    // 0) split inputs to (hi,lo) bf16
    split_kernel<<<(ROWS * EMBED / 4 + 255) / 256, 256>>>(X, Xhi, Xlo, ROWS * EMBED / 4);
    split_kernel<<<(3 * EMBED * EMBED / 4 + 255) / 256, 256>>>(Wqkv, Wqkvhi, Wqkvlo,
                                                               3 * EMBED * EMBED / 4);
    split_kernel<<<(EMBED * EMBED / 4 + 255) / 256, 256>>>(Wout, Wouthi, Woutlo,
                                                           EMBED * EMBED / 4);

    // 1) qkv = X Wqkv^T + bqkv  (split output)
    {
        dim3 grid(3 * EMBED / BN, ROWS / BM, 1);
        gemm_bf16x3<true, true><<<grid, 256, SMEM_TOTAL>>>(
            Xhi, Xlo, Wqkvhi, Wqkvlo, bqkv,
            nullptr, qkvhi, qkvlo,
            EMBED, EMBED, EMBED, 3 * EMBED,
            0, 0, 0, 1.0f);
    }
    // 2) vt = V^T (hi,lo)
    {
        dim3 grid(EMBED / 32, SEQ / 32, BATCH);
        transpose_v_kernel<<<grid, 256>>>(qkvhi, qkvlo, vthi, vtlo);
    }
    // 3) att = Q K^T / 32  (fp32 output)
    {
        dim3 grid(SEQ / BN, SEQ / BM, BATCH);
        gemm_bf16x3<false, false><<<grid, 256, SMEM_TOTAL>>>(
            qkvhi, qkvlo, qkvhi + EMBED, qkvlo + EMBED, nullptr,
            att, nullptr, nullptr,
            EMBED, 3 * EMBED, 3 * EMBED, SEQ,
            (long)SEQ * 3 * EMBED, (long)SEQ * 3 * EMBED, (long)SEQ * SEQ,
            1.0f / 32.0f);
    }
    // 4) softmax -> (hi,lo)
    softmax_kernel<<<BATCH * SEQ, 256>>>(att, mask, atthi, attlo);

    // 5) ctx = att vt^T  (split output)
    {
        dim3 grid(EMBED / BN, SEQ / BM, BATCH);
        gemm_bf16x3<false, true><<<grid, 256, SMEM_TOTAL>>>(
            atthi, attlo, vthi, vtlo, nullptr,
            nullptr, ctxhi, ctxlo,
            SEQ, SEQ, SEQ, EMBED,
            (long)SEQ * SEQ, (long)EMBED * SEQ, (long)SEQ * EMBED,
            1.0f);
    }
    // 6) out = ctx Wout^T + bout  (fp32)
    {
        dim3 grid(EMBED / BN, ROWS / BM, 1);
        gemm_bf16x3<true, false><<<grid, 256, SMEM_TOTAL>>>(
            ctxhi, ctxlo, Wouthi, Woutlo, bout,
            out, nullptr, nullptr,
            EMBED, EMBED, EMBED, EMBED,
            0, 0, 0, 1.0f);
    }
}

// round 8
// speedup vs baseline: 2.5033x; 1.4149x over previous
#include <cuda_runtime.h>
#include <cuda_fp16.h>
#include <cstdint>
#include <math.h>

// ---------------------------------------------------------------------------
// SelfAttentionV3 (B=4, S=2048, E=1024) via fp16x2 split-precision HMMA GEMMs.
// C ~= Ahi*Bhi + Ahi*Blo  (A-side lo dropped; fp16 keeps 11 mantissa bits ->
// per-GEMM rel err ~2e-4, RSS over 4 stages ~5e-4 < 1e-3 threshold).
// R8: R6/R7-proven config (128x64 CTA, 32x32 warp tile, 2 CTAs/SM, Kc=32,
// 4-stage single-barrier cp.async pipeline), 33% fewer MMAs than bf16x3.
// ---------------------------------------------------------------------------

#define EMBED 1024
#define BATCH 4
#define SEQ   2048
#define ROWS  (BATCH * SEQ)   // 8192

typedef __half h16;

// ---------------- static scratch (no allocs allowed) -----------------------
__device__ h16 g_Xhi[(size_t)ROWS * EMBED];
__device__ h16 g_Wqkvhi[(size_t)3 * EMBED * EMBED];
__device__ h16 g_Wqkvlo[(size_t)3 * EMBED * EMBED];
__device__ h16 g_Wouthi[(size_t)EMBED * EMBED];
__device__ h16 g_Woutlo[(size_t)EMBED * EMBED];
__device__ h16 g_qkvhi[(size_t)ROWS * 3 * EMBED];
__device__ h16 g_qkvlo[(size_t)ROWS * 3 * EMBED];
__device__ float g_att[(size_t)BATCH * SEQ * SEQ];
__device__ h16 g_atthi[(size_t)BATCH * SEQ * SEQ];
__device__ h16 g_vthi[(size_t)BATCH * EMBED * SEQ];
__device__ h16 g_vtlo[(size_t)BATCH * EMBED * SEQ];
__device__ h16 g_ctxhi[(size_t)ROWS * EMBED];

// ---------------- PTX helpers ----------------------------------------------
__device__ __forceinline__ uint32_t smem_u32(const void* p) {
    uint32_t a;
    asm("{ .reg .u64 t; cvta.to.shared.u64 t, %1; cvt.u32.u64 %0, t; }"
        : "=r"(a) : "l"(p));
    return a;
}
__device__ __forceinline__ void cp16(uint32_t dst, const void* src) {
    asm volatile("cp.async.cg.shared.global [%0], [%1], 16;"
                 :: "r"(dst), "l"(src) : "memory");
}
__device__ __forceinline__ void cp_commit() {
    asm volatile("cp.async.commit_group;" ::: "memory");
}
template <int N>
__device__ __forceinline__ void cp_wait() {
    asm volatile("cp.async.wait_group %0;" :: "n"(N) : "memory");
}
__device__ __forceinline__ void ldm4(uint32_t* r, uint32_t addr) {
    asm volatile("ldmatrix.sync.aligned.m8n8.x4.shared.b16 {%0,%1,%2,%3}, [%4];"
                 : "=r"(r[0]), "=r"(r[1]), "=r"(r[2]), "=r"(r[3]) : "r"(addr));
}
__device__ __forceinline__ void mma16816(float* c, const uint32_t* a, const uint32_t* b) {
    asm volatile("mma.sync.aligned.m16n8k16.row.col.f32.f16.f16.f32 "
                 "{%0,%1,%2,%3}, {%4,%5,%6,%7}, {%8,%9}, {%0,%1,%2,%3};"
                 : "+f"(c[0]), "+f"(c[1]), "+f"(c[2]), "+f"(c[3])
                 : "r"(a[0]), "r"(a[1]), "r"(a[2]), "r"(a[3]), "r"(b[0]), "r"(b[1]));
}
__device__ __forceinline__ void split1(float x, h16& h, h16& l) {
    h = __float2half(x);
    l = __float2half(x - __half2float(h));
}
__device__ __forceinline__ uint32_t pack2(h16 a, h16 b) {
    uint16_t ua = *reinterpret_cast<uint16_t*>(&a);
    uint16_t ub = *reinterpret_cast<uint16_t*>(&b);
    return (uint32_t)ua | ((uint32_t)ub << 16);
}

// ---------------------------------------------------------------------------
// fp16x2 GEMM: C = scale*(A[M,K] x B[N,K]^T) (+bias). CTA tile 128x64, Kc=32.
// A smem row (64B): 32 fp16 hi, XOR-((row>>1)&3)*16 swizzle.
// B smem row (128B): [hi 32 fp16 | lo 32 fp16], XOR-(row&7)*16 swizzle.
// 8 warps in 4(m) x 2(n) grid, warp tile 32x32.
// OUT: 0 = fp32 C, 1 = (hi,lo) fp16 pair, 2 = hi fp16 only.
// ---------------------------------------------------------------------------
#define BM 128
#define BN 64
#define NSTAGE 4
#define A_BYTES 8192                     // 128 rows x 64B
#define B_BYTES 8192                     // 64 rows x 128B
#define STAGE_BYTES (A_BYTES + B_BYTES)  // 16384
#define SMEM_TOTAL (NSTAGE * STAGE_BYTES)  // 65536

template <bool HAS_BIAS, int OUT>
__global__ __launch_bounds__(256, 2) void gemm_fp16x2(
    const h16* __restrict__ Ah,
    const h16* __restrict__ Bh, const h16* __restrict__ Bl,
    const float* __restrict__ bias,
    float* __restrict__ C, h16* __restrict__ Chi, h16* __restrict__ Clo,
    int K, int lda, int ldb, int ldc,
    long aBS, long bBS, long cBS, float scale)
{
    extern __shared__ char smem[];
    const uint32_t sb = smem_u32(smem);
    const int tid = threadIdx.x;
    const int lane = tid & 31;
    const int wid = tid >> 5;
    const int wm = wid & 3;       // m 32-quarter (0..3)
    const int wn = wid >> 2;      // n 32-half    (0..1)

    const long bm = (long)blockIdx.y * BM;
    const long bn = (long)blockIdx.x * BN;
    Ah += (long)blockIdx.z * aBS;
    Bh += (long)blockIdx.z * bBS;  Bl += (long)blockIdx.z * bBS;
    if (OUT == 0)      { C   += (long)blockIdx.z * cBS; }
    else               { Chi += (long)blockIdx.z * cBS;
                         if (OUT == 1) Clo += (long)blockIdx.z * cBS; }

    const int nchunk = K >> 5;

    // ---- cp.async assignments: A 2x16B/thread, B 2x16B/thread ----
    const h16* pA[2]; const h16* pB[2];
    uint32_t dA[2], dB[2];
#pragma unroll
    for (int i = 0; i < 2; i++) {
        int ch = tid + i * 256;          // 0..511
        int row = ch >> 2;               // 0..127
        int q = ch & 3;                  // 16B quarter in 64B row
        dA[i] = (uint32_t)(row * 64) + ((uint32_t)(q * 16) ^ (((row >> 1) & 3) * 16));
        pA[i] = Ah + (size_t)(bm + row) * lda + q * 8;
    }
#pragma unroll
    for (int i = 0; i < 2; i++) {
        int ch = tid + i * 256;          // 0..511
        int row = ch >> 3;               // 0..63
        int q = ch & 7;
        int half = q >> 2;               // 0=hi 1=lo
        int qq = q & 3;
        uint32_t col = half * 64 + qq * 16;
        uint32_t sw = col ^ ((row & 7) * 16);
        dB[i] = (uint32_t)(row * 128) + sw;
        pB[i] = (half ? Bl : Bh) + (size_t)(bn + row) * ldb + qq * 8;
    }

    // ---- ldmatrix lane address components ----
    const int rA = (lane & 7) + ((lane >> 3) & 1) * 8;
    const uint32_t cA16 = ((lane >> 4) & 1) * 16;
    const int rB = (lane & 7) + ((lane >> 4) & 1) * 8;
    const uint32_t cB16 = ((lane >> 3) & 1) * 16;

    uint32_t aoff[2], axor[2];
#pragma unroll
    for (int mt = 0; mt < 2; mt++) {
        int arow = wm * 32 + mt * 16 + rA;
        aoff[mt] = arow * 64;
        axor[mt] = ((arow >> 1) & 3) * 16;
    }
    uint32_t boff[2], bxor[2];
#pragma unroll
    for (int t = 0; t < 2; t++) {
        int brow = wn * 32 + t * 16 + rB;
        boff[t] = brow * 128;
        bxor[t] = (brow & 7) * 16;
    }

    float acc[2][4][4];
#pragma unroll
    for (int mt = 0; mt < 2; mt++)
#pragma unroll
        for (int nt = 0; nt < 4; nt++)
#pragma unroll
            for (int r = 0; r < 4; r++) acc[mt][nt][r] = 0.f;

    // ---- prologue: stages 0..NSTAGE-2 in flight ----
#pragma unroll
    for (int st = 0; st < NSTAGE - 1; st++) {
        int k0 = st * 32;
        uint32_t base = sb + st * STAGE_BYTES;
#pragma unroll
        for (int i = 0; i < 2; i++) cp16(base + dA[i], pA[i] + k0);
#pragma unroll
        for (int i = 0; i < 2; i++) cp16(base + A_BYTES + dB[i], pB[i] + k0);
        cp_commit();
    }
    cp_wait<NSTAGE - 2>();
    __syncthreads();

    // ---- main loop: ONE barrier per chunk ----
    for (int kc = 0; kc < nchunk; kc++) {
        const uint32_t baseA = sb + (kc % NSTAGE) * STAGE_BYTES;
        const uint32_t baseB = baseA + A_BYTES;

        // prefetch chunk kc+NSTAGE-1 into the stage consumed at kc-1
        int next = kc + NSTAGE - 1;
        if (next < nchunk) {
            int k0 = next * 32;
            uint32_t nb = sb + (next % NSTAGE) * STAGE_BYTES;
#pragma unroll
            for (int i = 0; i < 2; i++) cp16(nb + dA[i], pA[i] + k0);
#pragma unroll
            for (int i = 0; i < 2; i++) cp16(nb + A_BYTES + dB[i], pB[i] + k0);
        }
        cp_commit();

        // compute current chunk: 2 k16 steps, 16 MMAs + 6 LDSM each
#pragma unroll
        for (int s = 0; s < 2; s++) {
            uint32_t bh[8], bl[8];
#pragma unroll
            for (int t = 0; t < 2; t++) {
                uint32_t c = s * 32 + cB16;
                ldm4(&bh[t * 4], baseB + boff[t] + (c ^ bxor[t]));
                ldm4(&bl[t * 4], baseB + boff[t] + ((c + 64) ^ bxor[t]));
            }
#pragma unroll
            for (int mt = 0; mt < 2; mt++) {
                uint32_t a[4];
                uint32_t cc = s * 32 + cA16;
                ldm4(a, baseA + aoff[mt] + (cc ^ axor[mt]));
#pragma unroll
                for (int nt = 0; nt < 4; nt++) mma16816(acc[mt][nt], a, &bh[nt * 2]);
#pragma unroll
                for (int nt = 0; nt < 4; nt++) mma16816(acc[mt][nt], a, &bl[nt * 2]);
            }
        }

        cp_wait<NSTAGE - 2>();   // chunk kc+1 resident
        __syncthreads();
    }

    // ---- epilogue ----
#pragma unroll
    for (int mt = 0; mt < 2; mt++) {
        long r0 = bm + wm * 32 + mt * 16 + (lane >> 2);
        long r1 = r0 + 8;
#pragma unroll
        for (int nt = 0; nt < 4; nt++) {
            long col = bn + wn * 32 + nt * 8 + (lane & 3) * 2;
            float b0v = 0.f, b1v = 0.f;
            if (HAS_BIAS) { b0v = bias[col]; b1v = bias[col + 1]; }
            float v00 = acc[mt][nt][0] * scale + b0v;
            float v01 = acc[mt][nt][1] * scale + b1v;
            float v10 = acc[mt][nt][2] * scale + b0v;
            float v11 = acc[mt][nt][3] * scale + b1v;
            if (OUT == 1) {
                h16 h0, h1, l0, l1;
                split1(v00, h0, l0); split1(v01, h1, l1);
                *reinterpret_cast<uint32_t*>(&Chi[r0 * ldc + col]) = pack2(h0, h1);
                *reinterpret_cast<uint32_t*>(&Clo[r0 * ldc + col]) = pack2(l0, l1);
                split1(v10, h0, l0); split1(v11, h1, l1);
                *reinterpret_cast<uint32_t*>(&Chi[r1 * ldc + col]) = pack2(h0, h1);
                *reinterpret_cast<uint32_t*>(&Clo[r1 * ldc + col]) = pack2(l0, l1);
            } else if (OUT == 2) {
                *reinterpret_cast<uint32_t*>(&Chi[r0 * ldc + col]) =
                    pack2(__float2half(v00), __float2half(v01));
                *reinterpret_cast<uint32_t*>(&Chi[r1 * ldc + col]) =
                    pack2(__float2half(v10), __float2half(v11));
            } else {
                float2 u0 = make_float2(v00, v01);
                float2 u1 = make_float2(v10, v11);
                *reinterpret_cast<float2*>(&C[r0 * ldc + col]) = u0;
                *reinterpret_cast<float2*>(&C[r1 * ldc + col]) = u1;
            }
        }
    }
}

// ---------------------------------------------------------------------------
// fp32 -> fp16 split conversions (vectorized)
// ---------------------------------------------------------------------------
__global__ __launch_bounds__(256) void split_hl_kernel(
    const float* __restrict__ src, h16* __restrict__ hi, h16* __restrict__ lo, int n4)
{
    int i = blockIdx.x * blockDim.x + threadIdx.x;
    if (i >= n4) return;
    float4 v = reinterpret_cast<const float4*>(src)[i];
    h16 h0, h1, h2, h3, l0, l1, l2, l3;
    split1(v.x, h0, l0); split1(v.y, h1, l1);
    split1(v.z, h2, l2); split1(v.w, h3, l3);
    reinterpret_cast<uint2*>(hi)[i] = make_uint2(pack2(h0, h1), pack2(h2, h3));
    reinterpret_cast<uint2*>(lo)[i] = make_uint2(pack2(l0, l1), pack2(l2, l3));
}

__global__ __launch_bounds__(256) void split_h_kernel(
    const float* __restrict__ src, h16* __restrict__ hi, int n4)
{
    int i = blockIdx.x * blockDim.x + threadIdx.x;
    if (i >= n4) return;
    float4 v = reinterpret_cast<const float4*>(src)[i];
    reinterpret_cast<uint2*>(hi)[i] = make_uint2(
        pack2(__float2half(v.x), __float2half(v.y)),
        pack2(__float2half(v.z), __float2half(v.w)));
}

// ---------------------------------------------------------------------------
// V transpose (hi & lo): vt[b][e][s] = qkv[b*S+s][2E+e]
// ---------------------------------------------------------------------------
__global__ __launch_bounds__(256) void transpose_v_kernel(
    const h16* __restrict__ qh, const h16* __restrict__ ql,
    h16* __restrict__ vth, h16* __restrict__ vtl)
{
    __shared__ h16 th[32][33];
    __shared__ h16 tl[32][33];
    const int b = blockIdx.z;
    const int e0 = blockIdx.x * 32;
    const int s0 = blockIdx.y * 32;
    const int tx = threadIdx.x & 31;
    const int ty = threadIdx.x >> 5;  // 0..7
#pragma unroll
    for (int i = 0; i < 4; i++) {
        int s = s0 + ty + i * 8;
        size_t idx = (size_t)(b * SEQ + s) * (3 * EMBED) + 2 * EMBED + e0 + tx;
        th[ty + i * 8][tx] = qh[idx];
        tl[ty + i * 8][tx] = ql[idx];
    }
    __syncthreads();
#pragma unroll
    for (int i = 0; i < 4; i++) {
        int e = e0 + ty + i * 8;
        size_t o = (size_t)(b * EMBED + e) * SEQ + s0 + tx;
        vth[o] = th[tx][ty + i * 8];
        vtl[o] = tl[tx][ty + i * 8];
    }
}

// ---------------------------------------------------------------------------
// Row softmax with mask; writes fp16 hi probabilities (A-side of ctx GEMM).
// ---------------------------------------------------------------------------
__global__ __launch_bounds__(256) void softmax_kernel(
    const float* __restrict__ att, const int* __restrict__ mask,
    h16* __restrict__ phi)
{
    const size_t row = blockIdx.x;
    const float* a = att + row * SEQ;
    const int* m = mask + row * SEQ;
    const int tid = threadIdx.x;

    __shared__ float red_max[8];
    __shared__ float red_sum[8];

    float v[8];
    float mx = -INFINITY;
#pragma unroll
    for (int i = 0; i < 8; i++) {
        int idx = tid + i * 256;
        float x = a[idx];
        x = (m[idx] != 0) ? x : -INFINITY;
        v[i] = x;
        mx = fmaxf(mx, x);
    }
#pragma unroll
    for (int o = 16; o > 0; o >>= 1)
        mx = fmaxf(mx, __shfl_xor_sync(0xffffffffu, mx, o));
    if ((tid & 31) == 0) red_max[tid >> 5] = mx;
    __syncthreads();
    float bmax = red_max[0];
#pragma unroll
    for (int w = 1; w < 8; w++) bmax = fmaxf(bmax, red_max[w]);

    float s = 0.f;
#pragma unroll
    for (int i = 0; i < 8; i++) {
        v[i] = __expf(v[i] - bmax);
        s += v[i];
    }
#pragma unroll
    for (int o = 16; o > 0; o >>= 1)
        s += __shfl_xor_sync(0xffffffffu, s, o);
    if ((tid & 31) == 0) red_sum[tid >> 5] = s;
    __syncthreads();
    float total = 0.f;
#pragma unroll
    for (int w = 0; w < 8; w++) total += red_sum[w];

    float inv = 1.f / total;
#pragma unroll
    for (int i = 0; i < 8; i++) {
        int idx = tid + i * 256;
        phi[row * SEQ + idx] = __float2half(v[i] * inv);
    }
}

// ---------------------------------------------------------------------------
extern "C" void kernel_launch(void* const* d_in, const int* in_sizes, int n_in,
                              void* d_out, int out_size)
{
    const float* X    = (const float*)d_in[0];
    const int*   mask = (const int*)  d_in[1];
    const float* Wqkv = (const float*)d_in[2];
    const float* bqkv = (const float*)d_in[3];
    const float* Wout = (const float*)d_in[4];
    const float* bout = (const float*)d_in[5];
    float* out = (float*)d_out;

    h16 *Xhi, *Wqkvhi, *Wqkvlo, *Wouthi, *Woutlo;
    h16 *qkvhi, *qkvlo, *atthi, *vthi, *vtlo, *ctxhi;
    float* att;
    cudaGetSymbolAddress((void**)&Xhi, g_Xhi);
    cudaGetSymbolAddress((void**)&Wqkvhi, g_Wqkvhi);
    cudaGetSymbolAddress((void**)&Wqkvlo, g_Wqkvlo);
    cudaGetSymbolAddress((void**)&Wouthi, g_Wouthi);
    cudaGetSymbolAddress((void**)&Woutlo, g_Woutlo);
    cudaGetSymbolAddress((void**)&qkvhi, g_qkvhi);
    cudaGetSymbolAddress((void**)&qkvlo, g_qkvlo);
    cudaGetSymbolAddress((void**)&att, g_att);
    cudaGetSymbolAddress((void**)&atthi, g_atthi);
    cudaGetSymbolAddress((void**)&vthi, g_vthi);
    cudaGetSymbolAddress((void**)&vtlo, g_vtlo);
    cudaGetSymbolAddress((void**)&ctxhi, g_ctxhi);

    cudaFuncSetAttribute(gemm_fp16x2<true, 1>,
                         cudaFuncAttributeMaxDynamicSharedMemorySize, SMEM_TOTAL);
    cudaFuncSetAttribute(gemm_fp16x2<false, 0>,
                         cudaFuncAttributeMaxDynamicSharedMemorySize, SMEM_TOTAL);
    cudaFuncSetAttribute(gemm_fp16x2<false, 2>,
                         cudaFuncAttributeMaxDynamicSharedMemorySize, SMEM_TOTAL);
    cudaFuncSetAttribute(gemm_fp16x2<true, 0>,
                         cudaFuncAttributeMaxDynamicSharedMemorySize, SMEM_TOTAL);

    // 0) split inputs to fp16
    split_h_kernel<<<(ROWS * EMBED / 4 + 255) / 256, 256>>>(X, Xhi, ROWS * EMBED / 4);
    split_hl_kernel<<<(3 * EMBED * EMBED / 4 + 255) / 256, 256>>>(
        Wqkv, Wqkvhi, Wqkvlo, 3 * EMBED * EMBED / 4);
    split_hl_kernel<<<(EMBED * EMBED / 4 + 255) / 256, 256>>>(
        Wout, Wouthi, Woutlo, EMBED * EMBED / 4);

    // 1) qkv = X Wqkv^T + bqkv  (hi,lo output)
    {
        dim3 grid(3 * EMBED / BN, ROWS / BM, 1);
        gemm_fp16x2<true, 1><<<grid, 256, SMEM_TOTAL>>>(
            Xhi, Wqkvhi, Wqkvlo, bqkv,
            nullptr, qkvhi, qkvlo,
            EMBED, EMBED, EMBED, 3 * EMBED,
            0, 0, 0, 1.0f);
    }
    // 2) vt = V^T (hi,lo)
    {
        dim3 grid(EMBED / 32, SEQ / 32, BATCH);
        transpose_v_kernel<<<grid, 256>>>(qkvhi, qkvlo, vthi, vtlo);
    }
    // 3) att = Q K^T / 32  (fp32 output); A = Q (hi), B = K (hi,lo)
    {
        dim3 grid(SEQ / BN, SEQ / BM, BATCH);
        gemm_fp16x2<false, 0><<<grid, 256, SMEM_TOTAL>>>(
            qkvhi, qkvhi + EMBED, qkvlo + EMBED, nullptr,
            att, nullptr, nullptr,
            EMBED, 3 * EMBED, 3 * EMBED, SEQ,
            (long)SEQ * 3 * EMBED, (long)SEQ * 3 * EMBED, (long)SEQ * SEQ,
            1.0f / 32.0f);
    }
    // 4) softmax -> p (hi only)
    softmax_kernel<<<BATCH * SEQ, 256>>>(att, mask, atthi);

    // 5) ctx = p vt^T  (hi-only output); A = p (hi), B = V^T (hi,lo)
    {
        dim3 grid(EMBED / BN, SEQ / BM, BATCH);
        gemm_fp16x2<false, 2><<<grid, 256, SMEM_TOTAL>>>(
            atthi, vthi, vtlo, nullptr,
            nullptr, ctxhi, nullptr,
            SEQ, SEQ, SEQ, EMBED,
            (long)SEQ * SEQ, (long)EMBED * SEQ, (long)SEQ * EMBED,
            1.0f);
    }
    // 6) out = ctx Wout^T + bout  (fp32); A = ctx (hi), B = Wout (hi,lo)
    {
        dim3 grid(EMBED / BN, ROWS / BM, 1);
        gemm_fp16x2<true, 0><<<grid, 256, SMEM_TOTAL>>>(
            ctxhi, Wouthi, Woutlo, bout,
            out, nullptr, nullptr,
            EMBED, EMBED, EMBED, EMBED,
            0, 0, 0, 1.0f);
    }
}

// round 10
// speedup vs baseline: 3.1464x; 1.2569x over previous
#include <cuda_runtime.h>
#include <cuda_fp16.h>
#include <cstdint>
#include <math.h>

// ---------------------------------------------------------------------------
// SelfAttentionV3 (B=4, S=2048, E=1024) via fp16 split-precision HMMA GEMMs.
// Weight GEMMs (1,6): C ~= Ahi*(Bhi+Blo)  (2-pass, fp16 hi/lo split).
// Attention GEMMs (3,5): C ~= Ahi*Bhi      (1-pass; error budget analysis
//   shows K-lo/V-lo contribute only ~3e-4 each; total ~6.5e-4 < 1e-3).
// R10: R9 with the launch-config bug fixed (cudaFuncSetAttribute applied to
// the EXACT template instantiations launched).
// ---------------------------------------------------------------------------

#define EMBED 1024
#define BATCH 4
#define SEQ   2048
#define ROWS  (BATCH * SEQ)   // 8192

typedef __half h16;

// ---------------- static scratch (no allocs allowed) -----------------------
__device__ h16 g_Xhi[(size_t)ROWS * EMBED];
__device__ h16 g_Wqkvhi[(size_t)3 * EMBED * EMBED];
__device__ h16 g_Wqkvlo[(size_t)3 * EMBED * EMBED];
__device__ h16 g_Wouthi[(size_t)EMBED * EMBED];
__device__ h16 g_Woutlo[(size_t)EMBED * EMBED];
__device__ h16 g_qkvhi[(size_t)ROWS * 3 * EMBED];
__device__ float g_att[(size_t)BATCH * SEQ * SEQ];
__device__ h16 g_atthi[(size_t)BATCH * SEQ * SEQ];
__device__ h16 g_vthi[(size_t)BATCH * EMBED * SEQ];
__device__ h16 g_ctxhi[(size_t)ROWS * EMBED];

// ---------------- PTX helpers ----------------------------------------------
__device__ __forceinline__ uint32_t smem_u32(const void* p) {
    uint32_t a;
    asm("{ .reg .u64 t; cvta.to.shared.u64 t, %1; cvt.u32.u64 %0, t; }"
        : "=r"(a) : "l"(p));
    return a;
}
__device__ __forceinline__ void cp16(uint32_t dst, const void* src) {
    asm volatile("cp.async.cg.shared.global [%0], [%1], 16;"
                 :: "r"(dst), "l"(src) : "memory");
}
__device__ __forceinline__ void cp_commit() {
    asm volatile("cp.async.commit_group;" ::: "memory");
}
template <int N>
__device__ __forceinline__ void cp_wait() {
    asm volatile("cp.async.wait_group %0;" :: "n"(N) : "memory");
}
__device__ __forceinline__ void ldm4(uint32_t* r, uint32_t addr) {
    asm volatile("ldmatrix.sync.aligned.m8n8.x4.shared.b16 {%0,%1,%2,%3}, [%4];"
                 : "=r"(r[0]), "=r"(r[1]), "=r"(r[2]), "=r"(r[3]) : "r"(addr));
}
__device__ __forceinline__ void mma16816(float* c, const uint32_t* a, const uint32_t* b) {
    asm volatile("mma.sync.aligned.m16n8k16.row.col.f32.f16.f16.f32 "
                 "{%0,%1,%2,%3}, {%4,%5,%6,%7}, {%8,%9}, {%0,%1,%2,%3};"
                 : "+f"(c[0]), "+f"(c[1]), "+f"(c[2]), "+f"(c[3])
                 : "r"(a[0]), "r"(a[1]), "r"(a[2]), "r"(a[3]), "r"(b[0]), "r"(b[1]));
}
__device__ __forceinline__ void split1(float x, h16& h, h16& l) {
    h = __float2half(x);
    l = __float2half(x - __half2float(h));
}
__device__ __forceinline__ uint32_t pack2(h16 a, h16 b) {
    uint16_t ua = *reinterpret_cast<uint16_t*>(&a);
    uint16_t ub = *reinterpret_cast<uint16_t*>(&b);
    return (uint32_t)ua | ((uint32_t)ub << 16);
}

// ---------------------------------------------------------------------------
// fp16 GEMM: C = scale*(A[M,K] x B[N,K]^T) (+bias). CTA tile 128x64, Kc=32.
// A smem row (64B): 32 fp16 hi, XOR-((row>>1)&3)*16 swizzle.
// B smem row: BLO ? 128B [hi|lo] with (row&7) swizzle : 64B hi-only like A.
// 8 warps in 4(m) x 2(n) grid, warp tile 32x32.
// OUT: 0 = fp32 C, 1 = (hi,lo) fp16 pair, 2 = hi fp16 only.
// ---------------------------------------------------------------------------
#define BM 128
#define BN 64
#define NSTAGE 4
#define A_BYTES 8192                     // 128 rows x 64B

template <bool HAS_BIAS, int OUT, bool BLO>
__global__ __launch_bounds__(256, 2) void gemm_fp16(
    const h16* __restrict__ Ah,
    const h16* __restrict__ Bh, const h16* __restrict__ Bl,
    const float* __restrict__ bias,
    float* __restrict__ C, h16* __restrict__ Chi, h16* __restrict__ Clo,
    int K, int lda, int ldb, int ldc,
    long aBS, long bBS, long cBS, float scale)
{
    constexpr int B_BYTES = BLO ? 8192 : 4096;
    constexpr int STAGE_BYTES = A_BYTES + B_BYTES;

    extern __shared__ char smem[];
    const uint32_t sb = smem_u32(smem);
    const int tid = threadIdx.x;
    const int lane = tid & 31;
    const int wid = tid >> 5;
    const int wm = wid & 3;       // m 32-quarter (0..3)
    const int wn = wid >> 2;      // n 32-half    (0..1)

    const long bm = (long)blockIdx.y * BM;
    const long bn = (long)blockIdx.x * BN;
    Ah += (long)blockIdx.z * aBS;
    Bh += (long)blockIdx.z * bBS;
    if (BLO) Bl += (long)blockIdx.z * bBS;
    if (OUT == 0)      { C   += (long)blockIdx.z * cBS; }
    else               { Chi += (long)blockIdx.z * cBS;
                         if (OUT == 1) Clo += (long)blockIdx.z * cBS; }

    const int nchunk = K >> 5;

    // ---- cp.async assignments ----
    const h16* pA[2];
    uint32_t dA[2];
#pragma unroll
    for (int i = 0; i < 2; i++) {
        int ch = tid + i * 256;          // 0..511
        int row = ch >> 2;               // 0..127
        int q = ch & 3;                  // 16B quarter in 64B row
        dA[i] = (uint32_t)(row * 64) + ((uint32_t)(q * 16) ^ (((row >> 1) & 3) * 16));
        pA[i] = Ah + (size_t)(bm + row) * lda + q * 8;
    }
    const h16* pB[2];
    uint32_t dB[2];
    if (BLO) {
#pragma unroll
        for (int i = 0; i < 2; i++) {
            int ch = tid + i * 256;      // 0..511
            int row = ch >> 3;           // 0..63
            int q = ch & 7;
            int half = q >> 2;           // 0=hi 1=lo
            int qq = q & 3;
            uint32_t col = half * 64 + qq * 16;
            uint32_t sw = col ^ ((row & 7) * 16);
            dB[i] = (uint32_t)(row * 128) + sw;
            pB[i] = (half ? Bl : Bh) + (size_t)(bn + row) * ldb + qq * 8;
        }
    } else {
        int ch = tid;                    // 0..255
        int row = ch >> 2;               // 0..63
        int q = ch & 3;
        dB[0] = (uint32_t)(row * 64) + ((uint32_t)(q * 16) ^ (((row >> 1) & 3) * 16));
        pB[0] = Bh + (size_t)(bn + row) * ldb + q * 8;
        dB[1] = dB[0]; pB[1] = pB[0];    // unused
    }

    // ---- ldmatrix lane address components ----
    const int rA = (lane & 7) + ((lane >> 3) & 1) * 8;
    const uint32_t cA16 = ((lane >> 4) & 1) * 16;
    const int rB = (lane & 7) + ((lane >> 4) & 1) * 8;
    const uint32_t cB16 = ((lane >> 3) & 1) * 16;

    uint32_t aoff[2], axor[2];
#pragma unroll
    for (int mt = 0; mt < 2; mt++) {
        int arow = wm * 32 + mt * 16 + rA;
        aoff[mt] = arow * 64;
        axor[mt] = ((arow >> 1) & 3) * 16;
    }
    uint32_t boff[2], bxor[2];
#pragma unroll
    for (int t = 0; t < 2; t++) {
        int brow = wn * 32 + t * 16 + rB;
        if (BLO) {
            boff[t] = brow * 128;
            bxor[t] = (brow & 7) * 16;
        } else {
            boff[t] = brow * 64;
            bxor[t] = ((brow >> 1) & 3) * 16;
        }
    }

    float acc[2][4][4];
#pragma unroll
    for (int mt = 0; mt < 2; mt++)
#pragma unroll
        for (int nt = 0; nt < 4; nt++)
#pragma unroll
            for (int r = 0; r < 4; r++) acc[mt][nt][r] = 0.f;

    // ---- prologue: stages 0..NSTAGE-2 in flight ----
#pragma unroll
    for (int st = 0; st < NSTAGE - 1; st++) {
        int k0 = st * 32;
        uint32_t base = sb + st * STAGE_BYTES;
#pragma unroll
        for (int i = 0; i < 2; i++) cp16(base + dA[i], pA[i] + k0);
#pragma unroll
        for (int i = 0; i < (BLO ? 2 : 1); i++)
            cp16(base + A_BYTES + dB[i], pB[i] + k0);
        cp_commit();
    }
    cp_wait<NSTAGE - 2>();
    __syncthreads();

    // ---- main loop: ONE barrier per chunk ----
    for (int kc = 0; kc < nchunk; kc++) {
        const uint32_t baseA = sb + (kc % NSTAGE) * STAGE_BYTES;
        const uint32_t baseB = baseA + A_BYTES;

        // prefetch chunk kc+NSTAGE-1 into the stage consumed at kc-1
        int next = kc + NSTAGE - 1;
        if (next < nchunk) {
            int k0 = next * 32;
            uint32_t nb = sb + (next % NSTAGE) * STAGE_BYTES;
#pragma unroll
            for (int i = 0; i < 2; i++) cp16(nb + dA[i], pA[i] + k0);
#pragma unroll
            for (int i = 0; i < (BLO ? 2 : 1); i++)
                cp16(nb + A_BYTES + dB[i], pB[i] + k0);
        }
        cp_commit();

        // compute current chunk: 2 k16 steps
#pragma unroll
        for (int s = 0; s < 2; s++) {
            uint32_t bh[8], bl[8];
#pragma unroll
            for (int t = 0; t < 2; t++) {
                uint32_t c = s * 32 + cB16;
                ldm4(&bh[t * 4], baseB + boff[t] + (c ^ bxor[t]));
                if (BLO)
                    ldm4(&bl[t * 4], baseB + boff[t] + ((c + 64) ^ bxor[t]));
            }
#pragma unroll
            for (int mt = 0; mt < 2; mt++) {
                uint32_t a[4];
                uint32_t cc = s * 32 + cA16;
                ldm4(a, baseA + aoff[mt] + (cc ^ axor[mt]));
#pragma unroll
                for (int nt = 0; nt < 4; nt++) mma16816(acc[mt][nt], a, &bh[nt * 2]);
                if (BLO) {
#pragma unroll
                    for (int nt = 0; nt < 4; nt++) mma16816(acc[mt][nt], a, &bl[nt * 2]);
                }
            }
        }

        cp_wait<NSTAGE - 2>();   // chunk kc+1 resident
        __syncthreads();
    }

    // ---- epilogue ----
#pragma unroll
    for (int mt = 0; mt < 2; mt++) {
        long r0 = bm + wm * 32 + mt * 16 + (lane >> 2);
        long r1 = r0 + 8;
#pragma unroll
        for (int nt = 0; nt < 4; nt++) {
            long col = bn + wn * 32 + nt * 8 + (lane & 3) * 2;
            float b0v = 0.f, b1v = 0.f;
            if (HAS_BIAS) { b0v = bias[col]; b1v = bias[col + 1]; }
            float v00 = acc[mt][nt][0] * scale + b0v;
            float v01 = acc[mt][nt][1] * scale + b1v;
            float v10 = acc[mt][nt][2] * scale + b0v;
            float v11 = acc[mt][nt][3] * scale + b1v;
            if (OUT == 1) {
                h16 h0, h1, l0, l1;
                split1(v00, h0, l0); split1(v01, h1, l1);
                *reinterpret_cast<uint32_t*>(&Chi[r0 * ldc + col]) = pack2(h0, h1);
                *reinterpret_cast<uint32_t*>(&Clo[r0 * ldc + col]) = pack2(l0, l1);
                split1(v10, h0, l0); split1(v11, h1, l1);
                *reinterpret_cast<uint32_t*>(&Chi[r1 * ldc + col]) = pack2(h0, h1);
                *reinterpret_cast<uint32_t*>(&Clo[r1 * ldc + col]) = pack2(l0, l1);
            } else if (OUT == 2) {
                *reinterpret_cast<uint32_t*>(&Chi[r0 * ldc + col]) =
                    pack2(__float2half(v00), __float2half(v01));
                *reinterpret_cast<uint32_t*>(&Chi[r1 * ldc + col]) =
                    pack2(__float2half(v10), __float2half(v11));
            } else {
                float2 u0 = make_float2(v00, v01);
                float2 u1 = make_float2(v10, v11);
                *reinterpret_cast<float2*>(&C[r0 * ldc + col]) = u0;
                *reinterpret_cast<float2*>(&C[r1 * ldc + col]) = u1;
            }
        }
    }
}

// ---------------------------------------------------------------------------
// fp32 -> fp16 split conversions (vectorized)
// ---------------------------------------------------------------------------
__global__ __launch_bounds__(256) void split_hl_kernel(
    const float* __restrict__ src, h16* __restrict__ hi, h16* __restrict__ lo, int n4)
{
    int i = blockIdx.x * blockDim.x + threadIdx.x;
    if (i >= n4) return;
    float4 v = reinterpret_cast<const float4*>(src)[i];
    h16 h0, h1, h2, h3, l0, l1, l2, l3;
    split1(v.x, h0, l0); split1(v.y, h1, l1);
    split1(v.z, h2, l2); split1(v.w, h3, l3);
    reinterpret_cast<uint2*>(hi)[i] = make_uint2(pack2(h0, h1), pack2(h2, h3));
    reinterpret_cast<uint2*>(lo)[i] = make_uint2(pack2(l0, l1), pack2(l2, l3));
}

__global__ __launch_bounds__(256) void split_h_kernel(
    const float* __restrict__ src, h16* __restrict__ hi, int n4)
{
    int i = blockIdx.x * blockDim.x + threadIdx.x;
    if (i >= n4) return;
    float4 v = reinterpret_cast<const float4*>(src)[i];
    reinterpret_cast<uint2*>(hi)[i] = make_uint2(
        pack2(__float2half(v.x), __float2half(v.y)),
        pack2(__float2half(v.z), __float2half(v.w)));
}

// ---------------------------------------------------------------------------
// V transpose (hi only): vt[b][e][s] = qkv[b*S+s][2E+e]
// ---------------------------------------------------------------------------
__global__ __launch_bounds__(256) void transpose_v_kernel(
    const h16* __restrict__ qh, h16* __restrict__ vth)
{
    __shared__ h16 th[32][33];
    const int b = blockIdx.z;
    const int e0 = blockIdx.x * 32;
    const int s0 = blockIdx.y * 32;
    const int tx = threadIdx.x & 31;
    const int ty = threadIdx.x >> 5;  // 0..7
#pragma unroll
    for (int i = 0; i < 4; i++) {
        int s = s0 + ty + i * 8;
        size_t idx = (size_t)(b * SEQ + s) * (3 * EMBED) + 2 * EMBED + e0 + tx;
        th[ty + i * 8][tx] = qh[idx];
    }
    __syncthreads();
#pragma unroll
    for (int i = 0; i < 4; i++) {
        int e = e0 + ty + i * 8;
        size_t o = (size_t)(b * EMBED + e) * SEQ + s0 + tx;
        vth[o] = th[tx][ty + i * 8];
    }
}

// ---------------------------------------------------------------------------
// Row softmax with mask; writes fp16 hi probabilities (A-side of ctx GEMM).
// ---------------------------------------------------------------------------
__global__ __launch_bounds__(256) void softmax_kernel(
    const float* __restrict__ att, const int* __restrict__ mask,
    h16* __restrict__ phi)
{
    const size_t row = blockIdx.x;
    const float* a = att + row * SEQ;
    const int* m = mask + row * SEQ;
    const int tid = threadIdx.x;

    __shared__ float red_max[8];
    __shared__ float red_sum[8];

    float v[8];
    float mx = -INFINITY;
#pragma unroll
    for (int i = 0; i < 8; i++) {
        int idx = tid + i * 256;
        float x = a[idx];
        x = (m[idx] != 0) ? x : -INFINITY;
        v[i] = x;
        mx = fmaxf(mx, x);
    }
#pragma unroll
    for (int o = 16; o > 0; o >>= 1)
        mx = fmaxf(mx, __shfl_xor_sync(0xffffffffu, mx, o));
    if ((tid & 31) == 0) red_max[tid >> 5] = mx;
    __syncthreads();
    float bmax = red_max[0];
#pragma unroll
    for (int w = 1; w < 8; w++) bmax = fmaxf(bmax, red_max[w]);

    float s = 0.f;
#pragma unroll
    for (int i = 0; i < 8; i++) {
        v[i] = __expf(v[i] - bmax);
        s += v[i];
    }
#pragma unroll
    for (int o = 16; o > 0; o >>= 1)
        s += __shfl_xor_sync(0xffffffffu, s, o);
    if ((tid & 31) == 0) red_sum[tid >> 5] = s;
    __syncthreads();
    float total = 0.f;
#pragma unroll
    for (int w = 0; w < 8; w++) total += red_sum[w];

    float inv = 1.f / total;
#pragma unroll
    for (int i = 0; i < 8; i++) {
        int idx = tid + i * 256;
        phi[row * SEQ + idx] = __float2half(v[i] * inv);
    }
}

// ---------------------------------------------------------------------------
extern "C" void kernel_launch(void* const* d_in, const int* in_sizes, int n_in,
                              void* d_out, int out_size)
{
    const float* X    = (const float*)d_in[0];
    const int*   mask = (const int*)  d_in[1];
    const float* Wqkv = (const float*)d_in[2];
    const float* bqkv = (const float*)d_in[3];
    const float* Wout = (const float*)d_in[4];
    const float* bout = (const float*)d_in[5];
    float* out = (float*)d_out;

    h16 *Xhi, *Wqkvhi, *Wqkvlo, *Wouthi, *Woutlo;
    h16 *qkvhi, *atthi, *vthi, *ctxhi;
    float* att;
    cudaGetSymbolAddress((void**)&Xhi, g_Xhi);
    cudaGetSymbolAddress((void**)&Wqkvhi, g_Wqkvhi);
    cudaGetSymbolAddress((void**)&Wqkvlo, g_Wqkvlo);
    cudaGetSymbolAddress((void**)&Wouthi, g_Wouthi);
    cudaGetSymbolAddress((void**)&Woutlo, g_Woutlo);
    cudaGetSymbolAddress((void**)&qkvhi, g_qkvhi);
    cudaGetSymbolAddress((void**)&att, g_att);
    cudaGetSymbolAddress((void**)&atthi, g_atthi);
    cudaGetSymbolAddress((void**)&vthi, g_vthi);
    cudaGetSymbolAddress((void**)&ctxhi, g_ctxhi);

    constexpr int SM_HL = NSTAGE * (A_BYTES + 8192);  // 65536 (BLO=true)
    constexpr int SM_H  = NSTAGE * (A_BYTES + 4096);  // 49152 (BLO=false)

    // NOTE: attributes must be set on the EXACT instantiations launched below.
    cudaFuncSetAttribute(gemm_fp16<true, 2, true>,
                         cudaFuncAttributeMaxDynamicSharedMemorySize, SM_HL);
    cudaFuncSetAttribute(gemm_fp16<false, 0, false>,
                         cudaFuncAttributeMaxDynamicSharedMemorySize, SM_H);
    cudaFuncSetAttribute(gemm_fp16<false, 2, false>,
                         cudaFuncAttributeMaxDynamicSharedMemorySize, SM_H);
    cudaFuncSetAttribute(gemm_fp16<true, 0, true>,
                         cudaFuncAttributeMaxDynamicSharedMemorySize, SM_HL);

    // 0) split inputs to fp16
    split_h_kernel<<<(ROWS * EMBED / 4 + 255) / 256, 256>>>(X, Xhi, ROWS * EMBED / 4);
    split_hl_kernel<<<(3 * EMBED * EMBED / 4 + 255) / 256, 256>>>(
        Wqkv, Wqkvhi, Wqkvlo, 3 * EMBED * EMBED / 4);
    split_hl_kernel<<<(EMBED * EMBED / 4 + 255) / 256, 256>>>(
        Wout, Wouthi, Woutlo, EMBED * EMBED / 4);

    // 1) qkv = X Wqkv^T + bqkv  (hi,lo weights; hi-only output)
    {
        dim3 grid(3 * EMBED / BN, ROWS / BM, 1);
        gemm_fp16<true, 2, true><<<grid, 256, SM_HL>>>(
            Xhi, Wqkvhi, Wqkvlo, bqkv,
            nullptr, qkvhi, nullptr,
            EMBED, EMBED, EMBED, 3 * EMBED,
            0, 0, 0, 1.0f);
    }
    // 2) vt = V^T (hi)
    {
        dim3 grid(EMBED / 32, SEQ / 32, BATCH);
        transpose_v_kernel<<<grid, 256>>>(qkvhi, vthi);
    }
    // 3) att = Q K^T / 32  (fp32 output); single-pass hi x hi
    {
        dim3 grid(SEQ / BN, SEQ / BM, BATCH);
        gemm_fp16<false, 0, false><<<grid, 256, SM_H>>>(
            qkvhi, qkvhi + EMBED, nullptr, nullptr,
            att, nullptr, nullptr,
            EMBED, 3 * EMBED, 3 * EMBED, SEQ,
            (long)SEQ * 3 * EMBED, (long)SEQ * 3 * EMBED, (long)SEQ * SEQ,
            1.0f / 32.0f);
    }
    // 4) softmax -> p (hi only)
    softmax_kernel<<<BATCH * SEQ, 256>>>(att, mask, atthi);

    // 5) ctx = p vt^T  (hi-only output); single-pass hi x hi
    {
        dim3 grid(EMBED / BN, SEQ / BM, BATCH);
        gemm_fp16<false, 2, false><<<grid, 256, SM_H>>>(
            atthi, vthi, nullptr, nullptr,
            nullptr, ctxhi, nullptr,
            SEQ, SEQ, SEQ, EMBED,
            (long)SEQ * SEQ, (long)EMBED * SEQ, (long)SEQ * EMBED,
            1.0f);
    }
    // 6) out = ctx Wout^T + bout  (fp32); 2-pass weights
    {
        dim3 grid(EMBED / BN, ROWS / BM, 1);
        gemm_fp16<true, 0, true><<<grid, 256, SM_HL>>>(
            ctxhi, Wouthi, Woutlo, bout,
            out, nullptr, nullptr,
            EMBED, EMBED, EMBED, EMBED,
            0, 0, 0, 1.0f);
    }
}

// round 11
// speedup vs baseline: 3.7596x; 1.1949x over previous
#include <cuda_runtime.h>
#include <cuda_fp16.h>
#include <cstdint>
#include <math.h>

// ---------------------------------------------------------------------------
// SelfAttentionV3 (B=4, S=2048, E=1024) via fp16 split-precision HMMA GEMMs.
// GEMMs 1,3,5: single-pass hi x hi fp16 (error budget: each contributes
//   ~2.8e-4, q/k attenuated by softmax; measured trajectory 4.5e-4 -> 5.0e-4).
// GEMM 6 (output): 2-pass Ahi*(Bhi+Blo) -- its error hits out unattenuated.
// R11: R10 + drop Wqkv-lo pass (GEMM1 was 255us carrying half the MMA work).
// ---------------------------------------------------------------------------

#define EMBED 1024
#define BATCH 4
#define SEQ   2048
#define ROWS  (BATCH * SEQ)   // 8192

typedef __half h16;

// ---------------- static scratch (no allocs allowed) -----------------------
__device__ h16 g_Xhi[(size_t)ROWS * EMBED];
__device__ h16 g_Wqkvhi[(size_t)3 * EMBED * EMBED];
__device__ h16 g_Wouthi[(size_t)EMBED * EMBED];
__device__ h16 g_Woutlo[(size_t)EMBED * EMBED];
__device__ h16 g_qkvhi[(size_t)ROWS * 3 * EMBED];
__device__ float g_att[(size_t)BATCH * SEQ * SEQ];
__device__ h16 g_atthi[(size_t)BATCH * SEQ * SEQ];
__device__ h16 g_vthi[(size_t)BATCH * EMBED * SEQ];
__device__ h16 g_ctxhi[(size_t)ROWS * EMBED];

// ---------------- PTX helpers ----------------------------------------------
__device__ __forceinline__ uint32_t smem_u32(const void* p) {
    uint32_t a;
    asm("{ .reg .u64 t; cvta.to.shared.u64 t, %1; cvt.u32.u64 %0, t; }"
        : "=r"(a) : "l"(p));
    return a;
}
__device__ __forceinline__ void cp16(uint32_t dst, const void* src) {
    asm volatile("cp.async.cg.shared.global [%0], [%1], 16;"
                 :: "r"(dst), "l"(src) : "memory");
}
__device__ __forceinline__ void cp_commit() {
    asm volatile("cp.async.commit_group;" ::: "memory");
}
template <int N>
__device__ __forceinline__ void cp_wait() {
    asm volatile("cp.async.wait_group %0;" :: "n"(N) : "memory");
}
__device__ __forceinline__ void ldm4(uint32_t* r, uint32_t addr) {
    asm volatile("ldmatrix.sync.aligned.m8n8.x4.shared.b16 {%0,%1,%2,%3}, [%4];"
                 : "=r"(r[0]), "=r"(r[1]), "=r"(r[2]), "=r"(r[3]) : "r"(addr));
}
__device__ __forceinline__ void mma16816(float* c, const uint32_t* a, const uint32_t* b) {
    asm volatile("mma.sync.aligned.m16n8k16.row.col.f32.f16.f16.f32 "
                 "{%0,%1,%2,%3}, {%4,%5,%6,%7}, {%8,%9}, {%0,%1,%2,%3};"
                 : "+f"(c[0]), "+f"(c[1]), "+f"(c[2]), "+f"(c[3])
                 : "r"(a[0]), "r"(a[1]), "r"(a[2]), "r"(a[3]), "r"(b[0]), "r"(b[1]));
}
__device__ __forceinline__ void split1(float x, h16& h, h16& l) {
    h = __float2half(x);
    l = __float2half(x - __half2float(h));
}
__device__ __forceinline__ uint32_t pack2(h16 a, h16 b) {
    uint16_t ua = *reinterpret_cast<uint16_t*>(&a);
    uint16_t ub = *reinterpret_cast<uint16_t*>(&b);
    return (uint32_t)ua | ((uint32_t)ub << 16);
}

// ---------------------------------------------------------------------------
// fp16 GEMM: C = scale*(A[M,K] x B[N,K]^T) (+bias). CTA tile 128x64, Kc=32.
// A smem row (64B): 32 fp16 hi, XOR-((row>>1)&3)*16 swizzle.
// B smem row: BLO ? 128B [hi|lo] with (row&7) swizzle : 64B hi-only like A.
// 8 warps in 4(m) x 2(n) grid, warp tile 32x32.
// OUT: 0 = fp32 C, 2 = hi fp16 only.
// ---------------------------------------------------------------------------
#define BM 128
#define BN 64
#define NSTAGE 4
#define A_BYTES 8192                     // 128 rows x 64B

template <bool HAS_BIAS, int OUT, bool BLO>
__global__ __launch_bounds__(256, 2) void gemm_fp16(
    const h16* __restrict__ Ah,
    const h16* __restrict__ Bh, const h16* __restrict__ Bl,
    const float* __restrict__ bias,
    float* __restrict__ C, h16* __restrict__ Chi,
    int K, int lda, int ldb, int ldc,
    long aBS, long bBS, long cBS, float scale)
{
    constexpr int B_BYTES = BLO ? 8192 : 4096;
    constexpr int STAGE_BYTES = A_BYTES + B_BYTES;

    extern __shared__ char smem[];
    const uint32_t sb = smem_u32(smem);
    const int tid = threadIdx.x;
    const int lane = tid & 31;
    const int wid = tid >> 5;
    const int wm = wid & 3;       // m 32-quarter (0..3)
    const int wn = wid >> 2;      // n 32-half    (0..1)

    const long bm = (long)blockIdx.y * BM;
    const long bn = (long)blockIdx.x * BN;
    Ah += (long)blockIdx.z * aBS;
    Bh += (long)blockIdx.z * bBS;
    if (BLO) Bl += (long)blockIdx.z * bBS;
    if (OUT == 0) C   += (long)blockIdx.z * cBS;
    else          Chi += (long)blockIdx.z * cBS;

    const int nchunk = K >> 5;

    // ---- cp.async assignments ----
    const h16* pA[2];
    uint32_t dA[2];
#pragma unroll
    for (int i = 0; i < 2; i++) {
        int ch = tid + i * 256;          // 0..511
        int row = ch >> 2;               // 0..127
        int q = ch & 3;                  // 16B quarter in 64B row
        dA[i] = (uint32_t)(row * 64) + ((uint32_t)(q * 16) ^ (((row >> 1) & 3) * 16));
        pA[i] = Ah + (size_t)(bm + row) * lda + q * 8;
    }
    const h16* pB[2];
    uint32_t dB[2];
    if (BLO) {
#pragma unroll
        for (int i = 0; i < 2; i++) {
            int ch = tid + i * 256;      // 0..511
            int row = ch >> 3;           // 0..63
            int q = ch & 7;
            int half = q >> 2;           // 0=hi 1=lo
            int qq = q & 3;
            uint32_t col = half * 64 + qq * 16;
            uint32_t sw = col ^ ((row & 7) * 16);
            dB[i] = (uint32_t)(row * 128) + sw;
            pB[i] = (half ? Bl : Bh) + (size_t)(bn + row) * ldb + qq * 8;
        }
    } else {
        int ch = tid;                    // 0..255
        int row = ch >> 2;               // 0..63
        int q = ch & 3;
        dB[0] = (uint32_t)(row * 64) + ((uint32_t)(q * 16) ^ (((row >> 1) & 3) * 16));
        pB[0] = Bh + (size_t)(bn + row) * ldb + q * 8;
        dB[1] = dB[0]; pB[1] = pB[0];    // unused
    }

    // ---- ldmatrix lane address components ----
    const int rA = (lane & 7) + ((lane >> 3) & 1) * 8;
    const uint32_t cA16 = ((lane >> 4) & 1) * 16;
    const int rB = (lane & 7) + ((lane >> 4) & 1) * 8;
    const uint32_t cB16 = ((lane >> 3) & 1) * 16;

    uint32_t aoff[2], axor[2];
#pragma unroll
    for (int mt = 0; mt < 2; mt++) {
        int arow = wm * 32 + mt * 16 + rA;
        aoff[mt] = arow * 64;
        axor[mt] = ((arow >> 1) & 3) * 16;
    }
    uint32_t boff[2], bxor[2];
#pragma unroll
    for (int t = 0; t < 2; t++) {
        int brow = wn * 32 + t * 16 + rB;
        if (BLO) {
            boff[t] = brow * 128;
            bxor[t] = (brow & 7) * 16;
        } else {
            boff[t] = brow * 64;
            bxor[t] = ((brow >> 1) & 3) * 16;
        }
    }

    float acc[2][4][4];
#pragma unroll
    for (int mt = 0; mt < 2; mt++)
#pragma unroll
        for (int nt = 0; nt < 4; nt++)
#pragma unroll
            for (int r = 0; r < 4; r++) acc[mt][nt][r] = 0.f;

    // ---- prologue: stages 0..NSTAGE-2 in flight ----
#pragma unroll
    for (int st = 0; st < NSTAGE - 1; st++) {
        int k0 = st * 32;
        uint32_t base = sb + st * STAGE_BYTES;
#pragma unroll
        for (int i = 0; i < 2; i++) cp16(base + dA[i], pA[i] + k0);
#pragma unroll
        for (int i = 0; i < (BLO ? 2 : 1); i++)
            cp16(base + A_BYTES + dB[i], pB[i] + k0);
        cp_commit();
    }
    cp_wait<NSTAGE - 2>();
    __syncthreads();

    // ---- main loop: ONE barrier per chunk ----
    for (int kc = 0; kc < nchunk; kc++) {
        const uint32_t baseA = sb + (kc % NSTAGE) * STAGE_BYTES;
        const uint32_t baseB = baseA + A_BYTES;

        // prefetch chunk kc+NSTAGE-1 into the stage consumed at kc-1
        int next = kc + NSTAGE - 1;
        if (next < nchunk) {
            int k0 = next * 32;
            uint32_t nb = sb + (next % NSTAGE) * STAGE_BYTES;
#pragma unroll
            for (int i = 0; i < 2; i++) cp16(nb + dA[i], pA[i] + k0);
#pragma unroll
            for (int i = 0; i < (BLO ? 2 : 1); i++)
                cp16(nb + A_BYTES + dB[i], pB[i] + k0);
        }
        cp_commit();

        // compute current chunk: 2 k16 steps
#pragma unroll
        for (int s = 0; s < 2; s++) {
            uint32_t bh[8], bl[8];
#pragma unroll
            for (int t = 0; t < 2; t++) {
                uint32_t c = s * 32 + cB16;
                ldm4(&bh[t * 4], baseB + boff[t] + (c ^ bxor[t]));
                if (BLO)
                    ldm4(&bl[t * 4], baseB + boff[t] + ((c + 64) ^ bxor[t]));
            }
#pragma unroll
            for (int mt = 0; mt < 2; mt++) {
                uint32_t a[4];
                uint32_t cc = s * 32 + cA16;
                ldm4(a, baseA + aoff[mt] + (cc ^ axor[mt]));
#pragma unroll
                for (int nt = 0; nt < 4; nt++) mma16816(acc[mt][nt], a, &bh[nt * 2]);
                if (BLO) {
#pragma unroll
                    for (int nt = 0; nt < 4; nt++) mma16816(acc[mt][nt], a, &bl[nt * 2]);
                }
            }
        }

        cp_wait<NSTAGE - 2>();   // chunk kc+1 resident
        __syncthreads();
    }

    // ---- epilogue ----
#pragma unroll
    for (int mt = 0; mt < 2; mt++) {
        long r0 = bm + wm * 32 + mt * 16 + (lane >> 2);
        long r1 = r0 + 8;
#pragma unroll
        for (int nt = 0; nt < 4; nt++) {
            long col = bn + wn * 32 + nt * 8 + (lane & 3) * 2;
            float b0v = 0.f, b1v = 0.f;
            if (HAS_BIAS) { b0v = bias[col]; b1v = bias[col + 1]; }
            float v00 = acc[mt][nt][0] * scale + b0v;
            float v01 = acc[mt][nt][1] * scale + b1v;
            float v10 = acc[mt][nt][2] * scale + b0v;
            float v11 = acc[mt][nt][3] * scale + b1v;
            if (OUT == 2) {
                *reinterpret_cast<uint32_t*>(&Chi[r0 * ldc + col]) =
                    pack2(__float2half(v00), __float2half(v01));
                *reinterpret_cast<uint32_t*>(&Chi[r1 * ldc + col]) =
                    pack2(__float2half(v10), __float2half(v11));
            } else {
                float2 u0 = make_float2(v00, v01);
                float2 u1 = make_float2(v10, v11);
                *reinterpret_cast<float2*>(&C[r0 * ldc + col]) = u0;
                *reinterpret_cast<float2*>(&C[r1 * ldc + col]) = u1;
            }
        }
    }
}

// ---------------------------------------------------------------------------
// fp32 -> fp16 split conversions (vectorized)
// ---------------------------------------------------------------------------
__global__ __launch_bounds__(256) void split_hl_kernel(
    const float* __restrict__ src, h16* __restrict__ hi, h16* __restrict__ lo, int n4)
{
    int i = blockIdx.x * blockDim.x + threadIdx.x;
    if (i >= n4) return;
    float4 v = reinterpret_cast<const float4*>(src)[i];
    h16 h0, h1, h2, h3, l0, l1, l2, l3;
    split1(v.x, h0, l0); split1(v.y, h1, l1);
    split1(v.z, h2, l2); split1(v.w, h3, l3);
    reinterpret_cast<uint2*>(hi)[i] = make_uint2(pack2(h0, h1), pack2(h2, h3));
    reinterpret_cast<uint2*>(lo)[i] = make_uint2(pack2(l0, l1), pack2(l2, l3));
}

__global__ __launch_bounds__(256) void split_h_kernel(
    const float* __restrict__ src, h16* __restrict__ hi, int n4)
{
    int i = blockIdx.x * blockDim.x + threadIdx.x;
    if (i >= n4) return;
    float4 v = reinterpret_cast<const float4*>(src)[i];
    reinterpret_cast<uint2*>(hi)[i] = make_uint2(
        pack2(__float2half(v.x), __float2half(v.y)),
        pack2(__float2half(v.z), __float2half(v.w)));
}

// ---------------------------------------------------------------------------
// V transpose (hi only): vt[b][e][s] = qkv[b*S+s][2E+e]
// ---------------------------------------------------------------------------
__global__ __launch_bounds__(256) void transpose_v_kernel(
    const h16* __restrict__ qh, h16* __restrict__ vth)
{
    __shared__ h16 th[32][33];
    const int b = blockIdx.z;
    const int e0 = blockIdx.x * 32;
    const int s0 = blockIdx.y * 32;
    const int tx = threadIdx.x & 31;
    const int ty = threadIdx.x >> 5;  // 0..7
#pragma unroll
    for (int i = 0; i < 4; i++) {
        int s = s0 + ty + i * 8;
        size_t idx = (size_t)(b * SEQ + s) * (3 * EMBED) + 2 * EMBED + e0 + tx;
        th[ty + i * 8][tx] = qh[idx];
    }
    __syncthreads();
#pragma unroll
    for (int i = 0; i < 4; i++) {
        int e = e0 + ty + i * 8;
        size_t o = (size_t)(b * EMBED + e) * SEQ + s0 + tx;
        vth[o] = th[tx][ty + i * 8];
    }
}

// ---------------------------------------------------------------------------
// Row softmax with mask; writes fp16 hi probabilities (A-side of ctx GEMM).
// ---------------------------------------------------------------------------
__global__ __launch_bounds__(256) void softmax_kernel(
    const float* __restrict__ att, const int* __restrict__ mask,
    h16* __restrict__ phi)
{
    const size_t row = blockIdx.x;
    const float* a = att + row * SEQ;
    const int* m = mask + row * SEQ;
    const int tid = threadIdx.x;

    __shared__ float red_max[8];
    __shared__ float red_sum[8];

    float v[8];
    float mx = -INFINITY;
#pragma unroll
    for (int i = 0; i < 8; i++) {
        int idx = tid + i * 256;
        float x = a[idx];
        x = (m[idx] != 0) ? x : -INFINITY;
        v[i] = x;
        mx = fmaxf(mx, x);
    }
#pragma unroll
    for (int o = 16; o > 0; o >>= 1)
        mx = fmaxf(mx, __shfl_xor_sync(0xffffffffu, mx, o));
    if ((tid & 31) == 0) red_max[tid >> 5] = mx;
    __syncthreads();
    float bmax = red_max[0];
#pragma unroll
    for (int w = 1; w < 8; w++) bmax = fmaxf(bmax, red_max[w]);

    float s = 0.f;
#pragma unroll
    for (int i = 0; i < 8; i++) {
        v[i] = __expf(v[i] - bmax);
        s += v[i];
    }
#pragma unroll
    for (int o = 16; o > 0; o >>= 1)
        s += __shfl_xor_sync(0xffffffffu, s, o);
    if ((tid & 31) == 0) red_sum[tid >> 5] = s;
    __syncthreads();
    float total = 0.f;
#pragma unroll
    for (int w = 0; w < 8; w++) total += red_sum[w];

    float inv = 1.f / total;
#pragma unroll
    for (int i = 0; i < 8; i++) {
        int idx = tid + i * 256;
        phi[row * SEQ + idx] = __float2half(v[i] * inv);
    }
}

// ---------------------------------------------------------------------------
extern "C" void kernel_launch(void* const* d_in, const int* in_sizes, int n_in,
                              void* d_out, int out_size)
{
    const float* X    = (const float*)d_in[0];
    const int*   mask = (const int*)  d_in[1];
    const float* Wqkv = (const float*)d_in[2];
    const float* bqkv = (const float*)d_in[3];
    const float* Wout = (const float*)d_in[4];
    const float* bout = (const float*)d_in[5];
    float* out = (float*)d_out;

    h16 *Xhi, *Wqkvhi, *Wouthi, *Woutlo;
    h16 *qkvhi, *atthi, *vthi, *ctxhi;
    float* att;
    cudaGetSymbolAddress((void**)&Xhi, g_Xhi);
    cudaGetSymbolAddress((void**)&Wqkvhi, g_Wqkvhi);
    cudaGetSymbolAddress((void**)&Wouthi, g_Wouthi);
    cudaGetSymbolAddress((void**)&Woutlo, g_Woutlo);
    cudaGetSymbolAddress((void**)&qkvhi, g_qkvhi);
    cudaGetSymbolAddress((void**)&att, g_att);
    cudaGetSymbolAddress((void**)&atthi, g_atthi);
    cudaGetSymbolAddress((void**)&vthi, g_vthi);
    cudaGetSymbolAddress((void**)&ctxhi, g_ctxhi);

    constexpr int SM_HL = NSTAGE * (A_BYTES + 8192);  // 65536 (BLO=true)
    constexpr int SM_H  = NSTAGE * (A_BYTES + 4096);  // 49152 (BLO=false)

    // NOTE: attributes must be set on the EXACT instantiations launched below.
    cudaFuncSetAttribute(gemm_fp16<true, 2, false>,
                         cudaFuncAttributeMaxDynamicSharedMemorySize, SM_H);
    cudaFuncSetAttribute(gemm_fp16<false, 0, false>,
                         cudaFuncAttributeMaxDynamicSharedMemorySize, SM_H);
    cudaFuncSetAttribute(gemm_fp16<false, 2, false>,
                         cudaFuncAttributeMaxDynamicSharedMemorySize, SM_H);
    cudaFuncSetAttribute(gemm_fp16<true, 0, true>,
                         cudaFuncAttributeMaxDynamicSharedMemorySize, SM_HL);

    // 0) split inputs to fp16 (Wqkv: hi only now; Wout: hi+lo)
    split_h_kernel<<<(ROWS * EMBED / 4 + 255) / 256, 256>>>(X, Xhi, ROWS * EMBED / 4);
    split_h_kernel<<<(3 * EMBED * EMBED / 4 + 255) / 256, 256>>>(
        Wqkv, Wqkvhi, 3 * EMBED * EMBED / 4);
    split_hl_kernel<<<(EMBED * EMBED / 4 + 255) / 256, 256>>>(
        Wout, Wouthi, Woutlo, EMBED * EMBED / 4);

    // 1) qkv = X Wqkv^T + bqkv  (single-pass hi x hi; hi-only output)
    {
        dim3 grid(3 * EMBED / BN, ROWS / BM, 1);
        gemm_fp16<true, 2, false><<<grid, 256, SM_H>>>(
            Xhi, Wqkvhi, nullptr, bqkv,
            nullptr, qkvhi,
            EMBED, EMBED, EMBED, 3 * EMBED,
            0, 0, 0, 1.0f);
    }
    // 2) vt = V^T (hi)
    {
        dim3 grid(EMBED / 32, SEQ / 32, BATCH);
        transpose_v_kernel<<<grid, 256>>>(qkvhi, vthi);
    }
    // 3) att = Q K^T / 32  (fp32 output); single-pass hi x hi
    {
        dim3 grid(SEQ / BN, SEQ / BM, BATCH);
        gemm_fp16<false, 0, false><<<grid, 256, SM_H>>>(
            qkvhi, qkvhi + EMBED, nullptr, nullptr,
            att, nullptr,
            EMBED, 3 * EMBED, 3 * EMBED, SEQ,
            (long)SEQ * 3 * EMBED, (long)SEQ * 3 * EMBED, (long)SEQ * SEQ,
            1.0f / 32.0f);
    }
    // 4) softmax -> p (hi only)
    softmax_kernel<<<BATCH * SEQ, 256>>>(att, mask, atthi);

    // 5) ctx = p vt^T  (hi-only output); single-pass hi x hi
    {
        dim3 grid(EMBED / BN, SEQ / BM, BATCH);
        gemm_fp16<false, 2, false><<<grid, 256, SM_H>>>(
            atthi, vthi, nullptr, nullptr,
            nullptr, ctxhi,
            SEQ, SEQ, SEQ, EMBED,
            (long)SEQ * SEQ, (long)EMBED * SEQ, (long)SEQ * EMBED,
            1.0f);
    }
    // 6) out = ctx Wout^T + bout  (fp32); 2-pass weights
    {
        dim3 grid(EMBED / BN, ROWS / BM, 1);
        gemm_fp16<true, 0, true><<<grid, 256, SM_HL>>>(
            ctxhi, Wouthi, Woutlo, bout,
            out, nullptr,
            EMBED, EMBED, EMBED, EMBED,
            0, 0, 0, 1.0f);
    }
}

// round 12
// speedup vs baseline: 4.0437x; 1.0756x over previous
#include <cuda_runtime.h>
#include <cuda_fp16.h>
#include <cstdint>
#include <math.h>

// ---------------------------------------------------------------------------
// SelfAttentionV3 (B=4, S=2048, E=1024) via fp16 hi-only HMMA GEMMs.
// All 4 GEMMs single-pass hi x hi fp16. Error budget (measured trajectory):
// 4.5e-4 (R8) -> 5.0e-4 (R10) -> 6.2e-4 (R11) -> predicted ~6.8e-4 here.
// R12: R11 + drop Wout-lo (GEMM6 1-pass) + fp16 logits with in-place softmax.
// ---------------------------------------------------------------------------

#define EMBED 1024
#define BATCH 4
#define SEQ   2048
#define ROWS  (BATCH * SEQ)   // 8192

typedef __half h16;

// ---------------- static scratch (no allocs allowed) -----------------------
__device__ h16 g_Xhi[(size_t)ROWS * EMBED];
__device__ h16 g_Wqkvhi[(size_t)3 * EMBED * EMBED];
__device__ h16 g_Wouthi[(size_t)EMBED * EMBED];
__device__ h16 g_qkvhi[(size_t)ROWS * 3 * EMBED];
__device__ h16 g_att[(size_t)BATCH * SEQ * SEQ];    // logits, then probs (in-place)
__device__ h16 g_vthi[(size_t)BATCH * EMBED * SEQ];
__device__ h16 g_ctxhi[(size_t)ROWS * EMBED];

// ---------------- PTX helpers ----------------------------------------------
__device__ __forceinline__ uint32_t smem_u32(const void* p) {
    uint32_t a;
    asm("{ .reg .u64 t; cvta.to.shared.u64 t, %1; cvt.u32.u64 %0, t; }"
        : "=r"(a) : "l"(p));
    return a;
}
__device__ __forceinline__ void cp16(uint32_t dst, const void* src) {
    asm volatile("cp.async.cg.shared.global [%0], [%1], 16;"
                 :: "r"(dst), "l"(src) : "memory");
}
__device__ __forceinline__ void cp_commit() {
    asm volatile("cp.async.commit_group;" ::: "memory");
}
template <int N>
__device__ __forceinline__ void cp_wait() {
    asm volatile("cp.async.wait_group %0;" :: "n"(N) : "memory");
}
__device__ __forceinline__ void ldm4(uint32_t* r, uint32_t addr) {
    asm volatile("ldmatrix.sync.aligned.m8n8.x4.shared.b16 {%0,%1,%2,%3}, [%4];"
                 : "=r"(r[0]), "=r"(r[1]), "=r"(r[2]), "=r"(r[3]) : "r"(addr));
}
__device__ __forceinline__ void mma16816(float* c, const uint32_t* a, const uint32_t* b) {
    asm volatile("mma.sync.aligned.m16n8k16.row.col.f32.f16.f16.f32 "
                 "{%0,%1,%2,%3}, {%4,%5,%6,%7}, {%8,%9}, {%0,%1,%2,%3};"
                 : "+f"(c[0]), "+f"(c[1]), "+f"(c[2]), "+f"(c[3])
                 : "r"(a[0]), "r"(a[1]), "r"(a[2]), "r"(a[3]), "r"(b[0]), "r"(b[1]));
}
__device__ __forceinline__ uint32_t pack2(h16 a, h16 b) {
    uint16_t ua = *reinterpret_cast<uint16_t*>(&a);
    uint16_t ub = *reinterpret_cast<uint16_t*>(&b);
    return (uint32_t)ua | ((uint32_t)ub << 16);
}

// ---------------------------------------------------------------------------
// fp16 GEMM: C = scale*(A[M,K] x B[N,K]^T) (+bias). CTA tile 128x64, Kc=32.
// A/B smem row (64B): 32 fp16, XOR-((row>>1)&3)*16 swizzle.
// 8 warps in 4(m) x 2(n) grid, warp tile 32x32.
// OUT: 0 = fp32 C, 2 = fp16 Chi.
// ---------------------------------------------------------------------------
#define BM 128
#define BN 64
#define NSTAGE 4
#define A_BYTES 8192                     // 128 rows x 64B
#define B_BYTES 4096                     // 64 rows x 64B
#define STAGE_BYTES (A_BYTES + B_BYTES)  // 12288
#define SMEM_TOTAL (NSTAGE * STAGE_BYTES)  // 49152

template <bool HAS_BIAS, int OUT>
__global__ __launch_bounds__(256, 2) void gemm_fp16(
    const h16* __restrict__ Ah, const h16* __restrict__ Bh,
    const float* __restrict__ bias,
    float* __restrict__ C, h16* __restrict__ Chi,
    int K, int lda, int ldb, int ldc,
    long aBS, long bBS, long cBS, float scale)
{
    extern __shared__ char smem[];
    const uint32_t sb = smem_u32(smem);
    const int tid = threadIdx.x;
    const int lane = tid & 31;
    const int wid = tid >> 5;
    const int wm = wid & 3;       // m 32-quarter (0..3)
    const int wn = wid >> 2;      // n 32-half    (0..1)

    const long bm = (long)blockIdx.y * BM;
    const long bn = (long)blockIdx.x * BN;
    Ah += (long)blockIdx.z * aBS;
    Bh += (long)blockIdx.z * bBS;
    if (OUT == 0) C   += (long)blockIdx.z * cBS;
    else          Chi += (long)blockIdx.z * cBS;

    const int nchunk = K >> 5;

    // ---- cp.async assignments: A 2x16B/thread, B 1x16B/thread ----
    const h16* pA[2];
    uint32_t dA[2];
#pragma unroll
    for (int i = 0; i < 2; i++) {
        int ch = tid + i * 256;          // 0..511
        int row = ch >> 2;               // 0..127
        int q = ch & 3;                  // 16B quarter in 64B row
        dA[i] = (uint32_t)(row * 64) + ((uint32_t)(q * 16) ^ (((row >> 1) & 3) * 16));
        pA[i] = Ah + (size_t)(bm + row) * lda + q * 8;
    }
    const h16* pB0;
    uint32_t dB0;
    {
        int row = tid >> 2;              // 0..63
        int q = tid & 3;
        dB0 = (uint32_t)(row * 64) + ((uint32_t)(q * 16) ^ (((row >> 1) & 3) * 16));
        pB0 = Bh + (size_t)(bn + row) * ldb + q * 8;
    }

    // ---- ldmatrix lane address components ----
    const int rA = (lane & 7) + ((lane >> 3) & 1) * 8;
    const uint32_t cA16 = ((lane >> 4) & 1) * 16;
    const int rB = (lane & 7) + ((lane >> 4) & 1) * 8;
    const uint32_t cB16 = ((lane >> 3) & 1) * 16;

    uint32_t aoff[2], axor[2];
#pragma unroll
    for (int mt = 0; mt < 2; mt++) {
        int arow = wm * 32 + mt * 16 + rA;
        aoff[mt] = arow * 64;
        axor[mt] = ((arow >> 1) & 3) * 16;
    }
    uint32_t boff[2], bxor[2];
#pragma unroll
    for (int t = 0; t < 2; t++) {
        int brow = wn * 32 + t * 16 + rB;
        boff[t] = brow * 64;
        bxor[t] = ((brow >> 1) & 3) * 16;
    }

    float acc[2][4][4];
#pragma unroll
    for (int mt = 0; mt < 2; mt++)
#pragma unroll
        for (int nt = 0; nt < 4; nt++)
#pragma unroll
            for (int r = 0; r < 4; r++) acc[mt][nt][r] = 0.f;

    // ---- prologue: stages 0..NSTAGE-2 in flight ----
#pragma unroll
    for (int st = 0; st < NSTAGE - 1; st++) {
        int k0 = st * 32;
        uint32_t base = sb + st * STAGE_BYTES;
#pragma unroll
        for (int i = 0; i < 2; i++) cp16(base + dA[i], pA[i] + k0);
        cp16(base + A_BYTES + dB0, pB0 + k0);
        cp_commit();
    }
    cp_wait<NSTAGE - 2>();
    __syncthreads();

    // ---- main loop: ONE barrier per chunk ----
    for (int kc = 0; kc < nchunk; kc++) {
        const uint32_t baseA = sb + (kc % NSTAGE) * STAGE_BYTES;
        const uint32_t baseB = baseA + A_BYTES;

        // prefetch chunk kc+NSTAGE-1 into the stage consumed at kc-1
        int next = kc + NSTAGE - 1;
        if (next < nchunk) {
            int k0 = next * 32;
            uint32_t nb = sb + (next % NSTAGE) * STAGE_BYTES;
#pragma unroll
            for (int i = 0; i < 2; i++) cp16(nb + dA[i], pA[i] + k0);
            cp16(nb + A_BYTES + dB0, pB0 + k0);
        }
        cp_commit();

        // compute current chunk: 2 k16 steps, 8 MMAs + 4 LDSM each
#pragma unroll
        for (int s = 0; s < 2; s++) {
            uint32_t bh[8];
#pragma unroll
            for (int t = 0; t < 2; t++) {
                uint32_t c = s * 32 + cB16;
                ldm4(&bh[t * 4], baseB + boff[t] + (c ^ bxor[t]));
            }
#pragma unroll
            for (int mt = 0; mt < 2; mt++) {
                uint32_t a[4];
                uint32_t cc = s * 32 + cA16;
                ldm4(a, baseA + aoff[mt] + (cc ^ axor[mt]));
#pragma unroll
                for (int nt = 0; nt < 4; nt++) mma16816(acc[mt][nt], a, &bh[nt * 2]);
            }
        }

        cp_wait<NSTAGE - 2>();   // chunk kc+1 resident
        __syncthreads();
    }

    // ---- epilogue ----
#pragma unroll
    for (int mt = 0; mt < 2; mt++) {
        long r0 = bm + wm * 32 + mt * 16 + (lane >> 2);
        long r1 = r0 + 8;
#pragma unroll
        for (int nt = 0; nt < 4; nt++) {
            long col = bn + wn * 32 + nt * 8 + (lane & 3) * 2;
            float b0v = 0.f, b1v = 0.f;
            if (HAS_BIAS) { b0v = bias[col]; b1v = bias[col + 1]; }
            float v00 = acc[mt][nt][0] * scale + b0v;
            float v01 = acc[mt][nt][1] * scale + b1v;
            float v10 = acc[mt][nt][2] * scale + b0v;
            float v11 = acc[mt][nt][3] * scale + b1v;
            if (OUT == 2) {
                *reinterpret_cast<uint32_t*>(&Chi[r0 * ldc + col]) =
                    pack2(__float2half(v00), __float2half(v01));
                *reinterpret_cast<uint32_t*>(&Chi[r1 * ldc + col]) =
                    pack2(__float2half(v10), __float2half(v11));
            } else {
                float2 u0 = make_float2(v00, v01);
                float2 u1 = make_float2(v10, v11);
                *reinterpret_cast<float2*>(&C[r0 * ldc + col]) = u0;
                *reinterpret_cast<float2*>(&C[r1 * ldc + col]) = u1;
            }
        }
    }
}

// ---------------------------------------------------------------------------
// fp32 -> fp16 conversion (vectorized)
// ---------------------------------------------------------------------------
__global__ __launch_bounds__(256) void split_h_kernel(
    const float* __restrict__ src, h16* __restrict__ hi, int n4)
{
    int i = blockIdx.x * blockDim.x + threadIdx.x;
    if (i >= n4) return;
    float4 v = reinterpret_cast<const float4*>(src)[i];
    reinterpret_cast<uint2*>(hi)[i] = make_uint2(
        pack2(__float2half(v.x), __float2half(v.y)),
        pack2(__float2half(v.z), __float2half(v.w)));
}

// ---------------------------------------------------------------------------
// V transpose (hi only): vt[b][e][s] = qkv[b*S+s][2E+e]
// ---------------------------------------------------------------------------
__global__ __launch_bounds__(256) void transpose_v_kernel(
    const h16* __restrict__ qh, h16* __restrict__ vth)
{
    __shared__ h16 th[32][33];
    const int b = blockIdx.z;
    const int e0 = blockIdx.x * 32;
    const int s0 = blockIdx.y * 32;
    const int tx = threadIdx.x & 31;
    const int ty = threadIdx.x >> 5;  // 0..7
#pragma unroll
    for (int i = 0; i < 4; i++) {
        int s = s0 + ty + i * 8;
        size_t idx = (size_t)(b * SEQ + s) * (3 * EMBED) + 2 * EMBED + e0 + tx;
        th[ty + i * 8][tx] = qh[idx];
    }
    __syncthreads();
#pragma unroll
    for (int i = 0; i < 4; i++) {
        int e = e0 + ty + i * 8;
        size_t o = (size_t)(b * EMBED + e) * SEQ + s0 + tx;
        vth[o] = th[tx][ty + i * 8];
    }
}

// ---------------------------------------------------------------------------
// Row softmax with mask, IN-PLACE on fp16 logits (one block per row; each
// block reads then overwrites only its own row -- no cross-block hazard).
// ---------------------------------------------------------------------------
__global__ __launch_bounds__(256) void softmax_kernel(
    h16* __restrict__ att, const int* __restrict__ mask)
{
    const size_t row = blockIdx.x;
    h16* a = att + row * SEQ;
    const int* m = mask + row * SEQ;
    const int tid = threadIdx.x;

    __shared__ float red_max[8];
    __shared__ float red_sum[8];

    float v[8];
    float mx = -INFINITY;
#pragma unroll
    for (int i = 0; i < 8; i++) {
        int idx = tid + i * 256;
        float x = __half2float(a[idx]);
        x = (m[idx] != 0) ? x : -INFINITY;
        v[i] = x;
        mx = fmaxf(mx, x);
    }
#pragma unroll
    for (int o = 16; o > 0; o >>= 1)
        mx = fmaxf(mx, __shfl_xor_sync(0xffffffffu, mx, o));
    if ((tid & 31) == 0) red_max[tid >> 5] = mx;
    __syncthreads();
    float bmax = red_max[0];
#pragma unroll
    for (int w = 1; w < 8; w++) bmax = fmaxf(bmax, red_max[w]);

    float s = 0.f;
#pragma unroll
    for (int i = 0; i < 8; i++) {
        v[i] = __expf(v[i] - bmax);
        s += v[i];
    }
#pragma unroll
    for (int o = 16; o > 0; o >>= 1)
        s += __shfl_xor_sync(0xffffffffu, s, o);
    if ((tid & 31) == 0) red_sum[tid >> 5] = s;
    __syncthreads();
    float total = 0.f;
#pragma unroll
    for (int w = 0; w < 8; w++) total += red_sum[w];

    float inv = 1.f / total;
#pragma unroll
    for (int i = 0; i < 8; i++) {
        int idx = tid + i * 256;
        a[idx] = __float2half(v[i] * inv);
    }
}

// ---------------------------------------------------------------------------
extern "C" void kernel_launch(void* const* d_in, const int* in_sizes, int n_in,
                              void* d_out, int out_size)
{
    const float* X    = (const float*)d_in[0];
    const int*   mask = (const int*)  d_in[1];
    const float* Wqkv = (const float*)d_in[2];
    const float* bqkv = (const float*)d_in[3];
    const float* Wout = (const float*)d_in[4];
    const float* bout = (const float*)d_in[5];
    float* out = (float*)d_out;

    h16 *Xhi, *Wqkvhi, *Wouthi, *qkvhi, *att, *vthi, *ctxhi;
    cudaGetSymbolAddress((void**)&Xhi, g_Xhi);
    cudaGetSymbolAddress((void**)&Wqkvhi, g_Wqkvhi);
    cudaGetSymbolAddress((void**)&Wouthi, g_Wouthi);
    cudaGetSymbolAddress((void**)&qkvhi, g_qkvhi);
    cudaGetSymbolAddress((void**)&att, g_att);
    cudaGetSymbolAddress((void**)&vthi, g_vthi);
    cudaGetSymbolAddress((void**)&ctxhi, g_ctxhi);

    // NOTE: attributes must be set on the EXACT instantiations launched below.
    cudaFuncSetAttribute(gemm_fp16<true, 2>,
                         cudaFuncAttributeMaxDynamicSharedMemorySize, SMEM_TOTAL);
    cudaFuncSetAttribute(gemm_fp16<false, 2>,
                         cudaFuncAttributeMaxDynamicSharedMemorySize, SMEM_TOTAL);
    cudaFuncSetAttribute(gemm_fp16<true, 0>,
                         cudaFuncAttributeMaxDynamicSharedMemorySize, SMEM_TOTAL);

    // 0) convert inputs to fp16 (hi only)
    split_h_kernel<<<(ROWS * EMBED / 4 + 255) / 256, 256>>>(X, Xhi, ROWS * EMBED / 4);
    split_h_kernel<<<(3 * EMBED * EMBED / 4 + 255) / 256, 256>>>(
        Wqkv, Wqkvhi, 3 * EMBED * EMBED / 4);
    split_h_kernel<<<(EMBED * EMBED / 4 + 255) / 256, 256>>>(
        Wout, Wouthi, EMBED * EMBED / 4);

    // 1) qkv = X Wqkv^T + bqkv  (fp16 output)
    {
        dim3 grid(3 * EMBED / BN, ROWS / BM, 1);
        gemm_fp16<true, 2><<<grid, 256, SMEM_TOTAL>>>(
            Xhi, Wqkvhi, bqkv,
            nullptr, qkvhi,
            EMBED, EMBED, EMBED, 3 * EMBED,
            0, 0, 0, 1.0f);
    }
    // 2) vt = V^T
    {
        dim3 grid(EMBED / 32, SEQ / 32, BATCH);
        transpose_v_kernel<<<grid, 256>>>(qkvhi, vthi);
    }
    // 3) att = Q K^T / 32  (fp16 logits)
    {
        dim3 grid(SEQ / BN, SEQ / BM, BATCH);
        gemm_fp16<false, 2><<<grid, 256, SMEM_TOTAL>>>(
            qkvhi, qkvhi + EMBED, nullptr,
            nullptr, att,
            EMBED, 3 * EMBED, 3 * EMBED, SEQ,
            (long)SEQ * 3 * EMBED, (long)SEQ * 3 * EMBED, (long)SEQ * SEQ,
            1.0f / 32.0f);
    }
    // 4) softmax in-place on fp16 logits -> fp16 probs
    softmax_kernel<<<BATCH * SEQ, 256>>>(att, mask);

    // 5) ctx = p vt^T  (fp16 output)
    {
        dim3 grid(EMBED / BN, SEQ / BM, BATCH);
        gemm_fp16<false, 2><<<grid, 256, SMEM_TOTAL>>>(
            att, vthi, nullptr,
            nullptr, ctxhi,
            SEQ, SEQ, SEQ, EMBED,
            (long)SEQ * SEQ, (long)EMBED * SEQ, (long)SEQ * EMBED,
            1.0f);
    }
    // 6) out = ctx Wout^T + bout  (fp32)
    {
        dim3 grid(EMBED / BN, ROWS / BM, 1);
        gemm_fp16<true, 0><<<grid, 256, SMEM_TOTAL>>>(
            ctxhi, Wouthi, bout,
            out, nullptr,
            EMBED, EMBED, EMBED, EMBED,
            0, 0, 0, 1.0f);
    }
}

// round 13
// speedup vs baseline: 4.2283x; 1.0456x over previous
#include <cuda_runtime.h>
#include <cuda_fp16.h>
#include <cstdint>
#include <math.h>

// ---------------------------------------------------------------------------
// SelfAttentionV3 (B=4, S=2048, E=1024) via fp16 hi-only HMMA GEMMs.
// All 4 GEMMs single-pass hi x hi fp16 (rel_err budget spent: 7.4e-4).
// R13: R12 + __launch_bounds__(256,3) -> 3 CTAs/SM (24 warps), ptxas targets
// <=85 regs; hot loop needs ~81 so spills should land in cold epilogue code.
// ---------------------------------------------------------------------------

#define EMBED 1024
#define BATCH 4
#define SEQ   2048
#define ROWS  (BATCH * SEQ)   // 8192

typedef __half h16;

// ---------------- static scratch (no allocs allowed) -----------------------
__device__ h16 g_Xhi[(size_t)ROWS * EMBED];
__device__ h16 g_Wqkvhi[(size_t)3 * EMBED * EMBED];
__device__ h16 g_Wouthi[(size_t)EMBED * EMBED];
__device__ h16 g_qkvhi[(size_t)ROWS * 3 * EMBED];
__device__ h16 g_att[(size_t)BATCH * SEQ * SEQ];    // logits, then probs (in-place)
__device__ h16 g_vthi[(size_t)BATCH * EMBED * SEQ];
__device__ h16 g_ctxhi[(size_t)ROWS * EMBED];

// ---------------- PTX helpers ----------------------------------------------
__device__ __forceinline__ uint32_t smem_u32(const void* p) {
    uint32_t a;
    asm("{ .reg .u64 t; cvta.to.shared.u64 t, %1; cvt.u32.u64 %0, t; }"
        : "=r"(a) : "l"(p));
    return a;
}
__device__ __forceinline__ void cp16(uint32_t dst, const void* src) {
    asm volatile("cp.async.cg.shared.global [%0], [%1], 16;"
                 :: "r"(dst), "l"(src) : "memory");
}
__device__ __forceinline__ void cp_commit() {
    asm volatile("cp.async.commit_group;" ::: "memory");
}
template <int N>
__device__ __forceinline__ void cp_wait() {
    asm volatile("cp.async.wait_group %0;" :: "n"(N) : "memory");
}
__device__ __forceinline__ void ldm4(uint32_t* r, uint32_t addr) {
    asm volatile("ldmatrix.sync.aligned.m8n8.x4.shared.b16 {%0,%1,%2,%3}, [%4];"
                 : "=r"(r[0]), "=r"(r[1]), "=r"(r[2]), "=r"(r[3]) : "r"(addr));
}
__device__ __forceinline__ void mma16816(float* c, const uint32_t* a, const uint32_t* b) {
    asm volatile("mma.sync.aligned.m16n8k16.row.col.f32.f16.f16.f32 "
                 "{%0,%1,%2,%3}, {%4,%5,%6,%7}, {%8,%9}, {%0,%1,%2,%3};"
                 : "+f"(c[0]), "+f"(c[1]), "+f"(c[2]), "+f"(c[3])
                 : "r"(a[0]), "r"(a[1]), "r"(a[2]), "r"(a[3]), "r"(b[0]), "r"(b[1]));
}
__device__ __forceinline__ uint32_t pack2(h16 a, h16 b) {
    uint16_t ua = *reinterpret_cast<uint16_t*>(&a);
    uint16_t ub = *reinterpret_cast<uint16_t*>(&b);
    return (uint32_t)ua | ((uint32_t)ub << 16);
}

// ---------------------------------------------------------------------------
// fp16 GEMM: C = scale*(A[M,K] x B[N,K]^T) (+bias). CTA tile 128x64, Kc=32.
// A/B smem row (64B): 32 fp16, XOR-((row>>1)&3)*16 swizzle.
// 8 warps in 4(m) x 2(n) grid, warp tile 32x32.
// OUT: 0 = fp32 C, 2 = fp16 Chi.
// ---------------------------------------------------------------------------
#define BM 128
#define BN 64
#define NSTAGE 4
#define A_BYTES 8192                     // 128 rows x 64B
#define B_BYTES 4096                     // 64 rows x 64B
#define STAGE_BYTES (A_BYTES + B_BYTES)  // 12288
#define SMEM_TOTAL (NSTAGE * STAGE_BYTES)  // 49152

template <bool HAS_BIAS, int OUT>
__global__ __launch_bounds__(256, 3) void gemm_fp16(
    const h16* __restrict__ Ah, const h16* __restrict__ Bh,
    const float* __restrict__ bias,
    float* __restrict__ C, h16* __restrict__ Chi,
    int K, int lda, int ldb, int ldc,
    long aBS, long bBS, long cBS, float scale)
{
    extern __shared__ char smem[];
    const uint32_t sb = smem_u32(smem);
    const int tid = threadIdx.x;
    const int lane = tid & 31;
    const int wid = tid >> 5;
    const int wm = wid & 3;       // m 32-quarter (0..3)
    const int wn = wid >> 2;      // n 32-half    (0..1)

    const long bm = (long)blockIdx.y * BM;
    const long bn = (long)blockIdx.x * BN;
    Ah += (long)blockIdx.z * aBS;
    Bh += (long)blockIdx.z * bBS;
    if (OUT == 0) C   += (long)blockIdx.z * cBS;
    else          Chi += (long)blockIdx.z * cBS;

    const int nchunk = K >> 5;

    // ---- cp.async assignments: A 2x16B/thread, B 1x16B/thread ----
    const h16* pA[2];
    uint32_t dA[2];
#pragma unroll
    for (int i = 0; i < 2; i++) {
        int ch = tid + i * 256;          // 0..511
        int row = ch >> 2;               // 0..127
        int q = ch & 3;                  // 16B quarter in 64B row
        dA[i] = (uint32_t)(row * 64) + ((uint32_t)(q * 16) ^ (((row >> 1) & 3) * 16));
        pA[i] = Ah + (size_t)(bm + row) * lda + q * 8;
    }
    const h16* pB0;
    uint32_t dB0;
    {
        int row = tid >> 2;              // 0..63
        int q = tid & 3;
        dB0 = (uint32_t)(row * 64) + ((uint32_t)(q * 16) ^ (((row >> 1) & 3) * 16));
        pB0 = Bh + (size_t)(bn + row) * ldb + q * 8;
    }

    // ---- ldmatrix lane address components ----
    const int rA = (lane & 7) + ((lane >> 3) & 1) * 8;
    const uint32_t cA16 = ((lane >> 4) & 1) * 16;
    const int rB = (lane & 7) + ((lane >> 4) & 1) * 8;
    const uint32_t cB16 = ((lane >> 3) & 1) * 16;

    uint32_t aoff[2], axor[2];
#pragma unroll
    for (int mt = 0; mt < 2; mt++) {
        int arow = wm * 32 + mt * 16 + rA;
        aoff[mt] = arow * 64;
        axor[mt] = ((arow >> 1) & 3) * 16;
    }
    uint32_t boff[2], bxor[2];
#pragma unroll
    for (int t = 0; t < 2; t++) {
        int brow = wn * 32 + t * 16 + rB;
        boff[t] = brow * 64;
        bxor[t] = ((brow >> 1) & 3) * 16;
    }

    float acc[2][4][4];
#pragma unroll
    for (int mt = 0; mt < 2; mt++)
#pragma unroll
        for (int nt = 0; nt < 4; nt++)
#pragma unroll
            for (int r = 0; r < 4; r++) acc[mt][nt][r] = 0.f;

    // ---- prologue: stages 0..NSTAGE-2 in flight ----
#pragma unroll
    for (int st = 0; st < NSTAGE - 1; st++) {
        int k0 = st * 32;
        uint32_t base = sb + st * STAGE_BYTES;
#pragma unroll
        for (int i = 0; i < 2; i++) cp16(base + dA[i], pA[i] + k0);
        cp16(base + A_BYTES + dB0, pB0 + k0);
        cp_commit();
    }
    cp_wait<NSTAGE - 2>();
    __syncthreads();

    // ---- main loop: ONE barrier per chunk ----
    for (int kc = 0; kc < nchunk; kc++) {
        const uint32_t baseA = sb + (kc % NSTAGE) * STAGE_BYTES;
        const uint32_t baseB = baseA + A_BYTES;

        // prefetch chunk kc+NSTAGE-1 into the stage consumed at kc-1
        int next = kc + NSTAGE - 1;
        if (next < nchunk) {
            int k0 = next * 32;
            uint32_t nb = sb + (next % NSTAGE) * STAGE_BYTES;
#pragma unroll
            for (int i = 0; i < 2; i++) cp16(nb + dA[i], pA[i] + k0);
            cp16(nb + A_BYTES + dB0, pB0 + k0);
        }
        cp_commit();

        // compute current chunk: 2 k16 steps, 8 MMAs + 4 LDSM each
#pragma unroll
        for (int s = 0; s < 2; s++) {
            uint32_t bh[8];
#pragma unroll
            for (int t = 0; t < 2; t++) {
                uint32_t c = s * 32 + cB16;
                ldm4(&bh[t * 4], baseB + boff[t] + (c ^ bxor[t]));
            }
#pragma unroll
            for (int mt = 0; mt < 2; mt++) {
                uint32_t a[4];
                uint32_t cc = s * 32 + cA16;
                ldm4(a, baseA + aoff[mt] + (cc ^ axor[mt]));
#pragma unroll
                for (int nt = 0; nt < 4; nt++) mma16816(acc[mt][nt], a, &bh[nt * 2]);
            }
        }

        cp_wait<NSTAGE - 2>();   // chunk kc+1 resident
        __syncthreads();
    }

    // ---- epilogue ----
#pragma unroll
    for (int mt = 0; mt < 2; mt++) {
        long r0 = bm + wm * 32 + mt * 16 + (lane >> 2);
        long r1 = r0 + 8;
#pragma unroll
        for (int nt = 0; nt < 4; nt++) {
            long col = bn + wn * 32 + nt * 8 + (lane & 3) * 2;
            float b0v = 0.f, b1v = 0.f;
            if (HAS_BIAS) { b0v = bias[col]; b1v = bias[col + 1]; }
            float v00 = acc[mt][nt][0] * scale + b0v;
            float v01 = acc[mt][nt][1] * scale + b1v;
            float v10 = acc[mt][nt][2] * scale + b0v;
            float v11 = acc[mt][nt][3] * scale + b1v;
            if (OUT == 2) {
                *reinterpret_cast<uint32_t*>(&Chi[r0 * ldc + col]) =
                    pack2(__float2half(v00), __float2half(v01));
                *reinterpret_cast<uint32_t*>(&Chi[r1 * ldc + col]) =
                    pack2(__float2half(v10), __float2half(v11));
            } else {
                float2 u0 = make_float2(v00, v01);
                float2 u1 = make_float2(v10, v11);
                *reinterpret_cast<float2*>(&C[r0 * ldc + col]) = u0;
                *reinterpret_cast<float2*>(&C[r1 * ldc + col]) = u1;
            }
        }
    }
}

// ---------------------------------------------------------------------------
// fp32 -> fp16 conversion (vectorized)
// ---------------------------------------------------------------------------
__global__ __launch_bounds__(256) void split_h_kernel(
    const float* __restrict__ src, h16* __restrict__ hi, int n4)
{
    int i = blockIdx.x * blockDim.x + threadIdx.x;
    if (i >= n4) return;
    float4 v = reinterpret_cast<const float4*>(src)[i];
    reinterpret_cast<uint2*>(hi)[i] = make_uint2(
        pack2(__float2half(v.x), __float2half(v.y)),
        pack2(__float2half(v.z), __float2half(v.w)));
}

// ---------------------------------------------------------------------------
// V transpose (hi only): vt[b][e][s] = qkv[b*S+s][2E+e]
// ---------------------------------------------------------------------------
__global__ __launch_bounds__(256) void transpose_v_kernel(
    const h16* __restrict__ qh, h16* __restrict__ vth)
{
    __shared__ h16 th[32][33];
    const int b = blockIdx.z;
    const int e0 = blockIdx.x * 32;
    const int s0 = blockIdx.y * 32;
    const int tx = threadIdx.x & 31;
    const int ty = threadIdx.x >> 5;  // 0..7
#pragma unroll
    for (int i = 0; i < 4; i++) {
        int s = s0 + ty + i * 8;
        size_t idx = (size_t)(b * SEQ + s) * (3 * EMBED) + 2 * EMBED + e0 + tx;
        th[ty + i * 8][tx] = qh[idx];
    }
    __syncthreads();
#pragma unroll
    for (int i = 0; i < 4; i++) {
        int e = e0 + ty + i * 8;
        size_t o = (size_t)(b * EMBED + e) * SEQ + s0 + tx;
        vth[o] = th[tx][ty + i * 8];
    }
}

// ---------------------------------------------------------------------------
// Row softmax with mask, IN-PLACE on fp16 logits (one block per row).
// ---------------------------------------------------------------------------
__global__ __launch_bounds__(256) void softmax_kernel(
    h16* __restrict__ att, const int* __restrict__ mask)
{
    const size_t row = blockIdx.x;
    h16* a = att + row * SEQ;
    const int* m = mask + row * SEQ;
    const int tid = threadIdx.x;

    __shared__ float red_max[8];
    __shared__ float red_sum[8];

    float v[8];
    float mx = -INFINITY;
#pragma unroll
    for (int i = 0; i < 8; i++) {
        int idx = tid + i * 256;
        float x = __half2float(a[idx]);
        x = (m[idx] != 0) ? x : -INFINITY;
        v[i] = x;
        mx = fmaxf(mx, x);
    }
#pragma unroll
    for (int o = 16; o > 0; o >>= 1)
        mx = fmaxf(mx, __shfl_xor_sync(0xffffffffu, mx, o));
    if ((tid & 31) == 0) red_max[tid >> 5] = mx;
    __syncthreads();
    float bmax = red_max[0];
#pragma unroll
    for (int w = 1; w < 8; w++) bmax = fmaxf(bmax, red_max[w]);

    float s = 0.f;
#pragma unroll
    for (int i = 0; i < 8; i++) {
        v[i] = __expf(v[i] - bmax);
        s += v[i];
    }
#pragma unroll
    for (int o = 16; o > 0; o >>= 1)
        s += __shfl_xor_sync(0xffffffffu, s, o);
    if ((tid & 31) == 0) red_sum[tid >> 5] = s;
    __syncthreads();
    float total = 0.f;
#pragma unroll
    for (int w = 0; w < 8; w++) total += red_sum[w];

    float inv = 1.f / total;
#pragma unroll
    for (int i = 0; i < 8; i++) {
        int idx = tid + i * 256;
        a[idx] = __float2half(v[i] * inv);
    }
}

// ---------------------------------------------------------------------------
extern "C" void kernel_launch(void* const* d_in, const int* in_sizes, int n_in,
                              void* d_out, int out_size)
{
    const float* X    = (const float*)d_in[0];
    const int*   mask = (const int*)  d_in[1];
    const float* Wqkv = (const float*)d_in[2];
    const float* bqkv = (const float*)d_in[3];
    const float* Wout = (const float*)d_in[4];
    const float* bout = (const float*)d_in[5];
    float* out = (float*)d_out;

    h16 *Xhi, *Wqkvhi, *Wouthi, *qkvhi, *att, *vthi, *ctxhi;
    cudaGetSymbolAddress((void**)&Xhi, g_Xhi);
    cudaGetSymbolAddress((void**)&Wqkvhi, g_Wqkvhi);
    cudaGetSymbolAddress((void**)&Wouthi, g_Wouthi);
    cudaGetSymbolAddress((void**)&qkvhi, g_qkvhi);
    cudaGetSymbolAddress((void**)&att, g_att);
    cudaGetSymbolAddress((void**)&vthi, g_vthi);
    cudaGetSymbolAddress((void**)&ctxhi, g_ctxhi);

    // NOTE: attributes must be set on the EXACT instantiations launched below.
    cudaFuncSetAttribute(gemm_fp16<true, 2>,
                         cudaFuncAttributeMaxDynamicSharedMemorySize, SMEM_TOTAL);
    cudaFuncSetAttribute(gemm_fp16<false, 2>,
                         cudaFuncAttributeMaxDynamicSharedMemorySize, SMEM_TOTAL);
    cudaFuncSetAttribute(gemm_fp16<true, 0>,
                         cudaFuncAttributeMaxDynamicSharedMemorySize, SMEM_TOTAL);

    // 0) convert inputs to fp16 (hi only)
    split_h_kernel<<<(ROWS * EMBED / 4 + 255) / 256, 256>>>(X, Xhi, ROWS * EMBED / 4);
    split_h_kernel<<<(3 * EMBED * EMBED / 4 + 255) / 256, 256>>>(
        Wqkv, Wqkvhi, 3 * EMBED * EMBED / 4);
    split_h_kernel<<<(EMBED * EMBED / 4 + 255) / 256, 256>>>(
        Wout, Wouthi, EMBED * EMBED / 4);

    // 1) qkv = X Wqkv^T + bqkv  (fp16 output)
    {
        dim3 grid(3 * EMBED / BN, ROWS / BM, 1);
        gemm_fp16<true, 2><<<grid, 256, SMEM_TOTAL>>>(
            Xhi, Wqkvhi, bqkv,
            nullptr, qkvhi,
            EMBED, EMBED, EMBED, 3 * EMBED,
            0, 0, 0, 1.0f);
    }
    // 2) vt = V^T
    {
        dim3 grid(EMBED / 32, SEQ / 32, BATCH);
        transpose_v_kernel<<<grid, 256>>>(qkvhi, vthi);
    }
    // 3) att = Q K^T / 32  (fp16 logits)
    {
        dim3 grid(SEQ / BN, SEQ / BM, BATCH);
        gemm_fp16<false, 2><<<grid, 256, SMEM_TOTAL>>>(
            qkvhi, qkvhi + EMBED, nullptr,
            nullptr, att,
            EMBED, 3 * EMBED, 3 * EMBED, SEQ,
            (long)SEQ * 3 * EMBED, (long)SEQ * 3 * EMBED, (long)SEQ * SEQ,
            1.0f / 32.0f);
    }
    // 4) softmax in-place on fp16 logits -> fp16 probs
    softmax_kernel<<<BATCH * SEQ, 256>>>(att, mask);

    // 5) ctx = p vt^T  (fp16 output)
    {
        dim3 grid(EMBED / BN, SEQ / BM, BATCH);
        gemm_fp16<false, 2><<<grid, 256, SMEM_TOTAL>>>(
            att, vthi, nullptr,
            nullptr, ctxhi,
            SEQ, SEQ, SEQ, EMBED,
            (long)SEQ * SEQ, (long)EMBED * SEQ, (long)SEQ * EMBED,
            1.0f);
    }
    // 6) out = ctx Wout^T + bout  (fp32)
    {
        dim3 grid(EMBED / BN, ROWS / BM, 1);
        gemm_fp16<true, 0><<<grid, 256, SMEM_TOTAL>>>(
            ctxhi, Wouthi, bout,
            out, nullptr,
            EMBED, EMBED, EMBED, EMBED,
            0, 0, 0, 1.0f);
    }
}

// round 14
// speedup vs baseline: 4.3375x; 1.0258x over previous
#include <cuda_runtime.h>
#include <cuda_fp16.h>
#include <cstdint>
#include <math.h>

// ---------------------------------------------------------------------------
// SelfAttentionV3 (B=4, S=2048, E=1024) via fp16 hi-only HMMA GEMMs.
// R14: smem-BW-bound fix -- CTA tile 128x128, warp tile 32x64 (ratio
// MMA:LDSM 2.67 vs 2.0, smem bytes/MMA -27%), 2 CTAs/SM, Kc=32, 4 stages.
// ---------------------------------------------------------------------------

#define EMBED 1024
#define BATCH 4
#define SEQ   2048
#define ROWS  (BATCH * SEQ)   // 8192

typedef __half h16;

// ---------------- static scratch (no allocs allowed) -----------------------
__device__ h16 g_Xhi[(size_t)ROWS * EMBED];
__device__ h16 g_Wqkvhi[(size_t)3 * EMBED * EMBED];
__device__ h16 g_Wouthi[(size_t)EMBED * EMBED];
__device__ h16 g_qkvhi[(size_t)ROWS * 3 * EMBED];
__device__ h16 g_att[(size_t)BATCH * SEQ * SEQ];    // logits, then probs (in-place)
__device__ h16 g_vthi[(size_t)BATCH * EMBED * SEQ];
__device__ h16 g_ctxhi[(size_t)ROWS * EMBED];

// ---------------- PTX helpers ----------------------------------------------
__device__ __forceinline__ uint32_t smem_u32(const void* p) {
    uint32_t a;
    asm("{ .reg .u64 t; cvta.to.shared.u64 t, %1; cvt.u32.u64 %0, t; }"
        : "=r"(a) : "l"(p));
    return a;
}
__device__ __forceinline__ void cp16(uint32_t dst, const void* src) {
    asm volatile("cp.async.cg.shared.global [%0], [%1], 16;"
                 :: "r"(dst), "l"(src) : "memory");
}
__device__ __forceinline__ void cp_commit() {
    asm volatile("cp.async.commit_group;" ::: "memory");
}
template <int N>
__device__ __forceinline__ void cp_wait() {
    asm volatile("cp.async.wait_group %0;" :: "n"(N) : "memory");
}
__device__ __forceinline__ void ldm4(uint32_t* r, uint32_t addr) {
    asm volatile("ldmatrix.sync.aligned.m8n8.x4.shared.b16 {%0,%1,%2,%3}, [%4];"
                 : "=r"(r[0]), "=r"(r[1]), "=r"(r[2]), "=r"(r[3]) : "r"(addr));
}
__device__ __forceinline__ void mma16816(float* c, const uint32_t* a, const uint32_t* b) {
    asm volatile("mma.sync.aligned.m16n8k16.row.col.f32.f16.f16.f32 "
                 "{%0,%1,%2,%3}, {%4,%5,%6,%7}, {%8,%9}, {%0,%1,%2,%3};"
                 : "+f"(c[0]), "+f"(c[1]), "+f"(c[2]), "+f"(c[3])
                 : "r"(a[0]), "r"(a[1]), "r"(a[2]), "r"(a[3]), "r"(b[0]), "r"(b[1]));
}
__device__ __forceinline__ uint32_t pack2(h16 a, h16 b) {
    uint16_t ua = *reinterpret_cast<uint16_t*>(&a);
    uint16_t ub = *reinterpret_cast<uint16_t*>(&b);
    return (uint32_t)ua | ((uint32_t)ub << 16);
}

// ---------------------------------------------------------------------------
// fp16 GEMM: C = scale*(A[M,K] x B[N,K]^T) (+bias). CTA tile 128x128, Kc=32.
// A/B smem row (64B): 32 fp16, XOR-((row>>1)&3)*16 swizzle.
// 8 warps in 4(m) x 2(n) grid, warp tile 32x64.
// OUT: 0 = fp32 C, 2 = fp16 Chi.
// ---------------------------------------------------------------------------
#define BM 128
#define BN 128
#define NSTAGE 4
#define A_BYTES 8192                     // 128 rows x 64B
#define B_BYTES 8192                     // 128 rows x 64B
#define STAGE_BYTES (A_BYTES + B_BYTES)  // 16384
#define SMEM_TOTAL (NSTAGE * STAGE_BYTES)  // 65536

template <bool HAS_BIAS, int OUT>
__global__ __launch_bounds__(256, 2) void gemm_fp16(
    const h16* __restrict__ Ah, const h16* __restrict__ Bh,
    const float* __restrict__ bias,
    float* __restrict__ C, h16* __restrict__ Chi,
    int K, int lda, int ldb, int ldc,
    long aBS, long bBS, long cBS, float scale)
{
    extern __shared__ char smem[];
    const uint32_t sb = smem_u32(smem);
    const int tid = threadIdx.x;
    const int lane = tid & 31;
    const int wid = tid >> 5;
    const int wm = wid & 3;       // m 32-quarter (0..3)
    const int wn = wid >> 2;      // n 64-half    (0..1)

    const long bm = (long)blockIdx.y * BM;
    const long bn = (long)blockIdx.x * BN;
    Ah += (long)blockIdx.z * aBS;
    Bh += (long)blockIdx.z * bBS;
    if (OUT == 0) C   += (long)blockIdx.z * cBS;
    else          Chi += (long)blockIdx.z * cBS;

    const int nchunk = K >> 5;

    // ---- cp.async assignments: A 2x16B/thread, B 2x16B/thread ----
    const h16* pA[2]; const h16* pB[2];
    uint32_t dAB[2];
#pragma unroll
    for (int i = 0; i < 2; i++) {
        int ch = tid + i * 256;          // 0..511
        int row = ch >> 2;               // 0..127
        int q = ch & 3;                  // 16B quarter in 64B row
        dAB[i] = (uint32_t)(row * 64) + ((uint32_t)(q * 16) ^ (((row >> 1) & 3) * 16));
        pA[i] = Ah + (size_t)(bm + row) * lda + q * 8;
        pB[i] = Bh + (size_t)(bn + row) * ldb + q * 8;
    }

    // ---- ldmatrix lane address components ----
    const int rA = (lane & 7) + ((lane >> 3) & 1) * 8;
    const uint32_t cA16 = ((lane >> 4) & 1) * 16;
    const int rB = (lane & 7) + ((lane >> 4) & 1) * 8;
    const uint32_t cB16 = ((lane >> 3) & 1) * 16;

    uint32_t aoff[2], axor[2];
#pragma unroll
    for (int mt = 0; mt < 2; mt++) {
        int arow = wm * 32 + mt * 16 + rA;
        aoff[mt] = arow * 64;
        axor[mt] = ((arow >> 1) & 3) * 16;
    }
    uint32_t boff[4], bxor[4];
#pragma unroll
    for (int t = 0; t < 4; t++) {
        int brow = wn * 64 + t * 16 + rB;
        boff[t] = brow * 64;
        bxor[t] = ((brow >> 1) & 3) * 16;
    }

    float acc[2][8][4];
#pragma unroll
    for (int mt = 0; mt < 2; mt++)
#pragma unroll
        for (int nt = 0; nt < 8; nt++)
#pragma unroll
            for (int r = 0; r < 4; r++) acc[mt][nt][r] = 0.f;

    // ---- prologue: stages 0..NSTAGE-2 in flight ----
#pragma unroll
    for (int st = 0; st < NSTAGE - 1; st++) {
        int k0 = st * 32;
        uint32_t base = sb + st * STAGE_BYTES;
#pragma unroll
        for (int i = 0; i < 2; i++) cp16(base + dAB[i], pA[i] + k0);
#pragma unroll
        for (int i = 0; i < 2; i++) cp16(base + A_BYTES + dAB[i], pB[i] + k0);
        cp_commit();
    }
    cp_wait<NSTAGE - 2>();
    __syncthreads();

    // ---- main loop: ONE barrier per chunk ----
    for (int kc = 0; kc < nchunk; kc++) {
        const uint32_t baseA = sb + (kc % NSTAGE) * STAGE_BYTES;
        const uint32_t baseB = baseA + A_BYTES;

        // prefetch chunk kc+NSTAGE-1 into the stage consumed at kc-1
        int next = kc + NSTAGE - 1;
        if (next < nchunk) {
            int k0 = next * 32;
            uint32_t nb = sb + (next % NSTAGE) * STAGE_BYTES;
#pragma unroll
            for (int i = 0; i < 2; i++) cp16(nb + dAB[i], pA[i] + k0);
#pragma unroll
            for (int i = 0; i < 2; i++) cp16(nb + A_BYTES + dAB[i], pB[i] + k0);
        }
        cp_commit();

        // compute current chunk: 2 k16 steps, 16 MMAs + 6 LDSM each
#pragma unroll
        for (int s = 0; s < 2; s++) {
            uint32_t bh[16];
#pragma unroll
            for (int t = 0; t < 4; t++) {
                uint32_t c = s * 32 + cB16;
                ldm4(&bh[t * 4], baseB + boff[t] + (c ^ bxor[t]));
            }
#pragma unroll
            for (int mt = 0; mt < 2; mt++) {
                uint32_t a[4];
                uint32_t cc = s * 32 + cA16;
                ldm4(a, baseA + aoff[mt] + (cc ^ axor[mt]));
#pragma unroll
                for (int nt = 0; nt < 8; nt++) mma16816(acc[mt][nt], a, &bh[nt * 2]);
            }
        }

        cp_wait<NSTAGE - 2>();   // chunk kc+1 resident
        __syncthreads();
    }

    // ---- epilogue ----
#pragma unroll
    for (int mt = 0; mt < 2; mt++) {
        long r0 = bm + wm * 32 + mt * 16 + (lane >> 2);
        long r1 = r0 + 8;
#pragma unroll
        for (int nt = 0; nt < 8; nt++) {
            long col = bn + wn * 64 + nt * 8 + (lane & 3) * 2;
            float b0v = 0.f, b1v = 0.f;
            if (HAS_BIAS) { b0v = bias[col]; b1v = bias[col + 1]; }
            float v00 = acc[mt][nt][0] * scale + b0v;
            float v01 = acc[mt][nt][1] * scale + b1v;
            float v10 = acc[mt][nt][2] * scale + b0v;
            float v11 = acc[mt][nt][3] * scale + b1v;
            if (OUT == 2) {
                *reinterpret_cast<uint32_t*>(&Chi[r0 * ldc + col]) =
                    pack2(__float2half(v00), __float2half(v01));
                *reinterpret_cast<uint32_t*>(&Chi[r1 * ldc + col]) =
                    pack2(__float2half(v10), __float2half(v11));
            } else {
                float2 u0 = make_float2(v00, v01);
                float2 u1 = make_float2(v10, v11);
                *reinterpret_cast<float2*>(&C[r0 * ldc + col]) = u0;
                *reinterpret_cast<float2*>(&C[r1 * ldc + col]) = u1;
            }
        }
    }
}

// ---------------------------------------------------------------------------
// fp32 -> fp16 conversion (vectorized)
// ---------------------------------------------------------------------------
__global__ __launch_bounds__(256) void split_h_kernel(
    const float* __restrict__ src, h16* __restrict__ hi, int n4)
{
    int i = blockIdx.x * blockDim.x + threadIdx.x;
    if (i >= n4) return;
    float4 v = reinterpret_cast<const float4*>(src)[i];
    reinterpret_cast<uint2*>(hi)[i] = make_uint2(
        pack2(__float2half(v.x), __float2half(v.y)),
        pack2(__float2half(v.z), __float2half(v.w)));
}

// ---------------------------------------------------------------------------
// V transpose (hi only): vt[b][e][s] = qkv[b*S+s][2E+e]
// ---------------------------------------------------------------------------
__global__ __launch_bounds__(256) void transpose_v_kernel(
    const h16* __restrict__ qh, h16* __restrict__ vth)
{
    __shared__ h16 th[32][33];
    const int b = blockIdx.z;
    const int e0 = blockIdx.x * 32;
    const int s0 = blockIdx.y * 32;
    const int tx = threadIdx.x & 31;
    const int ty = threadIdx.x >> 5;  // 0..7
#pragma unroll
    for (int i = 0; i < 4; i++) {
        int s = s0 + ty + i * 8;
        size_t idx = (size_t)(b * SEQ + s) * (3 * EMBED) + 2 * EMBED + e0 + tx;
        th[ty + i * 8][tx] = qh[idx];
    }
    __syncthreads();
#pragma unroll
    for (int i = 0; i < 4; i++) {
        int e = e0 + ty + i * 8;
        size_t o = (size_t)(b * EMBED + e) * SEQ + s0 + tx;
        vth[o] = th[tx][ty + i * 8];
    }
}

// ---------------------------------------------------------------------------
// Row softmax with mask, IN-PLACE on fp16 logits (one block per row).
// ---------------------------------------------------------------------------
__global__ __launch_bounds__(256) void softmax_kernel(
    h16* __restrict__ att, const int* __restrict__ mask)
{
    const size_t row = blockIdx.x;
    h16* a = att + row * SEQ;
    const int* m = mask + row * SEQ;
    const int tid = threadIdx.x;

    __shared__ float red_max[8];
    __shared__ float red_sum[8];

    float v[8];
    float mx = -INFINITY;
#pragma unroll
    for (int i = 0; i < 8; i++) {
        int idx = tid + i * 256;
        float x = __half2float(a[idx]);
        x = (m[idx] != 0) ? x : -INFINITY;
        v[i] = x;
        mx = fmaxf(mx, x);
    }
#pragma unroll
    for (int o = 16; o > 0; o >>= 1)
        mx = fmaxf(mx, __shfl_xor_sync(0xffffffffu, mx, o));
    if ((tid & 31) == 0) red_max[tid >> 5] = mx;
    __syncthreads();
    float bmax = red_max[0];
#pragma unroll
    for (int w = 1; w < 8; w++) bmax = fmaxf(bmax, red_max[w]);

    float s = 0.f;
#pragma unroll
    for (int i = 0; i < 8; i++) {
        v[i] = __expf(v[i] - bmax);
        s += v[i];
    }
#pragma unroll
    for (int o = 16; o > 0; o >>= 1)
        s += __shfl_xor_sync(0xffffffffu, s, o);
    if ((tid & 31) == 0) red_sum[tid >> 5] = s;
    __syncthreads();
    float total = 0.f;
#pragma unroll
    for (int w = 0; w < 8; w++) total += red_sum[w];

    float inv = 1.f / total;
#pragma unroll
    for (int i = 0; i < 8; i++) {
        int idx = tid + i * 256;
        a[idx] = __float2half(v[i] * inv);
    }
}

// ---------------------------------------------------------------------------
extern "C" void kernel_launch(void* const* d_in, const int* in_sizes, int n_in,
                              void* d_out, int out_size)
{
    const float* X    = (const float*)d_in[0];
    const int*   mask = (const int*)  d_in[1];
    const float* Wqkv = (const float*)d_in[2];
    const float* bqkv = (const float*)d_in[3];
    const float* Wout = (const float*)d_in[4];
    const float* bout = (const float*)d_in[5];
    float* out = (float*)d_out;

    h16 *Xhi, *Wqkvhi, *Wouthi, *qkvhi, *att, *vthi, *ctxhi;
    cudaGetSymbolAddress((void**)&Xhi, g_Xhi);
    cudaGetSymbolAddress((void**)&Wqkvhi, g_Wqkvhi);
    cudaGetSymbolAddress((void**)&Wouthi, g_Wouthi);
    cudaGetSymbolAddress((void**)&qkvhi, g_qkvhi);
    cudaGetSymbolAddress((void**)&att, g_att);
    cudaGetSymbolAddress((void**)&vthi, g_vthi);
    cudaGetSymbolAddress((void**)&ctxhi, g_ctxhi);

    // NOTE: attributes must be set on the EXACT instantiations launched below.
    cudaFuncSetAttribute(gemm_fp16<true, 2>,
                         cudaFuncAttributeMaxDynamicSharedMemorySize, SMEM_TOTAL);
    cudaFuncSetAttribute(gemm_fp16<false, 2>,
                         cudaFuncAttributeMaxDynamicSharedMemorySize, SMEM_TOTAL);
    cudaFuncSetAttribute(gemm_fp16<true, 0>,
                         cudaFuncAttributeMaxDynamicSharedMemorySize, SMEM_TOTAL);

    // 0) convert inputs to fp16 (hi only)
    split_h_kernel<<<(ROWS * EMBED / 4 + 255) / 256, 256>>>(X, Xhi, ROWS * EMBED / 4);
    split_h_kernel<<<(3 * EMBED * EMBED / 4 + 255) / 256, 256>>>(
        Wqkv, Wqkvhi, 3 * EMBED * EMBED / 4);
    split_h_kernel<<<(EMBED * EMBED / 4 + 255) / 256, 256>>>(
        Wout, Wouthi, EMBED * EMBED / 4);

    // 1) qkv = X Wqkv^T + bqkv  (fp16 output)
    {
        dim3 grid(3 * EMBED / BN, ROWS / BM, 1);
        gemm_fp16<true, 2><<<grid, 256, SMEM_TOTAL>>>(
            Xhi, Wqkvhi, bqkv,
            nullptr, qkvhi,
            EMBED, EMBED, EMBED, 3 * EMBED,
            0, 0, 0, 1.0f);
    }
    // 2) vt = V^T
    {
        dim3 grid(EMBED / 32, SEQ / 32, BATCH);
        transpose_v_kernel<<<grid, 256>>>(qkvhi, vthi);
    }
    // 3) att = Q K^T / 32  (fp16 logits)
    {
        dim3 grid(SEQ / BN, SEQ / BM, BATCH);
        gemm_fp16<false, 2><<<grid, 256, SMEM_TOTAL>>>(
            qkvhi, qkvhi + EMBED, nullptr,
            nullptr, att,
            EMBED, 3 * EMBED, 3 * EMBED, SEQ,
            (long)SEQ * 3 * EMBED, (long)SEQ * 3 * EMBED, (long)SEQ * SEQ,
            1.0f / 32.0f);
    }
    // 4) softmax in-place on fp16 logits -> fp16 probs
    softmax_kernel<<<BATCH * SEQ, 256>>>(att, mask);

    // 5) ctx = p vt^T  (fp16 output)
    {
        dim3 grid(EMBED / BN, SEQ / BM, BATCH);
        gemm_fp16<false, 2><<<grid, 256, SMEM_TOTAL>>>(
            att, vthi, nullptr,
            nullptr, ctxhi,
            SEQ, SEQ, SEQ, EMBED,
            (long)SEQ * SEQ, (long)EMBED * SEQ, (long)SEQ * EMBED,
            1.0f);
    }
    // 6) out = ctx Wout^T + bout  (fp32)
    {
        dim3 grid(EMBED / BN, ROWS / BM, 1);
        gemm_fp16<true, 0><<<grid, 256, SMEM_TOTAL>>>(
            ctxhi, Wouthi, bout,
            out, nullptr,
            EMBED, EMBED, EMBED, EMBED,
            0, 0, 0, 1.0f);
    }
}